// round 1
// baseline (speedup 1.0000x reference)
#include <cuda_runtime.h>
#include <math.h>
#include <math_constants.h>

// Problem constants (fixed by setup_inputs)
#define B_     2
#define T_     2048
#define D_     1024
#define H_     16
#define HD_    64
#define TOK_   4096      // B*T
#define NCH_   64        // B*NC chunks
#define CH_    64        // chunk_size
#define KV_    256       // K*NL
#define KVTOK_ 16384     // NCH_*KV_
#define DFF_   4096

// ---------------- scratch (static device globals; no allocation) ----------------
__device__ float g_h   [TOK_  * D_];     // LN outputs (reused)
__device__ float g_q   [TOK_  * D_];
__device__ float g_k   [KVTOK_* D_];
__device__ float g_v   [KVTOK_* D_];
__device__ float g_kvln[KVTOK_* D_];
__device__ float g_attn[TOK_  * D_];
__device__ float g_x1  [TOK_  * D_];
__device__ float g_ffn [TOK_  * DFF_];   // 64 MB

// ---------------- LayerNorm: one block (256 thr) per row of 1024 ----------------
__global__ __launch_bounds__(256) void ln_kernel(
    const float* __restrict__ x, const float* __restrict__ g,
    const float* __restrict__ b, float* __restrict__ out)
{
    int row = blockIdx.x;
    int tid = threadIdx.x;
    const float4* xr = reinterpret_cast<const float4*>(x + (size_t)row * D_);
    float4 v4 = xr[tid];
    float s  = v4.x + v4.y + v4.z + v4.w;
    float ss = v4.x*v4.x + v4.y*v4.y + v4.z*v4.z + v4.w*v4.w;

    __shared__ float sh1[8], sh2[8];
    int lane = tid & 31, wid = tid >> 5;
    #pragma unroll
    for (int o = 16; o; o >>= 1) {
        s  += __shfl_down_sync(0xffffffffu, s,  o);
        ss += __shfl_down_sync(0xffffffffu, ss, o);
    }
    if (lane == 0) { sh1[wid] = s; sh2[wid] = ss; }
    __syncthreads();
    if (tid < 32) {
        s  = (tid < 8) ? sh1[tid] : 0.f;
        ss = (tid < 8) ? sh2[tid] : 0.f;
        #pragma unroll
        for (int o = 4; o; o >>= 1) {
            s  += __shfl_down_sync(0xffffffffu, s,  o);
            ss += __shfl_down_sync(0xffffffffu, ss, o);
        }
        if (tid == 0) { sh1[0] = s; sh2[0] = ss; }
    }
    __syncthreads();
    float mean = sh1[0] * (1.0f / D_);
    float var  = sh2[0] * (1.0f / D_) - mean * mean;
    float rstd = rsqrtf(var + 1e-5f);

    const float4 g4 = reinterpret_cast<const float4*>(g)[tid];
    const float4 b4 = reinterpret_cast<const float4*>(b)[tid];
    float4 o4;
    o4.x = (v4.x - mean) * rstd * g4.x + b4.x;
    o4.y = (v4.y - mean) * rstd * g4.y + b4.y;
    o4.z = (v4.z - mean) * rstd * g4.z + b4.z;
    o4.w = (v4.w - mean) * rstd * g4.w + b4.w;
    reinterpret_cast<float4*>(out + (size_t)row * D_)[tid] = o4;
}

// ---------------- fp32 tiled GEMM: C = A[MxK] @ B[KxN] (+resid) (+gelu) ----------
// 64x64 tile, BK=16, 256 threads, 4x4 per thread.
template<bool GELU>
__global__ __launch_bounds__(256) void gemm_kernel(
    const float* __restrict__ A, const float* __restrict__ Bm,
    const float* __restrict__ resid, float* __restrict__ C,
    int M, int N, int K)
{
    __shared__ float As[16][68];   // transposed A tile, padded (68*4B is 16B-aligned)
    __shared__ float Bs[16][64];

    int tid = threadIdx.x;
    int n0 = blockIdx.x * 64;
    int m0 = blockIdx.y * 64;
    int tm = (tid >> 4) << 2;
    int tn = (tid & 15) << 2;

    int ar = tid >> 2, ac = (tid & 3) << 2;     // A: 64 rows x 16 cols
    int br = tid >> 4, bc = (tid & 15) << 2;    // B: 16 rows x 64 cols
    const float* Aptr = A  + (size_t)(m0 + ar) * K + ac;
    const float* Bptr = Bm + (size_t)br * N + n0 + bc;

    float acc[4][4];
    #pragma unroll
    for (int i = 0; i < 4; i++)
        #pragma unroll
        for (int j = 0; j < 4; j++) acc[i][j] = 0.f;

    for (int k0 = 0; k0 < K; k0 += 16) {
        float4 a4 = *reinterpret_cast<const float4*>(Aptr + k0);
        float4 b4 = *reinterpret_cast<const float4*>(Bptr + (size_t)k0 * N);
        As[ac + 0][ar] = a4.x;
        As[ac + 1][ar] = a4.y;
        As[ac + 2][ar] = a4.z;
        As[ac + 3][ar] = a4.w;
        *reinterpret_cast<float4*>(&Bs[br][bc]) = b4;
        __syncthreads();

        #pragma unroll
        for (int k = 0; k < 16; k++) {
            float4 av = *reinterpret_cast<const float4*>(&As[k][tm]);
            float4 bv = *reinterpret_cast<const float4*>(&Bs[k][tn]);
            float a[4] = {av.x, av.y, av.z, av.w};
            float bb[4] = {bv.x, bv.y, bv.z, bv.w};
            #pragma unroll
            for (int i = 0; i < 4; i++)
                #pragma unroll
                for (int j = 0; j < 4; j++)
                    acc[i][j] += a[i] * bb[j];
        }
        __syncthreads();
    }

    #pragma unroll
    for (int i = 0; i < 4; i++) {
        #pragma unroll
        for (int j = 0; j < 4; j++) {
            size_t idx = (size_t)(m0 + tm + i) * N + (n0 + tn + j);
            float v = acc[i][j];
            if (GELU) v = 0.5f * v * (1.0f + erff(v * 0.70710678118654752f));
            if (resid) v += resid[idx];
            C[idx] = v;
        }
    }
}

// ---------------- flash attention (fp32, online softmax) ------------------------
// One block = 64 query rows for one (batch, head). 64 threads, 1 row/thread.
// Q/K/V/O layouts: [tokens, 1024], head h at cols h*64..h*64+63.
template<bool CAUSAL>
__global__ __launch_bounds__(64) void attn_kernel(
    const float* __restrict__ Q, const float* __restrict__ K,
    const float* __restrict__ V, float* __restrict__ O,
    int klen, int q_batch_tokens, int kv_batch_tokens)
{
    const int ld = D_;
    int qt = blockIdx.x, h = blockIdx.y, b = blockIdx.z;
    int tid = threadIdx.x;
    int qi = qt * 64 + tid;                 // local query index within batch

    const float* qrow = Q + (size_t)(b * q_batch_tokens + qi) * ld + h * HD_;
    float qreg[HD_];
    #pragma unroll
    for (int d = 0; d < HD_; d++) qreg[d] = qrow[d] * 0.125f;   // 1/sqrt(64)

    float acc[HD_];
    #pragma unroll
    for (int d = 0; d < HD_; d++) acc[d] = 0.f;
    float m = -1e30f, l = 0.f;

    __shared__ float Ks[32][HD_];
    __shared__ float Vs[32][HD_];

    int ktiles = klen >> 5;
    if (CAUSAL) {
        int need = ((qt * 64 + 63) >> 5) + 1;   // tiles covering max query in block
        if (need < ktiles) ktiles = need;
    }

    for (int kt = 0; kt < ktiles; kt++) {
        int kbase = b * kv_batch_tokens + kt * 32;
        __syncthreads();
        // 64 threads load 32x64 K and V tiles (8 float4 each per matrix)
        #pragma unroll
        for (int i = tid; i < 32 * 16; i += 64) {
            int r = i >> 4, c = (i & 15) << 2;
            *reinterpret_cast<float4*>(&Ks[r][c]) =
                *reinterpret_cast<const float4*>(&K[(size_t)(kbase + r) * ld + h * HD_ + c]);
            *reinterpret_cast<float4*>(&Vs[r][c]) =
                *reinterpret_cast<const float4*>(&V[(size_t)(kbase + r) * ld + h * HD_ + c]);
        }
        __syncthreads();

        float s[32];
        #pragma unroll
        for (int j = 0; j < 32; j++) {
            float dot = 0.f;
            #pragma unroll
            for (int d = 0; d < HD_; d++) dot += qreg[d] * Ks[j][d];
            if (CAUSAL && (kt * 32 + j > qi)) dot = -1e30f;
            s[j] = dot;
        }

        float tmax = s[0];
        #pragma unroll
        for (int j = 1; j < 32; j++) tmax = fmaxf(tmax, s[j]);
        float newm = fmaxf(m, tmax);
        float corr = __expf(m - newm);

        float tsum = 0.f;
        #pragma unroll
        for (int j = 0; j < 32; j++) {
            s[j] = __expf(s[j] - newm);
            tsum += s[j];
        }
        l = l * corr + tsum;

        #pragma unroll
        for (int d = 0; d < HD_; d++) {
            float a = acc[d] * corr;
            #pragma unroll
            for (int j = 0; j < 32; j++) a += s[j] * Vs[j][d];
            acc[d] = a;
        }
        m = newm;
    }

    float inv_l = 1.0f / l;
    float* orow = O + (size_t)(b * q_batch_tokens + qi) * ld + h * HD_;
    #pragma unroll
    for (int d = 0; d < HD_; d++) orow[d] = acc[d] * inv_l;
}

// ---------------- launch ---------------------------------------------------------
extern "C" void kernel_launch(void* const* d_in, const int* in_sizes, int n_in,
                              void* d_out, int out_size)
{
    const float* x         = (const float*)d_in[0];
    const float* neighbors = (const float*)d_in[1];
    const float* sa_ln_g   = (const float*)d_in[2];
    const float* sa_ln_b   = (const float*)d_in[3];
    const float* sa_wq     = (const float*)d_in[4];
    const float* sa_wk     = (const float*)d_in[5];
    const float* sa_wv     = (const float*)d_in[6];
    const float* sa_wo     = (const float*)d_in[7];
    const float* cca_lnq_g = (const float*)d_in[8];
    const float* cca_lnq_b = (const float*)d_in[9];
    const float* cca_lnkv_g= (const float*)d_in[10];
    const float* cca_lnkv_b= (const float*)d_in[11];
    const float* cca_wq    = (const float*)d_in[12];
    const float* cca_wk    = (const float*)d_in[13];
    const float* cca_wv    = (const float*)d_in[14];
    const float* cca_wo    = (const float*)d_in[15];
    const float* ffn_ln_g  = (const float*)d_in[16];
    const float* ffn_ln_b  = (const float*)d_in[17];
    const float* ffn_w1    = (const float*)d_in[18];
    const float* ffn_w2    = (const float*)d_in[19];
    float* out = (float*)d_out;

    float *h, *q, *k, *v, *kvln, *attn, *x1, *ffn;
    cudaGetSymbolAddress((void**)&h,    g_h);
    cudaGetSymbolAddress((void**)&q,    g_q);
    cudaGetSymbolAddress((void**)&k,    g_k);
    cudaGetSymbolAddress((void**)&v,    g_v);
    cudaGetSymbolAddress((void**)&kvln, g_kvln);
    cudaGetSymbolAddress((void**)&attn, g_attn);
    cudaGetSymbolAddress((void**)&x1,   g_x1);
    cudaGetSymbolAddress((void**)&ffn,  g_ffn);

    dim3 blk256(256);
    dim3 gProj(D_ / 64, TOK_ / 64);          // (16, 64): [4096x1024] = [4096x1024]@[1024x1024]
    dim3 gKV(D_ / 64, KVTOK_ / 64);          // (16, 256)
    dim3 gFFN1(DFF_ / 64, TOK_ / 64);        // (64, 64)

    // ---- self-attention ----
    ln_kernel<<<TOK_, blk256>>>(x, sa_ln_g, sa_ln_b, h);
    gemm_kernel<false><<<gProj, blk256>>>(h, sa_wq, nullptr, q, TOK_, D_, D_);
    gemm_kernel<false><<<gProj, blk256>>>(h, sa_wk, nullptr, k, TOK_, D_, D_);
    gemm_kernel<false><<<gProj, blk256>>>(h, sa_wv, nullptr, v, TOK_, D_, D_);
    attn_kernel<true><<<dim3(T_ / 64, H_, B_), 64>>>(q, k, v, attn, T_, T_, T_);
    gemm_kernel<false><<<gProj, blk256>>>(attn, sa_wo, x, x1, TOK_, D_, D_);

    // ---- chunked cross-attention (T == NC*chunk, all reshapes are views) ----
    ln_kernel<<<TOK_,  blk256>>>(x1, cca_lnq_g, cca_lnq_b, h);
    ln_kernel<<<KVTOK_, blk256>>>(neighbors, cca_lnkv_g, cca_lnkv_b, kvln);
    gemm_kernel<false><<<gProj, blk256>>>(h,    cca_wq, nullptr, q, TOK_,   D_, D_);
    gemm_kernel<false><<<gKV,   blk256>>>(kvln, cca_wk, nullptr, k, KVTOK_, D_, D_);
    gemm_kernel<false><<<gKV,   blk256>>>(kvln, cca_wv, nullptr, v, KVTOK_, D_, D_);
    attn_kernel<false><<<dim3(1, H_, NCH_), 64>>>(q, k, v, attn, KV_, CH_, KV_);
    gemm_kernel<false><<<gProj, blk256>>>(attn, cca_wo, x1, out, TOK_, D_, D_);  // out = x2

    // ---- FFN ----
    ln_kernel<<<TOK_, blk256>>>(out, ffn_ln_g, ffn_ln_b, h);
    gemm_kernel<true ><<<gFFN1, blk256>>>(h,   ffn_w1, nullptr, ffn, TOK_, DFF_, D_);
    gemm_kernel<false><<<gProj, blk256>>>(ffn, ffn_w2, out,     out, TOK_, D_, DFF_);
}

// round 3
// speedup vs baseline: 2.0395x; 2.0395x over previous
#include <cuda_runtime.h>
#include <math.h>
#include <cstdint>

// Problem constants (fixed by setup_inputs)
#define B_     2
#define T_     2048
#define D_     1024
#define H_     16
#define HD_    64
#define TOK_   4096      // B*T
#define NCH_   64        // B*NC chunks
#define CH_    64        // chunk_size
#define KV_    256       // K*NL
#define KVTOK_ 16384     // NCH_*KV_
#define DFF_   4096

// ---------------- scratch (static device globals; no allocation) ----------------
__device__ float g_h   [TOK_  * D_];
__device__ float g_q   [TOK_  * D_];
__device__ float g_k   [KVTOK_* D_];
__device__ float g_v   [KVTOK_* D_];
__device__ float g_kvln[KVTOK_* D_];
__device__ float g_attn[TOK_  * D_];
__device__ float g_x1  [TOK_  * D_];
__device__ float g_ffn [TOK_  * DFF_];
__device__ float g_wt  [16u * 1024u * 1024u];   // transposed weights, 64 MB

// ---------------- helpers ---------------------------------------------------------
__device__ __forceinline__ uint32_t smem_u32(const void* p) {
    uint32_t a;
    asm("{ .reg .u64 t; cvta.to.shared.u64 t, %1; cvt.u32.u64 %0, t; }" : "=r"(a) : "l"(p));
    return a;
}

__device__ __forceinline__ float to_tf32(float x) {
    uint32_t u;
    asm("cvt.rna.tf32.f32 %0, %1;" : "=r"(u) : "f"(x));
    return __uint_as_float(u);
}

__device__ __forceinline__ void cp16(uint32_t s, const void* g) {
    asm volatile("cp.async.cg.shared.global [%0], [%1], 16;" :: "r"(s), "l"(g));
}
__device__ __forceinline__ void cp_commit() {
    asm volatile("cp.async.commit_group;" ::: "memory");
}
template<int N>
__device__ __forceinline__ void cp_wait() {
    asm volatile("cp.async.wait_group %0;" :: "n"(N) : "memory");
}

// m16n8k8 tf32 MMA, C += A*B
__device__ __forceinline__ void mma8(float* c, const uint32_t* a, const uint32_t* b) {
    asm volatile(
        "mma.sync.aligned.m16n8k8.row.col.f32.tf32.tf32.f32 "
        "{%0,%1,%2,%3}, {%4,%5,%6,%7}, {%8,%9}, {%0,%1,%2,%3};"
        : "+f"(c[0]), "+f"(c[1]), "+f"(c[2]), "+f"(c[3])
        : "r"(a[0]), "r"(a[1]), "r"(a[2]), "r"(a[3]), "r"(b[0]), "r"(b[1]));
}

// ---------------- weight transpose: WT[n*K+k] = tf32(W[k*N+n]) -------------------
__global__ __launch_bounds__(256) void transpose_kernel(
    const float* __restrict__ W, float* __restrict__ WT, int K, int N)
{
    __shared__ float t[32][33];
    int kb = blockIdx.y * 32, nb = blockIdx.x * 32;
    int tx = threadIdx.x & 31, ty4 = (threadIdx.x >> 5) * 4;
    #pragma unroll
    for (int r = 0; r < 4; r++)
        t[ty4 + r][tx] = W[(size_t)(kb + ty4 + r) * N + nb + tx];
    __syncthreads();
    #pragma unroll
    for (int r = 0; r < 4; r++)
        WT[(size_t)(nb + ty4 + r) * K + kb + tx] = to_tf32(t[tx][ty4 + r]);
}

// ---------------- LayerNorm: one block (256 thr) per row of 1024 ----------------
// Output is tf32-rounded (only ever consumed as a GEMM A operand).
__global__ __launch_bounds__(256) void ln_kernel(
    const float* __restrict__ x, const float* __restrict__ g,
    const float* __restrict__ b, float* __restrict__ out)
{
    int row = blockIdx.x;
    int tid = threadIdx.x;
    const float4* xr = reinterpret_cast<const float4*>(x + (size_t)row * D_);
    float4 v4 = xr[tid];
    float s  = v4.x + v4.y + v4.z + v4.w;
    float ss = v4.x*v4.x + v4.y*v4.y + v4.z*v4.z + v4.w*v4.w;

    __shared__ float sh1[8], sh2[8];
    int lane = tid & 31, wid = tid >> 5;
    #pragma unroll
    for (int o = 16; o; o >>= 1) {
        s  += __shfl_down_sync(0xffffffffu, s,  o);
        ss += __shfl_down_sync(0xffffffffu, ss, o);
    }
    if (lane == 0) { sh1[wid] = s; sh2[wid] = ss; }
    __syncthreads();
    if (tid < 32) {
        s  = (tid < 8) ? sh1[tid] : 0.f;
        ss = (tid < 8) ? sh2[tid] : 0.f;
        #pragma unroll
        for (int o = 4; o; o >>= 1) {
            s  += __shfl_down_sync(0xffffffffu, s,  o);
            ss += __shfl_down_sync(0xffffffffu, ss, o);
        }
        if (tid == 0) { sh1[0] = s; sh2[0] = ss; }
    }
    __syncthreads();
    float mean = sh1[0] * (1.0f / D_);
    float var  = sh2[0] * (1.0f / D_) - mean * mean;
    float rstd = rsqrtf(var + 1e-5f);

    const float4 g4 = reinterpret_cast<const float4*>(g)[tid];
    const float4 b4 = reinterpret_cast<const float4*>(b)[tid];
    float4 o4;
    o4.x = to_tf32((v4.x - mean) * rstd * g4.x + b4.x);
    o4.y = to_tf32((v4.y - mean) * rstd * g4.y + b4.y);
    o4.z = to_tf32((v4.z - mean) * rstd * g4.z + b4.z);
    o4.w = to_tf32((v4.w - mean) * rstd * g4.w + b4.w);
    reinterpret_cast<float4*>(out + (size_t)row * D_)[tid] = o4;
}

// ---------------- tf32 mma.sync GEMM: C = A[MxK] @ WT[NxK]^T (+resid)(+gelu) -----
// 128x128x16 tiles, 256 threads (8 warps = 4Mx2N), warp tile 32x64.
// cp.async double-buffered smem; fragment loads bank-conflict-free (stride 20).
template<bool GELU, bool CVT>
__global__ __launch_bounds__(256) void gemm_mma(
    const float* __restrict__ A, const float* __restrict__ WT,
    const float* __restrict__ resid, float* __restrict__ C,
    int M, int N, int K)
{
    __shared__ float As[2][128][20];
    __shared__ float Bs[2][128][20];

    int tid = threadIdx.x;
    int wid = tid >> 5, lane = tid & 31;
    int warpM = wid >> 1, warpN = wid & 1;
    int grp = lane >> 2, tig = lane & 3;

    int n0 = blockIdx.x * 128, m0 = blockIdx.y * 128;
    const float* Ab = A  + (size_t)m0 * K;
    const float* Bb = WT + (size_t)n0 * K;

    // per-thread global->smem mapping: 2 float4 per matrix per tile
    int r0 = tid >> 1;                 // 0..127
    int c0 = (tid & 1) * 8;            // 0 or 8 (two float4 at c0, c0+4? no: 16 floats/row)
    // row r0 covers cols [c0, c0+8): two float4 loads? Use: each thread does 2 loads idx-based.

    float acc[2][8][4];
    #pragma unroll
    for (int i = 0; i < 2; i++)
        #pragma unroll
        for (int j = 0; j < 8; j++)
            #pragma unroll
            for (int q = 0; q < 4; q++) acc[i][j][q] = 0.f;

    int nk = K >> 4;

    // prologue: load tile 0 into buf 0
    {
        #pragma unroll
        for (int i = 0; i < 2; i++) {
            int idx = tid + i * 256;
            int m = idx >> 2, kc = (idx & 3) * 4;
            cp16(smem_u32(&As[0][m][kc]), Ab + (size_t)m * K + kc);
            cp16(smem_u32(&Bs[0][m][kc]), Bb + (size_t)m * K + kc);
        }
        cp_commit();
    }

    for (int kt = 0; kt < nk; kt++) {
        int buf = kt & 1;
        if (kt + 1 < nk) {
            int k0 = (kt + 1) << 4;
            #pragma unroll
            for (int i = 0; i < 2; i++) {
                int idx = tid + i * 256;
                int m = idx >> 2, kc = (idx & 3) * 4;
                cp16(smem_u32(&As[buf ^ 1][m][kc]), Ab + (size_t)m * K + k0 + kc);
                cp16(smem_u32(&Bs[buf ^ 1][m][kc]), Bb + (size_t)m * K + k0 + kc);
            }
            cp_commit();
            cp_wait<1>();
        } else {
            cp_wait<0>();
        }
        __syncthreads();

        #pragma unroll
        for (int ks = 0; ks < 2; ks++) {
            int k = ks * 8;
            uint32_t af[2][4], bf[8][2];
            #pragma unroll
            for (int mt = 0; mt < 2; mt++) {
                int rA = warpM * 32 + mt * 16 + grp;
                af[mt][0] = __float_as_uint(As[buf][rA    ][k + tig]);
                af[mt][1] = __float_as_uint(As[buf][rA + 8][k + tig]);
                af[mt][2] = __float_as_uint(As[buf][rA    ][k + tig + 4]);
                af[mt][3] = __float_as_uint(As[buf][rA + 8][k + tig + 4]);
            }
            #pragma unroll
            for (int nt = 0; nt < 8; nt++) {
                int rB = warpN * 64 + nt * 8 + grp;
                bf[nt][0] = __float_as_uint(Bs[buf][rB][k + tig]);
                bf[nt][1] = __float_as_uint(Bs[buf][rB][k + tig + 4]);
            }
            #pragma unroll
            for (int mt = 0; mt < 2; mt++)
                #pragma unroll
                for (int nt = 0; nt < 8; nt++)
                    mma8(acc[mt][nt], af[mt], bf[nt]);
        }
        __syncthreads();
    }

    // epilogue: c0,c1 at (row, col..col+1); c2,c3 at (row+8, col..col+1)
    #pragma unroll
    for (int mt = 0; mt < 2; mt++) {
        int row = m0 + warpM * 32 + mt * 16 + grp;
        #pragma unroll
        for (int nt = 0; nt < 8; nt++) {
            int col = n0 + warpN * 64 + nt * 8 + 2 * tig;
            #pragma unroll
            for (int half = 0; half < 2; half++) {
                int r = row + half * 8;
                float v0 = acc[mt][nt][half * 2 + 0];
                float v1 = acc[mt][nt][half * 2 + 1];
                if (GELU) {
                    v0 = 0.5f * v0 * (1.0f + erff(v0 * 0.70710678118654752f));
                    v1 = 0.5f * v1 * (1.0f + erff(v1 * 0.70710678118654752f));
                }
                size_t base = (size_t)r * N + col;
                if (resid) {
                    float2 rv = *reinterpret_cast<const float2*>(resid + base);
                    v0 += rv.x; v1 += rv.y;
                }
                if (CVT) { v0 = to_tf32(v0); v1 = to_tf32(v1); }
                float2 ov = {v0, v1};
                *reinterpret_cast<float2*>(C + base) = ov;
            }
        }
    }
}

// ---------------- flash attention (fp32, online softmax) ------------------------
// Output tf32-rounded (only consumed as GEMM A operand).
template<bool CAUSAL>
__global__ __launch_bounds__(64) void attn_kernel(
    const float* __restrict__ Q, const float* __restrict__ K,
    const float* __restrict__ V, float* __restrict__ O,
    int klen, int q_batch_tokens, int kv_batch_tokens)
{
    const int ld = D_;
    int qt = blockIdx.x, h = blockIdx.y, b = blockIdx.z;
    int tid = threadIdx.x;
    int qi = qt * 64 + tid;

    const float* qrow = Q + (size_t)(b * q_batch_tokens + qi) * ld + h * HD_;
    float qreg[HD_];
    #pragma unroll
    for (int d = 0; d < HD_; d++) qreg[d] = qrow[d] * 0.125f;

    float acc[HD_];
    #pragma unroll
    for (int d = 0; d < HD_; d++) acc[d] = 0.f;
    float m = -1e30f, l = 0.f;

    __shared__ float Ks[32][HD_];
    __shared__ float Vs[32][HD_];

    int ktiles = klen >> 5;
    if (CAUSAL) {
        int need = ((qt * 64 + 63) >> 5) + 1;
        if (need < ktiles) ktiles = need;
    }

    for (int kt = 0; kt < ktiles; kt++) {
        int kbase = b * kv_batch_tokens + kt * 32;
        __syncthreads();
        #pragma unroll
        for (int i = tid; i < 32 * 16; i += 64) {
            int r = i >> 4, c = (i & 15) << 2;
            *reinterpret_cast<float4*>(&Ks[r][c]) =
                *reinterpret_cast<const float4*>(&K[(size_t)(kbase + r) * ld + h * HD_ + c]);
            *reinterpret_cast<float4*>(&Vs[r][c]) =
                *reinterpret_cast<const float4*>(&V[(size_t)(kbase + r) * ld + h * HD_ + c]);
        }
        __syncthreads();

        float s[32];
        #pragma unroll
        for (int j = 0; j < 32; j++) {
            float dot = 0.f;
            #pragma unroll
            for (int d = 0; d < HD_; d++) dot += qreg[d] * Ks[j][d];
            if (CAUSAL && (kt * 32 + j > qi)) dot = -1e30f;
            s[j] = dot;
        }

        float tmax = s[0];
        #pragma unroll
        for (int j = 1; j < 32; j++) tmax = fmaxf(tmax, s[j]);
        float newm = fmaxf(m, tmax);
        float corr = __expf(m - newm);

        float tsum = 0.f;
        #pragma unroll
        for (int j = 0; j < 32; j++) {
            s[j] = __expf(s[j] - newm);
            tsum += s[j];
        }
        l = l * corr + tsum;

        #pragma unroll
        for (int d = 0; d < HD_; d++) {
            float a = acc[d] * corr;
            #pragma unroll
            for (int j = 0; j < 32; j++) a += s[j] * Vs[j][d];
            acc[d] = a;
        }
        m = newm;
    }

    float inv_l = 1.0f / l;
    float* orow = O + (size_t)(b * q_batch_tokens + qi) * ld + h * HD_;
    #pragma unroll
    for (int d = 0; d < HD_; d++) orow[d] = to_tf32(acc[d] * inv_l);
}

// ---------------- launch ---------------------------------------------------------
extern "C" void kernel_launch(void* const* d_in, const int* in_sizes, int n_in,
                              void* d_out, int out_size)
{
    const float* x         = (const float*)d_in[0];
    const float* neighbors = (const float*)d_in[1];
    const float* sa_ln_g   = (const float*)d_in[2];
    const float* sa_ln_b   = (const float*)d_in[3];
    const float* sa_wq     = (const float*)d_in[4];
    const float* sa_wk     = (const float*)d_in[5];
    const float* sa_wv     = (const float*)d_in[6];
    const float* sa_wo     = (const float*)d_in[7];
    const float* cca_lnq_g = (const float*)d_in[8];
    const float* cca_lnq_b = (const float*)d_in[9];
    const float* cca_lnkv_g= (const float*)d_in[10];
    const float* cca_lnkv_b= (const float*)d_in[11];
    const float* cca_wq    = (const float*)d_in[12];
    const float* cca_wk    = (const float*)d_in[13];
    const float* cca_wv    = (const float*)d_in[14];
    const float* cca_wo    = (const float*)d_in[15];
    const float* ffn_ln_g  = (const float*)d_in[16];
    const float* ffn_ln_b  = (const float*)d_in[17];
    const float* ffn_w1    = (const float*)d_in[18];
    const float* ffn_w2    = (const float*)d_in[19];
    float* out = (float*)d_out;

    float *h, *q, *k, *v, *kvln, *attn, *x1, *ffn, *wt;
    cudaGetSymbolAddress((void**)&h,    g_h);
    cudaGetSymbolAddress((void**)&q,    g_q);
    cudaGetSymbolAddress((void**)&k,    g_k);
    cudaGetSymbolAddress((void**)&v,    g_v);
    cudaGetSymbolAddress((void**)&kvln, g_kvln);
    cudaGetSymbolAddress((void**)&attn, g_attn);
    cudaGetSymbolAddress((void**)&x1,   g_x1);
    cudaGetSymbolAddress((void**)&ffn,  g_ffn);
    cudaGetSymbolAddress((void**)&wt,   g_wt);

    const size_t MB = 1024 * 1024;
    float* wt_saq = wt + 0 * MB;
    float* wt_sak = wt + 1 * MB;
    float* wt_sav = wt + 2 * MB;
    float* wt_sao = wt + 3 * MB;
    float* wt_ccq = wt + 4 * MB;
    float* wt_cck = wt + 5 * MB;
    float* wt_ccv = wt + 6 * MB;
    float* wt_cco = wt + 7 * MB;
    float* wt_f1  = wt + 8 * MB;    // [DFF, D]
    float* wt_f2  = wt + 12 * MB;   // [D, DFF]

    dim3 blk256(256);
    dim3 gT(D_ / 32, D_ / 32);
    dim3 gTf1(DFF_ / 32, D_ / 32);
    dim3 gTf2(D_ / 32, DFF_ / 32);

    // ---- weight transposes (+tf32 rounding) ----
    transpose_kernel<<<gT, blk256>>>(sa_wq,  wt_saq, D_, D_);
    transpose_kernel<<<gT, blk256>>>(sa_wk,  wt_sak, D_, D_);
    transpose_kernel<<<gT, blk256>>>(sa_wv,  wt_sav, D_, D_);
    transpose_kernel<<<gT, blk256>>>(sa_wo,  wt_sao, D_, D_);
    transpose_kernel<<<gT, blk256>>>(cca_wq, wt_ccq, D_, D_);
    transpose_kernel<<<gT, blk256>>>(cca_wk, wt_cck, D_, D_);
    transpose_kernel<<<gT, blk256>>>(cca_wv, wt_ccv, D_, D_);
    transpose_kernel<<<gT, blk256>>>(cca_wo, wt_cco, D_, D_);
    transpose_kernel<<<gTf1, blk256>>>(ffn_w1, wt_f1, D_, DFF_);
    transpose_kernel<<<gTf2, blk256>>>(ffn_w2, wt_f2, DFF_, D_);

    dim3 gProj(D_ / 128, TOK_ / 128);          // (8, 32)
    dim3 gKV(D_ / 128, KVTOK_ / 128);          // (8, 128)
    dim3 gFFN1(DFF_ / 128, TOK_ / 128);        // (32, 32)

    // ---- self-attention ----
    ln_kernel<<<TOK_, blk256>>>(x, sa_ln_g, sa_ln_b, h);
    gemm_mma<false,false><<<gProj, blk256>>>(h, wt_saq, nullptr, q, TOK_, D_, D_);
    gemm_mma<false,false><<<gProj, blk256>>>(h, wt_sak, nullptr, k, TOK_, D_, D_);
    gemm_mma<false,false><<<gProj, blk256>>>(h, wt_sav, nullptr, v, TOK_, D_, D_);
    attn_kernel<true><<<dim3(T_ / 64, H_, B_), 64>>>(q, k, v, attn, T_, T_, T_);
    gemm_mma<false,false><<<gProj, blk256>>>(attn, wt_sao, x, x1, TOK_, D_, D_);

    // ---- chunked cross-attention (T == NC*chunk; reshapes are views) ----
    ln_kernel<<<TOK_,  blk256>>>(x1, cca_lnq_g, cca_lnq_b, h);
    ln_kernel<<<KVTOK_, blk256>>>(neighbors, cca_lnkv_g, cca_lnkv_b, kvln);
    gemm_mma<false,false><<<gProj, blk256>>>(h,    wt_ccq, nullptr, q, TOK_,   D_, D_);
    gemm_mma<false,false><<<gKV,   blk256>>>(kvln, wt_cck, nullptr, k, KVTOK_, D_, D_);
    gemm_mma<false,false><<<gKV,   blk256>>>(kvln, wt_ccv, nullptr, v, KVTOK_, D_, D_);
    attn_kernel<false><<<dim3(1, H_, NCH_), 64>>>(q, k, v, attn, KV_, CH_, KV_);
    gemm_mma<false,false><<<gProj, blk256>>>(attn, wt_cco, x1, out, TOK_, D_, D_);

    // ---- FFN ----
    ln_kernel<<<TOK_, blk256>>>(out, ffn_ln_g, ffn_ln_b, h);
    gemm_mma<true, true ><<<gFFN1, blk256>>>(h,   wt_f1, nullptr, ffn, TOK_, DFF_, D_);
    gemm_mma<false,false><<<gProj, blk256>>>(ffn, wt_f2, out,     out, TOK_, D_, DFF_);
}

// round 4
// speedup vs baseline: 3.5154x; 1.7237x over previous
#include <cuda_runtime.h>
#include <math.h>
#include <cstdint>

// Problem constants (fixed by setup_inputs)
#define B_     2
#define T_     2048
#define D_     1024
#define H_     16
#define HD_    64
#define TOK_   4096      // B*T
#define NCH_   64        // B*NC chunks
#define CH_    64        // chunk_size
#define KV_    256       // K*NL
#define KVTOK_ 16384     // NCH_*KV_
#define DFF_   4096

// ---------------- scratch (static device globals; no allocation) ----------------
__device__ float g_h   [TOK_  * D_];
__device__ float g_q   [TOK_  * D_];
__device__ float g_k   [KVTOK_* D_];
__device__ float g_v   [KVTOK_* D_];
__device__ float g_kvln[KVTOK_* D_];
__device__ float g_attn[TOK_  * D_];
__device__ float g_x1  [TOK_  * D_];
__device__ float g_ffn [TOK_  * DFF_];
__device__ float g_wt  [16u * 1024u * 1024u];   // transposed weights, 64 MB

// ---------------- helpers ---------------------------------------------------------
__device__ __forceinline__ uint32_t smem_u32(const void* p) {
    uint32_t a;
    asm("{ .reg .u64 t; cvta.to.shared.u64 t, %1; cvt.u32.u64 %0, t; }" : "=r"(a) : "l"(p));
    return a;
}

__device__ __forceinline__ float to_tf32(float x) {
    uint32_t u;
    asm("cvt.rna.tf32.f32 %0, %1;" : "=r"(u) : "f"(x));
    return __uint_as_float(u);
}

__device__ __forceinline__ void cp16(uint32_t s, const void* g) {
    asm volatile("cp.async.cg.shared.global [%0], [%1], 16;" :: "r"(s), "l"(g));
}
__device__ __forceinline__ void cp_commit() {
    asm volatile("cp.async.commit_group;" ::: "memory");
}
template<int N>
__device__ __forceinline__ void cp_wait() {
    asm volatile("cp.async.wait_group %0;" :: "n"(N) : "memory");
}

// m16n8k8 tf32 MMA, C += A*B
__device__ __forceinline__ void mma8(float* c, const uint32_t* a, const uint32_t* b) {
    asm volatile(
        "mma.sync.aligned.m16n8k8.row.col.f32.tf32.tf32.f32 "
        "{%0,%1,%2,%3}, {%4,%5,%6,%7}, {%8,%9}, {%0,%1,%2,%3};"
        : "+f"(c[0]), "+f"(c[1]), "+f"(c[2]), "+f"(c[3])
        : "r"(a[0]), "r"(a[1]), "r"(a[2]), "r"(a[3]), "r"(b[0]), "r"(b[1]));
}

// ---------------- weight transpose: WT[n*K+k] = tf32(W[k*N+n]) -------------------
__global__ __launch_bounds__(256) void transpose_kernel(
    const float* __restrict__ W, float* __restrict__ WT, int K, int N)
{
    __shared__ float t[32][33];
    int kb = blockIdx.y * 32, nb = blockIdx.x * 32;
    int tx = threadIdx.x & 31, ty4 = (threadIdx.x >> 5) * 4;
    #pragma unroll
    for (int r = 0; r < 4; r++)
        t[ty4 + r][tx] = W[(size_t)(kb + ty4 + r) * N + nb + tx];
    __syncthreads();
    #pragma unroll
    for (int r = 0; r < 4; r++)
        WT[(size_t)(nb + ty4 + r) * K + kb + tx] = to_tf32(t[tx][ty4 + r]);
}

// ---------------- LayerNorm: one block (256 thr) per row of 1024 ----------------
__global__ __launch_bounds__(256) void ln_kernel(
    const float* __restrict__ x, const float* __restrict__ g,
    const float* __restrict__ b, float* __restrict__ out)
{
    int row = blockIdx.x;
    int tid = threadIdx.x;
    const float4* xr = reinterpret_cast<const float4*>(x + (size_t)row * D_);
    float4 v4 = xr[tid];
    float s  = v4.x + v4.y + v4.z + v4.w;
    float ss = v4.x*v4.x + v4.y*v4.y + v4.z*v4.z + v4.w*v4.w;

    __shared__ float sh1[8], sh2[8];
    int lane = tid & 31, wid = tid >> 5;
    #pragma unroll
    for (int o = 16; o; o >>= 1) {
        s  += __shfl_down_sync(0xffffffffu, s,  o);
        ss += __shfl_down_sync(0xffffffffu, ss, o);
    }
    if (lane == 0) { sh1[wid] = s; sh2[wid] = ss; }
    __syncthreads();
    if (tid < 32) {
        s  = (tid < 8) ? sh1[tid] : 0.f;
        ss = (tid < 8) ? sh2[tid] : 0.f;
        #pragma unroll
        for (int o = 4; o; o >>= 1) {
            s  += __shfl_down_sync(0xffffffffu, s,  o);
            ss += __shfl_down_sync(0xffffffffu, ss, o);
        }
        if (tid == 0) { sh1[0] = s; sh2[0] = ss; }
    }
    __syncthreads();
    float mean = sh1[0] * (1.0f / D_);
    float var  = sh2[0] * (1.0f / D_) - mean * mean;
    float rstd = rsqrtf(var + 1e-5f);

    const float4 g4 = reinterpret_cast<const float4*>(g)[tid];
    const float4 b4 = reinterpret_cast<const float4*>(b)[tid];
    float4 o4;
    o4.x = to_tf32((v4.x - mean) * rstd * g4.x + b4.x);
    o4.y = to_tf32((v4.y - mean) * rstd * g4.y + b4.y);
    o4.z = to_tf32((v4.z - mean) * rstd * g4.z + b4.z);
    o4.w = to_tf32((v4.w - mean) * rstd * g4.w + b4.w);
    reinterpret_cast<float4*>(out + (size_t)row * D_)[tid] = o4;
}

// ---------------- tf32 mma.sync GEMM: C = A[MxK] @ WT[NxK]^T (+resid)(+gelu) -----
template<bool GELU, bool CVT>
__global__ __launch_bounds__(256) void gemm_mma(
    const float* __restrict__ A, const float* __restrict__ WT,
    const float* __restrict__ resid, float* __restrict__ C,
    int M, int N, int K)
{
    __shared__ float As[2][128][20];
    __shared__ float Bs[2][128][20];

    int tid = threadIdx.x;
    int wid = tid >> 5, lane = tid & 31;
    int warpM = wid >> 1, warpN = wid & 1;
    int grp = lane >> 2, tig = lane & 3;

    int n0 = blockIdx.x * 128, m0 = blockIdx.y * 128;
    const float* Ab = A  + (size_t)m0 * K;
    const float* Bb = WT + (size_t)n0 * K;

    float acc[2][8][4];
    #pragma unroll
    for (int i = 0; i < 2; i++)
        #pragma unroll
        for (int j = 0; j < 8; j++)
            #pragma unroll
            for (int q = 0; q < 4; q++) acc[i][j][q] = 0.f;

    int nk = K >> 4;

    {
        #pragma unroll
        for (int i = 0; i < 2; i++) {
            int idx = tid + i * 256;
            int m = idx >> 2, kc = (idx & 3) * 4;
            cp16(smem_u32(&As[0][m][kc]), Ab + (size_t)m * K + kc);
            cp16(smem_u32(&Bs[0][m][kc]), Bb + (size_t)m * K + kc);
        }
        cp_commit();
    }

    for (int kt = 0; kt < nk; kt++) {
        int buf = kt & 1;
        if (kt + 1 < nk) {
            int k0 = (kt + 1) << 4;
            #pragma unroll
            for (int i = 0; i < 2; i++) {
                int idx = tid + i * 256;
                int m = idx >> 2, kc = (idx & 3) * 4;
                cp16(smem_u32(&As[buf ^ 1][m][kc]), Ab + (size_t)m * K + k0 + kc);
                cp16(smem_u32(&Bs[buf ^ 1][m][kc]), Bb + (size_t)m * K + k0 + kc);
            }
            cp_commit();
            cp_wait<1>();
        } else {
            cp_wait<0>();
        }
        __syncthreads();

        #pragma unroll
        for (int ks = 0; ks < 2; ks++) {
            int k = ks * 8;
            uint32_t af[2][4], bf[8][2];
            #pragma unroll
            for (int mt = 0; mt < 2; mt++) {
                int rA = warpM * 32 + mt * 16 + grp;
                af[mt][0] = __float_as_uint(As[buf][rA    ][k + tig]);
                af[mt][1] = __float_as_uint(As[buf][rA + 8][k + tig]);
                af[mt][2] = __float_as_uint(As[buf][rA    ][k + tig + 4]);
                af[mt][3] = __float_as_uint(As[buf][rA + 8][k + tig + 4]);
            }
            #pragma unroll
            for (int nt = 0; nt < 8; nt++) {
                int rB = warpN * 64 + nt * 8 + grp;
                bf[nt][0] = __float_as_uint(Bs[buf][rB][k + tig]);
                bf[nt][1] = __float_as_uint(Bs[buf][rB][k + tig + 4]);
            }
            #pragma unroll
            for (int mt = 0; mt < 2; mt++)
                #pragma unroll
                for (int nt = 0; nt < 8; nt++)
                    mma8(acc[mt][nt], af[mt], bf[nt]);
        }
        __syncthreads();
    }

    #pragma unroll
    for (int mt = 0; mt < 2; mt++) {
        int row = m0 + warpM * 32 + mt * 16 + grp;
        #pragma unroll
        for (int nt = 0; nt < 8; nt++) {
            int col = n0 + warpN * 64 + nt * 8 + 2 * tig;
            #pragma unroll
            for (int half = 0; half < 2; half++) {
                int r = row + half * 8;
                float v0 = acc[mt][nt][half * 2 + 0];
                float v1 = acc[mt][nt][half * 2 + 1];
                if (GELU) {
                    v0 = 0.5f * v0 * (1.0f + erff(v0 * 0.70710678118654752f));
                    v1 = 0.5f * v1 * (1.0f + erff(v1 * 0.70710678118654752f));
                }
                size_t base = (size_t)r * N + col;
                if (resid) {
                    float2 rv = *reinterpret_cast<const float2*>(resid + base);
                    v0 += rv.x; v1 += rv.y;
                }
                if (CVT) { v0 = to_tf32(v0); v1 = to_tf32(v1); }
                float2 ov = {v0, v1};
                *reinterpret_cast<float2*>(C + base) = ov;
            }
        }
    }
}

// ---------------- tensor-core flash attention (tf32 mma, online softmax) --------
// Block: 128 threads (4 warps), 64 queries x head-dim 64. Per warp: 16 q rows.
// K/V 64x64 tiles, cp.async double-buffered. K smem stride 68 (bank 4g+t),
// V stride 72 (bank 8t+g) -> conflict-free fragment LDS. P via warp-private smem.
#define KSTR 68
#define VSTR 72
#define ATT_SMEM_FLOATS (2 * (64 * KSTR + 64 * VSTR) + 4 * 16 * KSTR)
#define ATT_SMEM_BYTES  (ATT_SMEM_FLOATS * 4)

template<bool CAUSAL>
__global__ __launch_bounds__(128) void attn_mma(
    const float* __restrict__ Q, const float* __restrict__ Kg,
    const float* __restrict__ Vg, float* __restrict__ O,
    int klen, int q_tokens_per_batch, int kv_tokens_per_batch)
{
    extern __shared__ float sm[];
    int tid = threadIdx.x, w = tid >> 5, lane = tid & 31;
    int grp = lane >> 2, tig = lane & 3;
    int qt = blockIdx.x, h = blockIdx.y, b = blockIdx.z;
    int qbase  = b * q_tokens_per_batch + qt * 64;
    int kvbase = b * kv_tokens_per_batch;

    const int KV_BUF = 64 * KSTR + 64 * VSTR;
    float* Ksm0 = sm;
    float* Vsm0 = sm + 64 * KSTR;
    float* Ksm1 = sm + KV_BUF;
    float* Vsm1 = sm + KV_BUF + 64 * KSTR;
    float* Ps   = sm + 2 * KV_BUF + w * (16 * KSTR);

    // ---- stage Q through smem, build A-fragments (scale premultiplied) ----
    for (int i = tid; i < 64 * 16; i += 128) {
        int r = i >> 4, c4 = (i & 15) << 2;
        *reinterpret_cast<float4*>(&Ksm0[r * KSTR + c4]) =
            *reinterpret_cast<const float4*>(&Q[(size_t)(qbase + r) * D_ + h * HD_ + c4]);
    }
    __syncthreads();
    uint32_t aq[8][4];
    {
        int r0 = w * 16 + grp;
        #pragma unroll
        for (int kc = 0; kc < 8; kc++) {
            int c = kc * 8 + tig;
            aq[kc][0] = __float_as_uint(Ksm0[r0 * KSTR + c] * 0.125f);
            aq[kc][1] = __float_as_uint(Ksm0[(r0 + 8) * KSTR + c] * 0.125f);
            aq[kc][2] = __float_as_uint(Ksm0[r0 * KSTR + c + 4] * 0.125f);
            aq[kc][3] = __float_as_uint(Ksm0[(r0 + 8) * KSTR + c + 4] * 0.125f);
        }
    }
    __syncthreads();

    float o[8][4];
    #pragma unroll
    for (int i = 0; i < 8; i++)
        #pragma unroll
        for (int j = 0; j < 4; j++) o[i][j] = 0.f;
    float m0 = -1e30f, m1 = -1e30f, l0 = 0.f, l1 = 0.f;

    int ktiles = klen >> 6;
    if (CAUSAL && qt + 1 < ktiles) ktiles = qt + 1;

    // prologue: load key tile 0 into buffer 0
    {
        for (int i = tid; i < 64 * 16; i += 128) {
            int r = i >> 4, c4 = (i & 15) << 2;
            size_t gofs = (size_t)(kvbase + r) * D_ + h * HD_ + c4;
            cp16(smem_u32(&Ksm0[r * KSTR + c4]), Kg + gofs);
            cp16(smem_u32(&Vsm0[r * VSTR + c4]), Vg + gofs);
        }
        cp_commit();
    }

    for (int kt = 0; kt < ktiles; kt++) {
        int buf = kt & 1;
        float* Ks = buf ? Ksm1 : Ksm0;
        float* Vs = buf ? Vsm1 : Vsm0;
        if (kt + 1 < ktiles) {
            float* Kn = buf ? Ksm0 : Ksm1;
            float* Vn = buf ? Vsm0 : Vsm1;
            int kb = kvbase + (kt + 1) * 64;
            for (int i = tid; i < 64 * 16; i += 128) {
                int r = i >> 4, c4 = (i & 15) << 2;
                size_t gofs = (size_t)(kb + r) * D_ + h * HD_ + c4;
                cp16(smem_u32(&Kn[r * KSTR + c4]), Kg + gofs);
                cp16(smem_u32(&Vn[r * VSTR + c4]), Vg + gofs);
            }
            cp_commit();
            cp_wait<1>();
        } else {
            cp_wait<0>();
        }
        __syncthreads();

        // ---- S = Q @ K^T ----
        float s[8][4];
        #pragma unroll
        for (int nt = 0; nt < 8; nt++)
            #pragma unroll
            for (int j = 0; j < 4; j++) s[nt][j] = 0.f;

        #pragma unroll
        for (int kc = 0; kc < 8; kc++) {
            #pragma unroll
            for (int nt = 0; nt < 8; nt++) {
                uint32_t bk[2];
                int key = nt * 8 + grp;
                bk[0] = __float_as_uint(Ks[key * KSTR + kc * 8 + tig]);
                bk[1] = __float_as_uint(Ks[key * KSTR + kc * 8 + tig + 4]);
                mma8(s[nt], aq[kc], bk);
            }
        }

        // ---- causal mask (diagonal tile only) ----
        if (CAUSAL && kt == qt) {
            int r0 = qt * 64 + w * 16 + grp;   // batch-local query row
            #pragma unroll
            for (int nt = 0; nt < 8; nt++) {
                int c = kt * 64 + nt * 8 + 2 * tig;
                if (c     > r0)     s[nt][0] = -1e30f;
                if (c + 1 > r0)     s[nt][1] = -1e30f;
                if (c     > r0 + 8) s[nt][2] = -1e30f;
                if (c + 1 > r0 + 8) s[nt][3] = -1e30f;
            }
        }

        // ---- online softmax ----
        float t0 = -1e30f, t1 = -1e30f;
        #pragma unroll
        for (int nt = 0; nt < 8; nt++) {
            t0 = fmaxf(t0, fmaxf(s[nt][0], s[nt][1]));
            t1 = fmaxf(t1, fmaxf(s[nt][2], s[nt][3]));
        }
        t0 = fmaxf(t0, __shfl_xor_sync(0xffffffffu, t0, 1));
        t0 = fmaxf(t0, __shfl_xor_sync(0xffffffffu, t0, 2));
        t1 = fmaxf(t1, __shfl_xor_sync(0xffffffffu, t1, 1));
        t1 = fmaxf(t1, __shfl_xor_sync(0xffffffffu, t1, 2));
        float nm0 = fmaxf(m0, t0), nm1 = fmaxf(m1, t1);
        float c0 = __expf(m0 - nm0), c1 = __expf(m1 - nm1);
        float ts0 = 0.f, ts1 = 0.f;
        #pragma unroll
        for (int nt = 0; nt < 8; nt++) {
            s[nt][0] = __expf(s[nt][0] - nm0);
            s[nt][1] = __expf(s[nt][1] - nm0);
            s[nt][2] = __expf(s[nt][2] - nm1);
            s[nt][3] = __expf(s[nt][3] - nm1);
            ts0 += s[nt][0] + s[nt][1];
            ts1 += s[nt][2] + s[nt][3];
        }
        ts0 += __shfl_xor_sync(0xffffffffu, ts0, 1);
        ts0 += __shfl_xor_sync(0xffffffffu, ts0, 2);
        ts1 += __shfl_xor_sync(0xffffffffu, ts1, 1);
        ts1 += __shfl_xor_sync(0xffffffffu, ts1, 2);
        l0 = l0 * c0 + ts0;
        l1 = l1 * c1 + ts1;
        m0 = nm0; m1 = nm1;
        #pragma unroll
        for (int nt = 0; nt < 8; nt++) {
            o[nt][0] *= c0; o[nt][1] *= c0;
            o[nt][2] *= c1; o[nt][3] *= c1;
        }

        // ---- P to warp-private smem (C-layout -> A-layout roundtrip) ----
        #pragma unroll
        for (int nt = 0; nt < 8; nt++) {
            float2 p0 = {s[nt][0], s[nt][1]};
            float2 p1 = {s[nt][2], s[nt][3]};
            *reinterpret_cast<float2*>(&Ps[grp * KSTR + nt * 8 + 2 * tig]) = p0;
            *reinterpret_cast<float2*>(&Ps[(grp + 8) * KSTR + nt * 8 + 2 * tig]) = p1;
        }
        __syncwarp();

        // ---- O += P @ V ----
        #pragma unroll
        for (int kc = 0; kc < 8; kc++) {
            uint32_t ap[4];
            ap[0] = __float_as_uint(Ps[grp * KSTR + kc * 8 + tig]);
            ap[1] = __float_as_uint(Ps[(grp + 8) * KSTR + kc * 8 + tig]);
            ap[2] = __float_as_uint(Ps[grp * KSTR + kc * 8 + tig + 4]);
            ap[3] = __float_as_uint(Ps[(grp + 8) * KSTR + kc * 8 + tig + 4]);
            #pragma unroll
            for (int nt2 = 0; nt2 < 8; nt2++) {
                uint32_t bv[2];
                bv[0] = __float_as_uint(Vs[(kc * 8 + tig) * VSTR + nt2 * 8 + grp]);
                bv[1] = __float_as_uint(Vs[(kc * 8 + tig + 4) * VSTR + nt2 * 8 + grp]);
                mma8(o[nt2], ap, bv);
            }
        }
        __syncwarp();
        __syncthreads();   // protect K/V buffers before next prefetch overwrite
    }

    // ---- epilogue ----
    float il0 = 1.0f / l0, il1 = 1.0f / l1;
    int r0 = qbase + w * 16 + grp;
    #pragma unroll
    for (int nt2 = 0; nt2 < 8; nt2++) {
        int col = h * HD_ + nt2 * 8 + 2 * tig;
        float2 v0 = {to_tf32(o[nt2][0] * il0), to_tf32(o[nt2][1] * il0)};
        float2 v1 = {to_tf32(o[nt2][2] * il1), to_tf32(o[nt2][3] * il1)};
        *reinterpret_cast<float2*>(&O[(size_t)r0 * D_ + col]) = v0;
        *reinterpret_cast<float2*>(&O[(size_t)(r0 + 8) * D_ + col]) = v1;
    }
}

// ---------------- launch ---------------------------------------------------------
extern "C" void kernel_launch(void* const* d_in, const int* in_sizes, int n_in,
                              void* d_out, int out_size)
{
    const float* x         = (const float*)d_in[0];
    const float* neighbors = (const float*)d_in[1];
    const float* sa_ln_g   = (const float*)d_in[2];
    const float* sa_ln_b   = (const float*)d_in[3];
    const float* sa_wq     = (const float*)d_in[4];
    const float* sa_wk     = (const float*)d_in[5];
    const float* sa_wv     = (const float*)d_in[6];
    const float* sa_wo     = (const float*)d_in[7];
    const float* cca_lnq_g = (const float*)d_in[8];
    const float* cca_lnq_b = (const float*)d_in[9];
    const float* cca_lnkv_g= (const float*)d_in[10];
    const float* cca_lnkv_b= (const float*)d_in[11];
    const float* cca_wq    = (const float*)d_in[12];
    const float* cca_wk    = (const float*)d_in[13];
    const float* cca_wv    = (const float*)d_in[14];
    const float* cca_wo    = (const float*)d_in[15];
    const float* ffn_ln_g  = (const float*)d_in[16];
    const float* ffn_ln_b  = (const float*)d_in[17];
    const float* ffn_w1    = (const float*)d_in[18];
    const float* ffn_w2    = (const float*)d_in[19];
    float* out = (float*)d_out;

    float *h, *q, *k, *v, *kvln, *attn, *x1, *ffn, *wt;
    cudaGetSymbolAddress((void**)&h,    g_h);
    cudaGetSymbolAddress((void**)&q,    g_q);
    cudaGetSymbolAddress((void**)&k,    g_k);
    cudaGetSymbolAddress((void**)&v,    g_v);
    cudaGetSymbolAddress((void**)&kvln, g_kvln);
    cudaGetSymbolAddress((void**)&attn, g_attn);
    cudaGetSymbolAddress((void**)&x1,   g_x1);
    cudaGetSymbolAddress((void**)&ffn,  g_ffn);
    cudaGetSymbolAddress((void**)&wt,   g_wt);

    const size_t MB = 1024 * 1024;
    float* wt_saq = wt + 0 * MB;
    float* wt_sak = wt + 1 * MB;
    float* wt_sav = wt + 2 * MB;
    float* wt_sao = wt + 3 * MB;
    float* wt_ccq = wt + 4 * MB;
    float* wt_cck = wt + 5 * MB;
    float* wt_ccv = wt + 6 * MB;
    float* wt_cco = wt + 7 * MB;
    float* wt_f1  = wt + 8 * MB;    // [DFF, D]
    float* wt_f2  = wt + 12 * MB;   // [D, DFF]

    cudaFuncSetAttribute(attn_mma<true >, cudaFuncAttributeMaxDynamicSharedMemorySize, ATT_SMEM_BYTES);
    cudaFuncSetAttribute(attn_mma<false>, cudaFuncAttributeMaxDynamicSharedMemorySize, ATT_SMEM_BYTES);

    dim3 blk256(256), blk128(128);
    dim3 gT(D_ / 32, D_ / 32);
    dim3 gTf1(DFF_ / 32, D_ / 32);
    dim3 gTf2(D_ / 32, DFF_ / 32);

    // ---- weight transposes (+tf32 rounding) ----
    transpose_kernel<<<gT, blk256>>>(sa_wq,  wt_saq, D_, D_);
    transpose_kernel<<<gT, blk256>>>(sa_wk,  wt_sak, D_, D_);
    transpose_kernel<<<gT, blk256>>>(sa_wv,  wt_sav, D_, D_);
    transpose_kernel<<<gT, blk256>>>(sa_wo,  wt_sao, D_, D_);
    transpose_kernel<<<gT, blk256>>>(cca_wq, wt_ccq, D_, D_);
    transpose_kernel<<<gT, blk256>>>(cca_wk, wt_cck, D_, D_);
    transpose_kernel<<<gT, blk256>>>(cca_wv, wt_ccv, D_, D_);
    transpose_kernel<<<gT, blk256>>>(cca_wo, wt_cco, D_, D_);
    transpose_kernel<<<gTf1, blk256>>>(ffn_w1, wt_f1, D_, DFF_);
    transpose_kernel<<<gTf2, blk256>>>(ffn_w2, wt_f2, DFF_, D_);

    dim3 gProj(D_ / 128, TOK_ / 128);          // (8, 32)
    dim3 gKV(D_ / 128, KVTOK_ / 128);          // (8, 128)
    dim3 gFFN1(DFF_ / 128, TOK_ / 128);        // (32, 32)

    // ---- self-attention ----
    ln_kernel<<<TOK_, blk256>>>(x, sa_ln_g, sa_ln_b, h);
    gemm_mma<false,false><<<gProj, blk256>>>(h, wt_saq, nullptr, q, TOK_, D_, D_);
    gemm_mma<false,false><<<gProj, blk256>>>(h, wt_sak, nullptr, k, TOK_, D_, D_);
    gemm_mma<false,false><<<gProj, blk256>>>(h, wt_sav, nullptr, v, TOK_, D_, D_);
    attn_mma<true><<<dim3(T_ / 64, H_, B_), blk128, ATT_SMEM_BYTES>>>(
        q, k, v, attn, T_, T_, T_);
    gemm_mma<false,false><<<gProj, blk256>>>(attn, wt_sao, x, x1, TOK_, D_, D_);

    // ---- chunked cross-attention (T == NC*chunk; reshapes are views) ----
    ln_kernel<<<TOK_,  blk256>>>(x1, cca_lnq_g, cca_lnq_b, h);
    ln_kernel<<<KVTOK_, blk256>>>(neighbors, cca_lnkv_g, cca_lnkv_b, kvln);
    gemm_mma<false,false><<<gProj, blk256>>>(h,    wt_ccq, nullptr, q, TOK_,   D_, D_);
    gemm_mma<false,false><<<gKV,   blk256>>>(kvln, wt_cck, nullptr, k, KVTOK_, D_, D_);
    gemm_mma<false,false><<<gKV,   blk256>>>(kvln, wt_ccv, nullptr, v, KVTOK_, D_, D_);
    attn_mma<false><<<dim3(1, H_, NCH_), blk128, ATT_SMEM_BYTES>>>(
        q, k, v, attn, KV_, CH_, KV_);
    gemm_mma<false,false><<<gProj, blk256>>>(attn, wt_cco, x1, out, TOK_, D_, D_);

    // ---- FFN ----
    ln_kernel<<<TOK_, blk256>>>(out, ffn_ln_g, ffn_ln_b, h);
    gemm_mma<true, true ><<<gFFN1, blk256>>>(h,   wt_f1, nullptr, ffn, TOK_, DFF_, D_);
    gemm_mma<false,false><<<gProj, blk256>>>(ffn, wt_f2, out,     out, TOK_, D_, DFF_);
}

// round 5
// speedup vs baseline: 3.8979x; 1.1088x over previous
#include <cuda_runtime.h>
#include <math.h>
#include <cstdint>

// Problem constants (fixed by setup_inputs)
#define B_     2
#define T_     2048
#define D_     1024
#define H_     16
#define HD_    64
#define TOK_   4096      // B*T
#define NCH_   64        // B*NC chunks
#define CH_    64        // chunk_size
#define KV_    256       // K*NL
#define KVTOK_ 16384     // NCH_*KV_
#define DFF_   4096

// ---------------- scratch (static device globals; no allocation) ----------------
__device__ float g_h   [TOK_  * D_];
__device__ float g_q   [TOK_  * D_];
__device__ float g_k   [KVTOK_* D_];
__device__ float g_v   [KVTOK_* D_];
__device__ float g_kvln[KVTOK_* D_];
__device__ float g_attn[TOK_  * D_];
__device__ float g_x1  [TOK_  * D_];
__device__ float g_ffn [TOK_  * DFF_];
__device__ float g_wt  [16u * 1024u * 1024u];   // transposed weights, 64 MB

// ---------------- helpers ---------------------------------------------------------
__device__ __forceinline__ uint32_t smem_u32(const void* p) {
    uint32_t a;
    asm("{ .reg .u64 t; cvta.to.shared.u64 t, %1; cvt.u32.u64 %0, t; }" : "=r"(a) : "l"(p));
    return a;
}

__device__ __forceinline__ float to_tf32(float x) {
    uint32_t u;
    asm("cvt.rna.tf32.f32 %0, %1;" : "=r"(u) : "f"(x));
    return __uint_as_float(u);
}

__device__ __forceinline__ void cp16(uint32_t s, const void* g) {
    asm volatile("cp.async.cg.shared.global [%0], [%1], 16;" :: "r"(s), "l"(g));
}
__device__ __forceinline__ void cp_commit() {
    asm volatile("cp.async.commit_group;" ::: "memory");
}
template<int N>
__device__ __forceinline__ void cp_wait() {
    asm volatile("cp.async.wait_group %0;" :: "n"(N) : "memory");
}

// m16n8k8 tf32 MMA, C += A*B
__device__ __forceinline__ void mma8(float* c, const uint32_t* a, const uint32_t* b) {
    asm volatile(
        "mma.sync.aligned.m16n8k8.row.col.f32.tf32.tf32.f32 "
        "{%0,%1,%2,%3}, {%4,%5,%6,%7}, {%8,%9}, {%0,%1,%2,%3};"
        : "+f"(c[0]), "+f"(c[1]), "+f"(c[2]), "+f"(c[3])
        : "r"(a[0]), "r"(a[1]), "r"(a[2]), "r"(a[3]), "r"(b[0]), "r"(b[1]));
}

// ---------------- batched weight transpose: WT[n*K+k] = tf32(W[k*N+n]) -----------
struct TP8 { const float* src[8]; float* dst[8]; };

__global__ __launch_bounds__(256) void transpose8_kernel(TP8 p, int K, int N)
{
    __shared__ float t[32][33];
    const float* W = p.src[blockIdx.z];
    float* WT = p.dst[blockIdx.z];
    int kb = blockIdx.y * 32, nb = blockIdx.x * 32;
    int tx = threadIdx.x & 31, ty4 = (threadIdx.x >> 5) * 4;
    #pragma unroll
    for (int r = 0; r < 4; r++)
        t[ty4 + r][tx] = W[(size_t)(kb + ty4 + r) * N + nb + tx];
    __syncthreads();
    #pragma unroll
    for (int r = 0; r < 4; r++)
        WT[(size_t)(nb + ty4 + r) * K + kb + tx] = to_tf32(t[tx][ty4 + r]);
}

__global__ __launch_bounds__(256) void transpose_kernel(
    const float* __restrict__ W, float* __restrict__ WT, int K, int N)
{
    __shared__ float t[32][33];
    int kb = blockIdx.y * 32, nb = blockIdx.x * 32;
    int tx = threadIdx.x & 31, ty4 = (threadIdx.x >> 5) * 4;
    #pragma unroll
    for (int r = 0; r < 4; r++)
        t[ty4 + r][tx] = W[(size_t)(kb + ty4 + r) * N + nb + tx];
    __syncthreads();
    #pragma unroll
    for (int r = 0; r < 4; r++)
        WT[(size_t)(nb + ty4 + r) * K + kb + tx] = to_tf32(t[tx][ty4 + r]);
}

// ---------------- LayerNorm: one block (256 thr) per row of 1024 ----------------
__global__ __launch_bounds__(256) void ln_kernel(
    const float* __restrict__ x, const float* __restrict__ g,
    const float* __restrict__ b, float* __restrict__ out)
{
    int row = blockIdx.x;
    int tid = threadIdx.x;
    const float4* xr = reinterpret_cast<const float4*>(x + (size_t)row * D_);
    float4 v4 = xr[tid];
    float s  = v4.x + v4.y + v4.z + v4.w;
    float ss = v4.x*v4.x + v4.y*v4.y + v4.z*v4.z + v4.w*v4.w;

    __shared__ float sh1[8], sh2[8];
    int lane = tid & 31, wid = tid >> 5;
    #pragma unroll
    for (int o = 16; o; o >>= 1) {
        s  += __shfl_down_sync(0xffffffffu, s,  o);
        ss += __shfl_down_sync(0xffffffffu, ss, o);
    }
    if (lane == 0) { sh1[wid] = s; sh2[wid] = ss; }
    __syncthreads();
    if (tid < 32) {
        s  = (tid < 8) ? sh1[tid] : 0.f;
        ss = (tid < 8) ? sh2[tid] : 0.f;
        #pragma unroll
        for (int o = 4; o; o >>= 1) {
            s  += __shfl_down_sync(0xffffffffu, s,  o);
            ss += __shfl_down_sync(0xffffffffu, ss, o);
        }
        if (tid == 0) { sh1[0] = s; sh2[0] = ss; }
    }
    __syncthreads();
    float mean = sh1[0] * (1.0f / D_);
    float var  = sh2[0] * (1.0f / D_) - mean * mean;
    float rstd = rsqrtf(var + 1e-5f);

    const float4 g4 = reinterpret_cast<const float4*>(g)[tid];
    const float4 b4 = reinterpret_cast<const float4*>(b)[tid];
    float4 o4;
    o4.x = to_tf32((v4.x - mean) * rstd * g4.x + b4.x);
    o4.y = to_tf32((v4.y - mean) * rstd * g4.y + b4.y);
    o4.z = to_tf32((v4.z - mean) * rstd * g4.z + b4.z);
    o4.w = to_tf32((v4.w - mean) * rstd * g4.w + b4.w);
    reinterpret_cast<float4*>(out + (size_t)row * D_)[tid] = o4;
}

// ---------------- tf32 mma.sync GEMM: C = A[MxK] @ WT[NxK]^T (+resid)(+gelu) -----
// 128x128 block tile, 128 threads (4 warps, 2x2), warp tile 64x64, BK=16,
// 3-stage cp.async pipeline, dynamic smem (stride 20 -> conflict-free frag LDS).
#define GSTR 20
#define GEMM_SMEM (3 * 2 * 128 * GSTR * 4)      // 61440 bytes

template<bool GELU, bool CVT>
__global__ __launch_bounds__(128) void gemm_mma(
    const float* __restrict__ A, const float* __restrict__ WT,
    const float* __restrict__ resid, float* __restrict__ C,
    int M, int N, int K)
{
    extern __shared__ float sm[];
    float* As = sm;                      // [3][128][GSTR]
    float* Bs = sm + 3 * 128 * GSTR;     // [3][128][GSTR]

    int tid = threadIdx.x;
    int wid = tid >> 5, lane = tid & 31;
    int warpM = wid >> 1, warpN = wid & 1;
    int grp = lane >> 2, tig = lane & 3;

    int n0 = blockIdx.x * 128, m0 = blockIdx.y * 128;
    const float* Ab = A  + (size_t)m0 * K;
    const float* Bb = WT + (size_t)n0 * K;

    float acc[4][8][4];
    #pragma unroll
    for (int i = 0; i < 4; i++)
        #pragma unroll
        for (int j = 0; j < 8; j++)
            #pragma unroll
            for (int q = 0; q < 4; q++) acc[i][j][q] = 0.f;

    int nk = K >> 4;

    // stage loader: 128 threads x 4 float4 per matrix
    auto load_stage = [&](int st, int kt) {
        int k0 = kt << 4;
        float* Ast = As + st * 128 * GSTR;
        float* Bst = Bs + st * 128 * GSTR;
        #pragma unroll
        for (int i = 0; i < 4; i++) {
            int idx = tid + i * 128;
            int m = idx >> 2, kc = (idx & 3) * 4;
            cp16(smem_u32(Ast + m * GSTR + kc), Ab + (size_t)m * K + k0 + kc);
            cp16(smem_u32(Bst + m * GSTR + kc), Bb + (size_t)m * K + k0 + kc);
        }
        cp_commit();
    };

    load_stage(0, 0);
    if (nk > 1) load_stage(1, 1);

    for (int kt = 0; kt < nk; kt++) {
        int buf = kt % 3;
        if (kt + 2 < nk) { load_stage((kt + 2) % 3, kt + 2); cp_wait<2>(); }
        else if (kt + 1 < nk) { cp_wait<1>(); }
        else { cp_wait<0>(); }
        __syncthreads();

        float* Abuf = As + buf * 128 * GSTR;
        float* Bbuf = Bs + buf * 128 * GSTR;

        #pragma unroll
        for (int ks = 0; ks < 2; ks++) {
            int k = ks * 8;
            uint32_t af[4][4], bf[8][2];
            #pragma unroll
            for (int mt = 0; mt < 4; mt++) {
                int rA = warpM * 64 + mt * 16 + grp;
                af[mt][0] = __float_as_uint(Abuf[rA * GSTR + k + tig]);
                af[mt][1] = __float_as_uint(Abuf[(rA + 8) * GSTR + k + tig]);
                af[mt][2] = __float_as_uint(Abuf[rA * GSTR + k + tig + 4]);
                af[mt][3] = __float_as_uint(Abuf[(rA + 8) * GSTR + k + tig + 4]);
            }
            #pragma unroll
            for (int nt = 0; nt < 8; nt++) {
                int rB = warpN * 64 + nt * 8 + grp;
                bf[nt][0] = __float_as_uint(Bbuf[rB * GSTR + k + tig]);
                bf[nt][1] = __float_as_uint(Bbuf[rB * GSTR + k + tig + 4]);
            }
            #pragma unroll
            for (int mt = 0; mt < 4; mt++)
                #pragma unroll
                for (int nt = 0; nt < 8; nt++)
                    mma8(acc[mt][nt], af[mt], bf[nt]);
        }
        __syncthreads();
    }

    #pragma unroll
    for (int mt = 0; mt < 4; mt++) {
        int row = m0 + warpM * 64 + mt * 16 + grp;
        #pragma unroll
        for (int nt = 0; nt < 8; nt++) {
            int col = n0 + warpN * 64 + nt * 8 + 2 * tig;
            #pragma unroll
            for (int half = 0; half < 2; half++) {
                int r = row + half * 8;
                float v0 = acc[mt][nt][half * 2 + 0];
                float v1 = acc[mt][nt][half * 2 + 1];
                if (GELU) {
                    v0 = 0.5f * v0 * (1.0f + erff(v0 * 0.70710678118654752f));
                    v1 = 0.5f * v1 * (1.0f + erff(v1 * 0.70710678118654752f));
                }
                size_t base = (size_t)r * N + col;
                if (resid) {
                    float2 rv = *reinterpret_cast<const float2*>(resid + base);
                    v0 += rv.x; v1 += rv.y;
                }
                if (CVT) { v0 = to_tf32(v0); v1 = to_tf32(v1); }
                float2 ov = {v0, v1};
                *reinterpret_cast<float2*>(C + base) = ov;
            }
        }
    }
}

// ---------------- tensor-core flash attention (tf32 mma, online softmax) --------
#define KSTR 68
#define VSTR 72
#define ATT_SMEM_FLOATS (2 * (64 * KSTR + 64 * VSTR) + 4 * 16 * KSTR)
#define ATT_SMEM_BYTES  (ATT_SMEM_FLOATS * 4)

template<bool CAUSAL>
__global__ __launch_bounds__(128) void attn_mma(
    const float* __restrict__ Q, const float* __restrict__ Kg,
    const float* __restrict__ Vg, float* __restrict__ O,
    int klen, int q_tokens_per_batch, int kv_tokens_per_batch)
{
    extern __shared__ float sm[];
    int tid = threadIdx.x, w = tid >> 5, lane = tid & 31;
    int grp = lane >> 2, tig = lane & 3;
    int qt = blockIdx.x, h = blockIdx.y, b = blockIdx.z;
    int qbase  = b * q_tokens_per_batch + qt * 64;
    int kvbase = b * kv_tokens_per_batch;

    const int KV_BUF = 64 * KSTR + 64 * VSTR;
    float* Ksm0 = sm;
    float* Vsm0 = sm + 64 * KSTR;
    float* Ksm1 = sm + KV_BUF;
    float* Vsm1 = sm + KV_BUF + 64 * KSTR;
    float* Ps   = sm + 2 * KV_BUF + w * (16 * KSTR);

    for (int i = tid; i < 64 * 16; i += 128) {
        int r = i >> 4, c4 = (i & 15) << 2;
        *reinterpret_cast<float4*>(&Ksm0[r * KSTR + c4]) =
            *reinterpret_cast<const float4*>(&Q[(size_t)(qbase + r) * D_ + h * HD_ + c4]);
    }
    __syncthreads();
    uint32_t aq[8][4];
    {
        int r0 = w * 16 + grp;
        #pragma unroll
        for (int kc = 0; kc < 8; kc++) {
            int c = kc * 8 + tig;
            aq[kc][0] = __float_as_uint(Ksm0[r0 * KSTR + c] * 0.125f);
            aq[kc][1] = __float_as_uint(Ksm0[(r0 + 8) * KSTR + c] * 0.125f);
            aq[kc][2] = __float_as_uint(Ksm0[r0 * KSTR + c + 4] * 0.125f);
            aq[kc][3] = __float_as_uint(Ksm0[(r0 + 8) * KSTR + c + 4] * 0.125f);
        }
    }
    __syncthreads();

    float o[8][4];
    #pragma unroll
    for (int i = 0; i < 8; i++)
        #pragma unroll
        for (int j = 0; j < 4; j++) o[i][j] = 0.f;
    float m0 = -1e30f, m1 = -1e30f, l0 = 0.f, l1 = 0.f;

    int ktiles = klen >> 6;
    if (CAUSAL && qt + 1 < ktiles) ktiles = qt + 1;

    {
        for (int i = tid; i < 64 * 16; i += 128) {
            int r = i >> 4, c4 = (i & 15) << 2;
            size_t gofs = (size_t)(kvbase + r) * D_ + h * HD_ + c4;
            cp16(smem_u32(&Ksm0[r * KSTR + c4]), Kg + gofs);
            cp16(smem_u32(&Vsm0[r * VSTR + c4]), Vg + gofs);
        }
        cp_commit();
    }

    for (int kt = 0; kt < ktiles; kt++) {
        int buf = kt & 1;
        float* Ks = buf ? Ksm1 : Ksm0;
        float* Vs = buf ? Vsm1 : Vsm0;
        if (kt + 1 < ktiles) {
            float* Kn = buf ? Ksm0 : Ksm1;
            float* Vn = buf ? Vsm0 : Vsm1;
            int kb = kvbase + (kt + 1) * 64;
            for (int i = tid; i < 64 * 16; i += 128) {
                int r = i >> 4, c4 = (i & 15) << 2;
                size_t gofs = (size_t)(kb + r) * D_ + h * HD_ + c4;
                cp16(smem_u32(&Kn[r * KSTR + c4]), Kg + gofs);
                cp16(smem_u32(&Vn[r * VSTR + c4]), Vg + gofs);
            }
            cp_commit();
            cp_wait<1>();
        } else {
            cp_wait<0>();
        }
        __syncthreads();

        float s[8][4];
        #pragma unroll
        for (int nt = 0; nt < 8; nt++)
            #pragma unroll
            for (int j = 0; j < 4; j++) s[nt][j] = 0.f;

        #pragma unroll
        for (int kc = 0; kc < 8; kc++) {
            #pragma unroll
            for (int nt = 0; nt < 8; nt++) {
                uint32_t bk[2];
                int key = nt * 8 + grp;
                bk[0] = __float_as_uint(Ks[key * KSTR + kc * 8 + tig]);
                bk[1] = __float_as_uint(Ks[key * KSTR + kc * 8 + tig + 4]);
                mma8(s[nt], aq[kc], bk);
            }
        }

        if (CAUSAL && kt == qt) {
            int r0 = qt * 64 + w * 16 + grp;
            #pragma unroll
            for (int nt = 0; nt < 8; nt++) {
                int c = kt * 64 + nt * 8 + 2 * tig;
                if (c     > r0)     s[nt][0] = -1e30f;
                if (c + 1 > r0)     s[nt][1] = -1e30f;
                if (c     > r0 + 8) s[nt][2] = -1e30f;
                if (c + 1 > r0 + 8) s[nt][3] = -1e30f;
            }
        }

        float t0 = -1e30f, t1 = -1e30f;
        #pragma unroll
        for (int nt = 0; nt < 8; nt++) {
            t0 = fmaxf(t0, fmaxf(s[nt][0], s[nt][1]));
            t1 = fmaxf(t1, fmaxf(s[nt][2], s[nt][3]));
        }
        t0 = fmaxf(t0, __shfl_xor_sync(0xffffffffu, t0, 1));
        t0 = fmaxf(t0, __shfl_xor_sync(0xffffffffu, t0, 2));
        t1 = fmaxf(t1, __shfl_xor_sync(0xffffffffu, t1, 1));
        t1 = fmaxf(t1, __shfl_xor_sync(0xffffffffu, t1, 2));
        float nm0 = fmaxf(m0, t0), nm1 = fmaxf(m1, t1);
        float c0 = __expf(m0 - nm0), c1 = __expf(m1 - nm1);
        float ts0 = 0.f, ts1 = 0.f;
        #pragma unroll
        for (int nt = 0; nt < 8; nt++) {
            s[nt][0] = __expf(s[nt][0] - nm0);
            s[nt][1] = __expf(s[nt][1] - nm0);
            s[nt][2] = __expf(s[nt][2] - nm1);
            s[nt][3] = __expf(s[nt][3] - nm1);
            ts0 += s[nt][0] + s[nt][1];
            ts1 += s[nt][2] + s[nt][3];
        }
        ts0 += __shfl_xor_sync(0xffffffffu, ts0, 1);
        ts0 += __shfl_xor_sync(0xffffffffu, ts0, 2);
        ts1 += __shfl_xor_sync(0xffffffffu, ts1, 1);
        ts1 += __shfl_xor_sync(0xffffffffu, ts1, 2);
        l0 = l0 * c0 + ts0;
        l1 = l1 * c1 + ts1;
        m0 = nm0; m1 = nm1;
        #pragma unroll
        for (int nt = 0; nt < 8; nt++) {
            o[nt][0] *= c0; o[nt][1] *= c0;
            o[nt][2] *= c1; o[nt][3] *= c1;
        }

        #pragma unroll
        for (int nt = 0; nt < 8; nt++) {
            float2 p0 = {s[nt][0], s[nt][1]};
            float2 p1 = {s[nt][2], s[nt][3]};
            *reinterpret_cast<float2*>(&Ps[grp * KSTR + nt * 8 + 2 * tig]) = p0;
            *reinterpret_cast<float2*>(&Ps[(grp + 8) * KSTR + nt * 8 + 2 * tig]) = p1;
        }
        __syncwarp();

        #pragma unroll
        for (int kc = 0; kc < 8; kc++) {
            uint32_t ap[4];
            ap[0] = __float_as_uint(Ps[grp * KSTR + kc * 8 + tig]);
            ap[1] = __float_as_uint(Ps[(grp + 8) * KSTR + kc * 8 + tig]);
            ap[2] = __float_as_uint(Ps[grp * KSTR + kc * 8 + tig + 4]);
            ap[3] = __float_as_uint(Ps[(grp + 8) * KSTR + kc * 8 + tig + 4]);
            #pragma unroll
            for (int nt2 = 0; nt2 < 8; nt2++) {
                uint32_t bv[2];
                bv[0] = __float_as_uint(Vs[(kc * 8 + tig) * VSTR + nt2 * 8 + grp]);
                bv[1] = __float_as_uint(Vs[(kc * 8 + tig + 4) * VSTR + nt2 * 8 + grp]);
                mma8(o[nt2], ap, bv);
            }
        }
        __syncwarp();
        __syncthreads();
    }

    float il0 = 1.0f / l0, il1 = 1.0f / l1;
    int r0 = qbase + w * 16 + grp;
    #pragma unroll
    for (int nt2 = 0; nt2 < 8; nt2++) {
        int col = h * HD_ + nt2 * 8 + 2 * tig;
        float2 v0 = {to_tf32(o[nt2][0] * il0), to_tf32(o[nt2][1] * il0)};
        float2 v1 = {to_tf32(o[nt2][2] * il1), to_tf32(o[nt2][3] * il1)};
        *reinterpret_cast<float2*>(&O[(size_t)r0 * D_ + col]) = v0;
        *reinterpret_cast<float2*>(&O[(size_t)(r0 + 8) * D_ + col]) = v1;
    }
}

// ---------------- launch ---------------------------------------------------------
extern "C" void kernel_launch(void* const* d_in, const int* in_sizes, int n_in,
                              void* d_out, int out_size)
{
    const float* x         = (const float*)d_in[0];
    const float* neighbors = (const float*)d_in[1];
    const float* sa_ln_g   = (const float*)d_in[2];
    const float* sa_ln_b   = (const float*)d_in[3];
    const float* sa_wq     = (const float*)d_in[4];
    const float* sa_wk     = (const float*)d_in[5];
    const float* sa_wv     = (const float*)d_in[6];
    const float* sa_wo     = (const float*)d_in[7];
    const float* cca_lnq_g = (const float*)d_in[8];
    const float* cca_lnq_b = (const float*)d_in[9];
    const float* cca_lnkv_g= (const float*)d_in[10];
    const float* cca_lnkv_b= (const float*)d_in[11];
    const float* cca_wq    = (const float*)d_in[12];
    const float* cca_wk    = (const float*)d_in[13];
    const float* cca_wv    = (const float*)d_in[14];
    const float* cca_wo    = (const float*)d_in[15];
    const float* ffn_ln_g  = (const float*)d_in[16];
    const float* ffn_ln_b  = (const float*)d_in[17];
    const float* ffn_w1    = (const float*)d_in[18];
    const float* ffn_w2    = (const float*)d_in[19];
    float* out = (float*)d_out;

    float *h, *q, *k, *v, *kvln, *attn, *x1, *ffn, *wt;
    cudaGetSymbolAddress((void**)&h,    g_h);
    cudaGetSymbolAddress((void**)&q,    g_q);
    cudaGetSymbolAddress((void**)&k,    g_k);
    cudaGetSymbolAddress((void**)&v,    g_v);
    cudaGetSymbolAddress((void**)&kvln, g_kvln);
    cudaGetSymbolAddress((void**)&attn, g_attn);
    cudaGetSymbolAddress((void**)&x1,   g_x1);
    cudaGetSymbolAddress((void**)&ffn,  g_ffn);
    cudaGetSymbolAddress((void**)&wt,   g_wt);

    const size_t MB = 1024 * 1024;
    float* wt_saq = wt + 0 * MB;
    float* wt_sak = wt + 1 * MB;
    float* wt_sav = wt + 2 * MB;
    float* wt_sao = wt + 3 * MB;
    float* wt_ccq = wt + 4 * MB;
    float* wt_cck = wt + 5 * MB;
    float* wt_ccv = wt + 6 * MB;
    float* wt_cco = wt + 7 * MB;
    float* wt_f1  = wt + 8 * MB;    // [DFF, D]
    float* wt_f2  = wt + 12 * MB;   // [D, DFF]

    cudaFuncSetAttribute(attn_mma<true >, cudaFuncAttributeMaxDynamicSharedMemorySize, ATT_SMEM_BYTES);
    cudaFuncSetAttribute(attn_mma<false>, cudaFuncAttributeMaxDynamicSharedMemorySize, ATT_SMEM_BYTES);
    cudaFuncSetAttribute(gemm_mma<false,false>, cudaFuncAttributeMaxDynamicSharedMemorySize, GEMM_SMEM);
    cudaFuncSetAttribute(gemm_mma<true ,true >, cudaFuncAttributeMaxDynamicSharedMemorySize, GEMM_SMEM);

    dim3 blk256(256), blk128(128);

    // ---- batched weight transposes (+tf32 rounding): 8 square + 2 FFN ----
    TP8 tp;
    tp.src[0] = sa_wq;  tp.dst[0] = wt_saq;
    tp.src[1] = sa_wk;  tp.dst[1] = wt_sak;
    tp.src[2] = sa_wv;  tp.dst[2] = wt_sav;
    tp.src[3] = sa_wo;  tp.dst[3] = wt_sao;
    tp.src[4] = cca_wq; tp.dst[4] = wt_ccq;
    tp.src[5] = cca_wk; tp.dst[5] = wt_cck;
    tp.src[6] = cca_wv; tp.dst[6] = wt_ccv;
    tp.src[7] = cca_wo; tp.dst[7] = wt_cco;
    transpose8_kernel<<<dim3(D_ / 32, D_ / 32, 8), blk256>>>(tp, D_, D_);
    transpose_kernel<<<dim3(DFF_ / 32, D_ / 32), blk256>>>(ffn_w1, wt_f1, D_, DFF_);
    transpose_kernel<<<dim3(D_ / 32, DFF_ / 32), blk256>>>(ffn_w2, wt_f2, DFF_, D_);

    dim3 gProj(D_ / 128, TOK_ / 128);          // (8, 32)
    dim3 gKV(D_ / 128, KVTOK_ / 128);          // (8, 128)
    dim3 gFFN1(DFF_ / 128, TOK_ / 128);        // (32, 32)

    // ---- self-attention ----
    ln_kernel<<<TOK_, blk256>>>(x, sa_ln_g, sa_ln_b, h);
    gemm_mma<false,false><<<gProj, blk128, GEMM_SMEM>>>(h, wt_saq, nullptr, q, TOK_, D_, D_);
    gemm_mma<false,false><<<gProj, blk128, GEMM_SMEM>>>(h, wt_sak, nullptr, k, TOK_, D_, D_);
    gemm_mma<false,false><<<gProj, blk128, GEMM_SMEM>>>(h, wt_sav, nullptr, v, TOK_, D_, D_);
    attn_mma<true><<<dim3(T_ / 64, H_, B_), blk128, ATT_SMEM_BYTES>>>(
        q, k, v, attn, T_, T_, T_);
    gemm_mma<false,false><<<gProj, blk128, GEMM_SMEM>>>(attn, wt_sao, x, x1, TOK_, D_, D_);

    // ---- chunked cross-attention (T == NC*chunk; reshapes are views) ----
    ln_kernel<<<TOK_,  blk256>>>(x1, cca_lnq_g, cca_lnq_b, h);
    ln_kernel<<<KVTOK_, blk256>>>(neighbors, cca_lnkv_g, cca_lnkv_b, kvln);
    gemm_mma<false,false><<<gProj, blk128, GEMM_SMEM>>>(h,    wt_ccq, nullptr, q, TOK_,   D_, D_);
    gemm_mma<false,false><<<gKV,   blk128, GEMM_SMEM>>>(kvln, wt_cck, nullptr, k, KVTOK_, D_, D_);
    gemm_mma<false,false><<<gKV,   blk128, GEMM_SMEM>>>(kvln, wt_ccv, nullptr, v, KVTOK_, D_, D_);
    attn_mma<false><<<dim3(1, H_, NCH_), blk128, ATT_SMEM_BYTES>>>(
        q, k, v, attn, KV_, CH_, KV_);
    gemm_mma<false,false><<<gProj, blk128, GEMM_SMEM>>>(attn, wt_cco, x1, out, TOK_, D_, D_);

    // ---- FFN ----
    ln_kernel<<<TOK_, blk256>>>(out, ffn_ln_g, ffn_ln_b, h);
    gemm_mma<true, true ><<<gFFN1, blk128, GEMM_SMEM>>>(h,   wt_f1, nullptr, ffn, TOK_, DFF_, D_);
    gemm_mma<false,false><<<gProj, blk128, GEMM_SMEM>>>(ffn, wt_f2, out,     out, TOK_, D_, DFF_);
}

// round 6
// speedup vs baseline: 3.9619x; 1.0164x over previous
#include <cuda_runtime.h>
#include <math.h>
#include <cstdint>

// Problem constants (fixed by setup_inputs)
#define B_     2
#define T_     2048
#define D_     1024
#define H_     16
#define HD_    64
#define TOK_   4096      // B*T
#define NCH_   64        // B*NC chunks
#define CH_    64        // chunk_size
#define KV_    256       // K*NL
#define KVTOK_ 16384     // NCH_*KV_
#define DFF_   4096

// ---------------- scratch (static device globals; no allocation) ----------------
__device__ float g_h   [TOK_  * D_];
__device__ float g_qkv [TOK_  * 3 * D_];   // fused SA q|k|v, 48 MB
__device__ float g_q   [TOK_  * D_];       // cca q
__device__ float g_kv  [KVTOK_* 2 * D_];   // fused CCA k|v, 128 MB
__device__ float g_kvln[KVTOK_* D_];
__device__ float g_attn[TOK_  * D_];
__device__ float g_x1  [TOK_  * D_];
__device__ float g_ffn [TOK_  * DFF_];
__device__ float g_wt  [16u * 1024u * 1024u];   // transposed weights, 64 MB

// ---------------- helpers ---------------------------------------------------------
__device__ __forceinline__ uint32_t smem_u32(const void* p) {
    uint32_t a;
    asm("{ .reg .u64 t; cvta.to.shared.u64 t, %1; cvt.u32.u64 %0, t; }" : "=r"(a) : "l"(p));
    return a;
}

__device__ __forceinline__ float to_tf32(float x) {
    uint32_t u;
    asm("cvt.rna.tf32.f32 %0, %1;" : "=r"(u) : "f"(x));
    return __uint_as_float(u);
}

__device__ __forceinline__ void cp16(uint32_t s, const void* g) {
    asm volatile("cp.async.cg.shared.global [%0], [%1], 16;" :: "r"(s), "l"(g));
}
__device__ __forceinline__ void cp_commit() {
    asm volatile("cp.async.commit_group;" ::: "memory");
}
template<int N>
__device__ __forceinline__ void cp_wait() {
    asm volatile("cp.async.wait_group %0;" :: "n"(N) : "memory");
}

// m16n8k8 tf32 MMA, C += A*B
__device__ __forceinline__ void mma8(float* c, const uint32_t* a, const uint32_t* b) {
    asm volatile(
        "mma.sync.aligned.m16n8k8.row.col.f32.tf32.tf32.f32 "
        "{%0,%1,%2,%3}, {%4,%5,%6,%7}, {%8,%9}, {%0,%1,%2,%3};"
        : "+f"(c[0]), "+f"(c[1]), "+f"(c[2]), "+f"(c[3])
        : "r"(a[0]), "r"(a[1]), "r"(a[2]), "r"(a[3]), "r"(b[0]), "r"(b[1]));
}

// ---------------- batched weight transpose: WT[n*K+k] = tf32(W[k*N+n]) -----------
struct TP8 { const float* src[8]; float* dst[8]; };

__global__ __launch_bounds__(256) void transpose8_kernel(TP8 p, int K, int N)
{
    __shared__ float t[32][33];
    const float* W = p.src[blockIdx.z];
    float* WT = p.dst[blockIdx.z];
    int kb = blockIdx.y * 32, nb = blockIdx.x * 32;
    int tx = threadIdx.x & 31, ty4 = (threadIdx.x >> 5) * 4;
    #pragma unroll
    for (int r = 0; r < 4; r++)
        t[ty4 + r][tx] = W[(size_t)(kb + ty4 + r) * N + nb + tx];
    __syncthreads();
    #pragma unroll
    for (int r = 0; r < 4; r++)
        WT[(size_t)(nb + ty4 + r) * K + kb + tx] = to_tf32(t[tx][ty4 + r]);
}

__global__ __launch_bounds__(256) void transpose_kernel(
    const float* __restrict__ W, float* __restrict__ WT, int K, int N)
{
    __shared__ float t[32][33];
    int kb = blockIdx.y * 32, nb = blockIdx.x * 32;
    int tx = threadIdx.x & 31, ty4 = (threadIdx.x >> 5) * 4;
    #pragma unroll
    for (int r = 0; r < 4; r++)
        t[ty4 + r][tx] = W[(size_t)(kb + ty4 + r) * N + nb + tx];
    __syncthreads();
    #pragma unroll
    for (int r = 0; r < 4; r++)
        WT[(size_t)(nb + ty4 + r) * K + kb + tx] = to_tf32(t[tx][ty4 + r]);
}

// ---------------- LayerNorm: one block (256 thr) per row of 1024 ----------------
__global__ __launch_bounds__(256) void ln_kernel(
    const float* __restrict__ x, const float* __restrict__ g,
    const float* __restrict__ b, float* __restrict__ out)
{
    int row = blockIdx.x;
    int tid = threadIdx.x;
    const float4* xr = reinterpret_cast<const float4*>(x + (size_t)row * D_);
    float4 v4 = xr[tid];
    float s  = v4.x + v4.y + v4.z + v4.w;
    float ss = v4.x*v4.x + v4.y*v4.y + v4.z*v4.z + v4.w*v4.w;

    __shared__ float sh1[8], sh2[8];
    int lane = tid & 31, wid = tid >> 5;
    #pragma unroll
    for (int o = 16; o; o >>= 1) {
        s  += __shfl_down_sync(0xffffffffu, s,  o);
        ss += __shfl_down_sync(0xffffffffu, ss, o);
    }
    if (lane == 0) { sh1[wid] = s; sh2[wid] = ss; }
    __syncthreads();
    if (tid < 32) {
        s  = (tid < 8) ? sh1[tid] : 0.f;
        ss = (tid < 8) ? sh2[tid] : 0.f;
        #pragma unroll
        for (int o = 4; o; o >>= 1) {
            s  += __shfl_down_sync(0xffffffffu, s,  o);
            ss += __shfl_down_sync(0xffffffffu, ss, o);
        }
        if (tid == 0) { sh1[0] = s; sh2[0] = ss; }
    }
    __syncthreads();
    float mean = sh1[0] * (1.0f / D_);
    float var  = sh2[0] * (1.0f / D_) - mean * mean;
    float rstd = rsqrtf(var + 1e-5f);

    const float4 g4 = reinterpret_cast<const float4*>(g)[tid];
    const float4 b4 = reinterpret_cast<const float4*>(b)[tid];
    float4 o4;
    o4.x = to_tf32((v4.x - mean) * rstd * g4.x + b4.x);
    o4.y = to_tf32((v4.y - mean) * rstd * g4.y + b4.y);
    o4.z = to_tf32((v4.z - mean) * rstd * g4.z + b4.z);
    o4.w = to_tf32((v4.w - mean) * rstd * g4.w + b4.w);
    reinterpret_cast<float4*>(out + (size_t)row * D_)[tid] = o4;
}

// ---------------- tf32 mma.sync GEMM: C = A[MxK] @ WT[NxK]^T (+resid)(+gelu) -----
// 128x128 block tile, 128 threads (4 warps, 2x2), warp tile 64x64, BK=16,
// 3-stage cp.async pipeline, dynamic smem (stride 20 -> conflict-free frag LDS).
#define GSTR 20
#define GEMM_SMEM (3 * 2 * 128 * GSTR * 4)      // 61440 bytes

template<bool GELU, bool CVT>
__global__ __launch_bounds__(128) void gemm_mma(
    const float* __restrict__ A, const float* __restrict__ WT,
    const float* __restrict__ resid, float* __restrict__ C,
    int M, int N, int K)
{
    extern __shared__ float sm[];
    float* As = sm;                      // [3][128][GSTR]
    float* Bs = sm + 3 * 128 * GSTR;     // [3][128][GSTR]

    int tid = threadIdx.x;
    int wid = tid >> 5, lane = tid & 31;
    int warpM = wid >> 1, warpN = wid & 1;
    int grp = lane >> 2, tig = lane & 3;

    int n0 = blockIdx.x * 128, m0 = blockIdx.y * 128;
    const float* Ab = A  + (size_t)m0 * K;
    const float* Bb = WT + (size_t)n0 * K;

    float acc[4][8][4];
    #pragma unroll
    for (int i = 0; i < 4; i++)
        #pragma unroll
        for (int j = 0; j < 8; j++)
            #pragma unroll
            for (int q = 0; q < 4; q++) acc[i][j][q] = 0.f;

    int nk = K >> 4;

    auto load_stage = [&](int st, int kt) {
        int k0 = kt << 4;
        float* Ast = As + st * 128 * GSTR;
        float* Bst = Bs + st * 128 * GSTR;
        #pragma unroll
        for (int i = 0; i < 4; i++) {
            int idx = tid + i * 128;
            int m = idx >> 2, kc = (idx & 3) * 4;
            cp16(smem_u32(Ast + m * GSTR + kc), Ab + (size_t)m * K + k0 + kc);
            cp16(smem_u32(Bst + m * GSTR + kc), Bb + (size_t)m * K + k0 + kc);
        }
        cp_commit();
    };

    load_stage(0, 0);
    if (nk > 1) load_stage(1, 1);

    for (int kt = 0; kt < nk; kt++) {
        int buf = kt % 3;
        if (kt + 2 < nk) { load_stage((kt + 2) % 3, kt + 2); cp_wait<2>(); }
        else if (kt + 1 < nk) { cp_wait<1>(); }
        else { cp_wait<0>(); }
        __syncthreads();

        float* Abuf = As + buf * 128 * GSTR;
        float* Bbuf = Bs + buf * 128 * GSTR;

        #pragma unroll
        for (int ks = 0; ks < 2; ks++) {
            int k = ks * 8;
            uint32_t af[4][4], bf[8][2];
            #pragma unroll
            for (int mt = 0; mt < 4; mt++) {
                int rA = warpM * 64 + mt * 16 + grp;
                af[mt][0] = __float_as_uint(Abuf[rA * GSTR + k + tig]);
                af[mt][1] = __float_as_uint(Abuf[(rA + 8) * GSTR + k + tig]);
                af[mt][2] = __float_as_uint(Abuf[rA * GSTR + k + tig + 4]);
                af[mt][3] = __float_as_uint(Abuf[(rA + 8) * GSTR + k + tig + 4]);
            }
            #pragma unroll
            for (int nt = 0; nt < 8; nt++) {
                int rB = warpN * 64 + nt * 8 + grp;
                bf[nt][0] = __float_as_uint(Bbuf[rB * GSTR + k + tig]);
                bf[nt][1] = __float_as_uint(Bbuf[rB * GSTR + k + tig + 4]);
            }
            #pragma unroll
            for (int mt = 0; mt < 4; mt++)
                #pragma unroll
                for (int nt = 0; nt < 8; nt++)
                    mma8(acc[mt][nt], af[mt], bf[nt]);
        }
        __syncthreads();
    }

    #pragma unroll
    for (int mt = 0; mt < 4; mt++) {
        int row = m0 + warpM * 64 + mt * 16 + grp;
        #pragma unroll
        for (int nt = 0; nt < 8; nt++) {
            int col = n0 + warpN * 64 + nt * 8 + 2 * tig;
            #pragma unroll
            for (int half = 0; half < 2; half++) {
                int r = row + half * 8;
                float v0 = acc[mt][nt][half * 2 + 0];
                float v1 = acc[mt][nt][half * 2 + 1];
                if (GELU) {
                    v0 = 0.5f * v0 * (1.0f + erff(v0 * 0.70710678118654752f));
                    v1 = 0.5f * v1 * (1.0f + erff(v1 * 0.70710678118654752f));
                }
                size_t base = (size_t)r * N + col;
                if (resid) {
                    float2 rv = *reinterpret_cast<const float2*>(resid + base);
                    v0 += rv.x; v1 += rv.y;
                }
                if (CVT) { v0 = to_tf32(v0); v1 = to_tf32(v1); }
                float2 ov = {v0, v1};
                *reinterpret_cast<float2*>(C + base) = ov;
            }
        }
    }
}

// ---------------- tensor-core flash attention (tf32 mma, online softmax) --------
// qld/kld: row strides of Q and K/V buffers (supports packed QKV layouts).
#define KSTR 68
#define VSTR 72
#define ATT_SMEM_FLOATS (2 * (64 * KSTR + 64 * VSTR) + 4 * 16 * KSTR)
#define ATT_SMEM_BYTES  (ATT_SMEM_FLOATS * 4)

template<bool CAUSAL>
__global__ __launch_bounds__(128) void attn_mma(
    const float* __restrict__ Q, const float* __restrict__ Kg,
    const float* __restrict__ Vg, float* __restrict__ O,
    int klen, int q_tokens_per_batch, int kv_tokens_per_batch,
    int qld, int kld)
{
    extern __shared__ float sm[];
    int tid = threadIdx.x, w = tid >> 5, lane = tid & 31;
    int grp = lane >> 2, tig = lane & 3;
    int qt = blockIdx.x, h = blockIdx.y, b = blockIdx.z;
    int qbase  = b * q_tokens_per_batch + qt * 64;
    int kvbase = b * kv_tokens_per_batch;

    const int KV_BUF = 64 * KSTR + 64 * VSTR;
    float* Ksm0 = sm;
    float* Vsm0 = sm + 64 * KSTR;
    float* Ksm1 = sm + KV_BUF;
    float* Vsm1 = sm + KV_BUF + 64 * KSTR;
    float* Ps   = sm + 2 * KV_BUF + w * (16 * KSTR);

    for (int i = tid; i < 64 * 16; i += 128) {
        int r = i >> 4, c4 = (i & 15) << 2;
        *reinterpret_cast<float4*>(&Ksm0[r * KSTR + c4]) =
            *reinterpret_cast<const float4*>(&Q[(size_t)(qbase + r) * qld + h * HD_ + c4]);
    }
    __syncthreads();
    uint32_t aq[8][4];
    {
        int r0 = w * 16 + grp;
        #pragma unroll
        for (int kc = 0; kc < 8; kc++) {
            int c = kc * 8 + tig;
            aq[kc][0] = __float_as_uint(Ksm0[r0 * KSTR + c] * 0.125f);
            aq[kc][1] = __float_as_uint(Ksm0[(r0 + 8) * KSTR + c] * 0.125f);
            aq[kc][2] = __float_as_uint(Ksm0[r0 * KSTR + c + 4] * 0.125f);
            aq[kc][3] = __float_as_uint(Ksm0[(r0 + 8) * KSTR + c + 4] * 0.125f);
        }
    }
    __syncthreads();

    float o[8][4];
    #pragma unroll
    for (int i = 0; i < 8; i++)
        #pragma unroll
        for (int j = 0; j < 4; j++) o[i][j] = 0.f;
    float m0 = -1e30f, m1 = -1e30f, l0 = 0.f, l1 = 0.f;

    int ktiles = klen >> 6;
    if (CAUSAL && qt + 1 < ktiles) ktiles = qt + 1;

    {
        for (int i = tid; i < 64 * 16; i += 128) {
            int r = i >> 4, c4 = (i & 15) << 2;
            size_t gofs = (size_t)(kvbase + r) * kld + h * HD_ + c4;
            cp16(smem_u32(&Ksm0[r * KSTR + c4]), Kg + gofs);
            cp16(smem_u32(&Vsm0[r * VSTR + c4]), Vg + gofs);
        }
        cp_commit();
    }

    for (int kt = 0; kt < ktiles; kt++) {
        int buf = kt & 1;
        float* Ks = buf ? Ksm1 : Ksm0;
        float* Vs = buf ? Vsm1 : Vsm0;
        if (kt + 1 < ktiles) {
            float* Kn = buf ? Ksm0 : Ksm1;
            float* Vn = buf ? Vsm0 : Vsm1;
            int kb = kvbase + (kt + 1) * 64;
            for (int i = tid; i < 64 * 16; i += 128) {
                int r = i >> 4, c4 = (i & 15) << 2;
                size_t gofs = (size_t)(kb + r) * kld + h * HD_ + c4;
                cp16(smem_u32(&Kn[r * KSTR + c4]), Kg + gofs);
                cp16(smem_u32(&Vn[r * VSTR + c4]), Vg + gofs);
            }
            cp_commit();
            cp_wait<1>();
        } else {
            cp_wait<0>();
        }
        __syncthreads();

        float s[8][4];
        #pragma unroll
        for (int nt = 0; nt < 8; nt++)
            #pragma unroll
            for (int j = 0; j < 4; j++) s[nt][j] = 0.f;

        #pragma unroll
        for (int kc = 0; kc < 8; kc++) {
            #pragma unroll
            for (int nt = 0; nt < 8; nt++) {
                uint32_t bk[2];
                int key = nt * 8 + grp;
                bk[0] = __float_as_uint(Ks[key * KSTR + kc * 8 + tig]);
                bk[1] = __float_as_uint(Ks[key * KSTR + kc * 8 + tig + 4]);
                mma8(s[nt], aq[kc], bk);
            }
        }

        if (CAUSAL && kt == qt) {
            int r0 = qt * 64 + w * 16 + grp;
            #pragma unroll
            for (int nt = 0; nt < 8; nt++) {
                int c = kt * 64 + nt * 8 + 2 * tig;
                if (c     > r0)     s[nt][0] = -1e30f;
                if (c + 1 > r0)     s[nt][1] = -1e30f;
                if (c     > r0 + 8) s[nt][2] = -1e30f;
                if (c + 1 > r0 + 8) s[nt][3] = -1e30f;
            }
        }

        float t0 = -1e30f, t1 = -1e30f;
        #pragma unroll
        for (int nt = 0; nt < 8; nt++) {
            t0 = fmaxf(t0, fmaxf(s[nt][0], s[nt][1]));
            t1 = fmaxf(t1, fmaxf(s[nt][2], s[nt][3]));
        }
        t0 = fmaxf(t0, __shfl_xor_sync(0xffffffffu, t0, 1));
        t0 = fmaxf(t0, __shfl_xor_sync(0xffffffffu, t0, 2));
        t1 = fmaxf(t1, __shfl_xor_sync(0xffffffffu, t1, 1));
        t1 = fmaxf(t1, __shfl_xor_sync(0xffffffffu, t1, 2));
        float nm0 = fmaxf(m0, t0), nm1 = fmaxf(m1, t1);
        float c0 = __expf(m0 - nm0), c1 = __expf(m1 - nm1);
        float ts0 = 0.f, ts1 = 0.f;
        #pragma unroll
        for (int nt = 0; nt < 8; nt++) {
            s[nt][0] = __expf(s[nt][0] - nm0);
            s[nt][1] = __expf(s[nt][1] - nm0);
            s[nt][2] = __expf(s[nt][2] - nm1);
            s[nt][3] = __expf(s[nt][3] - nm1);
            ts0 += s[nt][0] + s[nt][1];
            ts1 += s[nt][2] + s[nt][3];
        }
        ts0 += __shfl_xor_sync(0xffffffffu, ts0, 1);
        ts0 += __shfl_xor_sync(0xffffffffu, ts0, 2);
        ts1 += __shfl_xor_sync(0xffffffffu, ts1, 1);
        ts1 += __shfl_xor_sync(0xffffffffu, ts1, 2);
        l0 = l0 * c0 + ts0;
        l1 = l1 * c1 + ts1;
        m0 = nm0; m1 = nm1;
        #pragma unroll
        for (int nt = 0; nt < 8; nt++) {
            o[nt][0] *= c0; o[nt][1] *= c0;
            o[nt][2] *= c1; o[nt][3] *= c1;
        }

        #pragma unroll
        for (int nt = 0; nt < 8; nt++) {
            float2 p0 = {s[nt][0], s[nt][1]};
            float2 p1 = {s[nt][2], s[nt][3]};
            *reinterpret_cast<float2*>(&Ps[grp * KSTR + nt * 8 + 2 * tig]) = p0;
            *reinterpret_cast<float2*>(&Ps[(grp + 8) * KSTR + nt * 8 + 2 * tig]) = p1;
        }
        __syncwarp();

        #pragma unroll
        for (int kc = 0; kc < 8; kc++) {
            uint32_t ap[4];
            ap[0] = __float_as_uint(Ps[grp * KSTR + kc * 8 + tig]);
            ap[1] = __float_as_uint(Ps[(grp + 8) * KSTR + kc * 8 + tig]);
            ap[2] = __float_as_uint(Ps[grp * KSTR + kc * 8 + tig + 4]);
            ap[3] = __float_as_uint(Ps[(grp + 8) * KSTR + kc * 8 + tig + 4]);
            #pragma unroll
            for (int nt2 = 0; nt2 < 8; nt2++) {
                uint32_t bv[2];
                bv[0] = __float_as_uint(Vs[(kc * 8 + tig) * VSTR + nt2 * 8 + grp]);
                bv[1] = __float_as_uint(Vs[(kc * 8 + tig + 4) * VSTR + nt2 * 8 + grp]);
                mma8(o[nt2], ap, bv);
            }
        }
        __syncwarp();
        __syncthreads();
    }

    float il0 = 1.0f / l0, il1 = 1.0f / l1;
    int r0 = qbase + w * 16 + grp;
    #pragma unroll
    for (int nt2 = 0; nt2 < 8; nt2++) {
        int col = h * HD_ + nt2 * 8 + 2 * tig;
        float2 v0 = {to_tf32(o[nt2][0] * il0), to_tf32(o[nt2][1] * il0)};
        float2 v1 = {to_tf32(o[nt2][2] * il1), to_tf32(o[nt2][3] * il1)};
        *reinterpret_cast<float2*>(&O[(size_t)r0 * D_ + col]) = v0;
        *reinterpret_cast<float2*>(&O[(size_t)(r0 + 8) * D_ + col]) = v1;
    }
}

// ---------------- launch ---------------------------------------------------------
extern "C" void kernel_launch(void* const* d_in, const int* in_sizes, int n_in,
                              void* d_out, int out_size)
{
    const float* x         = (const float*)d_in[0];
    const float* neighbors = (const float*)d_in[1];
    const float* sa_ln_g   = (const float*)d_in[2];
    const float* sa_ln_b   = (const float*)d_in[3];
    const float* sa_wq     = (const float*)d_in[4];
    const float* sa_wk     = (const float*)d_in[5];
    const float* sa_wv     = (const float*)d_in[6];
    const float* sa_wo     = (const float*)d_in[7];
    const float* cca_lnq_g = (const float*)d_in[8];
    const float* cca_lnq_b = (const float*)d_in[9];
    const float* cca_lnkv_g= (const float*)d_in[10];
    const float* cca_lnkv_b= (const float*)d_in[11];
    const float* cca_wq    = (const float*)d_in[12];
    const float* cca_wk    = (const float*)d_in[13];
    const float* cca_wv    = (const float*)d_in[14];
    const float* cca_wo    = (const float*)d_in[15];
    const float* ffn_ln_g  = (const float*)d_in[16];
    const float* ffn_ln_b  = (const float*)d_in[17];
    const float* ffn_w1    = (const float*)d_in[18];
    const float* ffn_w2    = (const float*)d_in[19];
    float* out = (float*)d_out;

    float *h, *qkv, *q, *kv, *kvln, *attn, *x1, *ffn, *wt;
    cudaGetSymbolAddress((void**)&h,    g_h);
    cudaGetSymbolAddress((void**)&qkv,  g_qkv);
    cudaGetSymbolAddress((void**)&q,    g_q);
    cudaGetSymbolAddress((void**)&kv,   g_kv);
    cudaGetSymbolAddress((void**)&kvln, g_kvln);
    cudaGetSymbolAddress((void**)&attn, g_attn);
    cudaGetSymbolAddress((void**)&x1,   g_x1);
    cudaGetSymbolAddress((void**)&ffn,  g_ffn);
    cudaGetSymbolAddress((void**)&wt,   g_wt);

    const size_t MB = 1024 * 1024;
    // SA q|k|v packed contiguous -> one [3072, 1024] WT; CCA k|v -> [2048, 1024].
    float* wt_saqkv = wt + 0 * MB;   // rows 0-3071
    float* wt_sao   = wt + 3 * MB;
    float* wt_ccq   = wt + 4 * MB;
    float* wt_cckv  = wt + 5 * MB;   // rows 0-2047
    float* wt_cco   = wt + 7 * MB;
    float* wt_f1    = wt + 8 * MB;   // [DFF, D]
    float* wt_f2    = wt + 12 * MB;  // [D, DFF]

    cudaFuncSetAttribute(attn_mma<true >, cudaFuncAttributeMaxDynamicSharedMemorySize, ATT_SMEM_BYTES);
    cudaFuncSetAttribute(attn_mma<false>, cudaFuncAttributeMaxDynamicSharedMemorySize, ATT_SMEM_BYTES);
    cudaFuncSetAttribute(gemm_mma<false,false>, cudaFuncAttributeMaxDynamicSharedMemorySize, GEMM_SMEM);
    cudaFuncSetAttribute(gemm_mma<true ,true >, cudaFuncAttributeMaxDynamicSharedMemorySize, GEMM_SMEM);

    dim3 blk256(256), blk128(128);

    // ---- batched weight transposes (+tf32 rounding) ----
    TP8 tp;
    tp.src[0] = sa_wq;  tp.dst[0] = wt_saqkv + 0 * MB;
    tp.src[1] = sa_wk;  tp.dst[1] = wt_saqkv + 1 * MB;
    tp.src[2] = sa_wv;  tp.dst[2] = wt_saqkv + 2 * MB;
    tp.src[3] = sa_wo;  tp.dst[3] = wt_sao;
    tp.src[4] = cca_wq; tp.dst[4] = wt_ccq;
    tp.src[5] = cca_wk; tp.dst[5] = wt_cckv + 0 * MB;
    tp.src[6] = cca_wv; tp.dst[6] = wt_cckv + 1 * MB;
    tp.src[7] = cca_wo; tp.dst[7] = wt_cco;
    transpose8_kernel<<<dim3(D_ / 32, D_ / 32, 8), blk256>>>(tp, D_, D_);
    transpose_kernel<<<dim3(DFF_ / 32, D_ / 32), blk256>>>(ffn_w1, wt_f1, D_, DFF_);
    transpose_kernel<<<dim3(D_ / 32, DFF_ / 32), blk256>>>(ffn_w2, wt_f2, DFF_, D_);

    dim3 gProj(D_ / 128, TOK_ / 128);            // (8, 32)
    dim3 gQKV(3 * D_ / 128, TOK_ / 128);         // (24, 32) = 768 CTAs
    dim3 gKV2(2 * D_ / 128, KVTOK_ / 128);       // (16, 128) = 2048 CTAs
    dim3 gFFN1(DFF_ / 128, TOK_ / 128);          // (32, 32)

    // ---- self-attention ----
    ln_kernel<<<TOK_, blk256>>>(x, sa_ln_g, sa_ln_b, h);
    gemm_mma<false,false><<<gQKV, blk128, GEMM_SMEM>>>(h, wt_saqkv, nullptr, qkv, TOK_, 3 * D_, D_);
    attn_mma<true><<<dim3(T_ / 64, H_, B_), blk128, ATT_SMEM_BYTES>>>(
        qkv, qkv + D_, qkv + 2 * D_, attn, T_, T_, T_, 3 * D_, 3 * D_);
    gemm_mma<false,false><<<gProj, blk128, GEMM_SMEM>>>(attn, wt_sao, x, x1, TOK_, D_, D_);

    // ---- chunked cross-attention (T == NC*chunk; reshapes are views) ----
    ln_kernel<<<TOK_,  blk256>>>(x1, cca_lnq_g, cca_lnq_b, h);
    ln_kernel<<<KVTOK_, blk256>>>(neighbors, cca_lnkv_g, cca_lnkv_b, kvln);
    gemm_mma<false,false><<<gProj, blk128, GEMM_SMEM>>>(h,    wt_ccq,  nullptr, q,  TOK_,   D_,     D_);
    gemm_mma<false,false><<<gKV2,  blk128, GEMM_SMEM>>>(kvln, wt_cckv, nullptr, kv, KVTOK_, 2 * D_, D_);
    attn_mma<false><<<dim3(1, H_, NCH_), blk128, ATT_SMEM_BYTES>>>(
        q, kv, kv + D_, attn, KV_, CH_, KV_, D_, 2 * D_);
    gemm_mma<false,false><<<gProj, blk128, GEMM_SMEM>>>(attn, wt_cco, x1, out, TOK_, D_, D_);

    // ---- FFN ----
    ln_kernel<<<TOK_, blk256>>>(out, ffn_ln_g, ffn_ln_b, h);
    gemm_mma<true, true ><<<gFFN1, blk128, GEMM_SMEM>>>(h,   wt_f1, nullptr, ffn, TOK_, DFF_, D_);
    gemm_mma<false,false><<<gProj, blk128, GEMM_SMEM>>>(ffn, wt_f2, out,     out, TOK_, D_, DFF_);
}

// round 7
// speedup vs baseline: 4.1157x; 1.0388x over previous
#include <cuda_runtime.h>
#include <math.h>
#include <cstdint>

// Problem constants (fixed by setup_inputs)
#define B_     2
#define T_     2048
#define D_     1024
#define H_     16
#define HD_    64
#define TOK_   4096      // B*T
#define NCH_   64        // B*NC chunks
#define CH_    64        // chunk_size
#define KV_    256       // K*NL
#define KVTOK_ 16384     // NCH_*KV_
#define DFF_   4096

// ---------------- scratch (static device globals; no allocation) ----------------
__device__ float g_h   [TOK_  * D_];
__device__ float g_qkv [TOK_  * 3 * D_];   // fused SA q|k|v
__device__ float g_q   [TOK_  * D_];       // cca q
__device__ float g_kv  [KVTOK_* 2 * D_];   // fused CCA k|v
__device__ float g_kvln[KVTOK_* D_];
__device__ float g_attn[TOK_  * D_];
__device__ float g_x1  [TOK_  * D_];
__device__ float g_ffn [TOK_  * DFF_];
__device__ float g_wt  [16u * 1024u * 1024u];   // transposed weights, 64 MB

// ---------------- helpers ---------------------------------------------------------
__device__ __forceinline__ uint32_t smem_u32(const void* p) {
    uint32_t a;
    asm("{ .reg .u64 t; cvta.to.shared.u64 t, %1; cvt.u32.u64 %0, t; }" : "=r"(a) : "l"(p));
    return a;
}

__device__ __forceinline__ float to_tf32(float x) {
    uint32_t u;
    asm("cvt.rna.tf32.f32 %0, %1;" : "=r"(u) : "f"(x));
    return __uint_as_float(u);
}

// k-permutation within each 8-column group: pairs (t, t+4) become adjacent.
__device__ __forceinline__ int pcol(int c) {
    return (c & ~7) | ((c & 3) << 1) | ((c >> 2) & 1);
}

__device__ __forceinline__ void cp16(uint32_t s, const void* g) {
    asm volatile("cp.async.cg.shared.global [%0], [%1], 16;" :: "r"(s), "l"(g));
}
__device__ __forceinline__ void cp_commit() {
    asm volatile("cp.async.commit_group;" ::: "memory");
}
template<int N>
__device__ __forceinline__ void cp_wait() {
    asm volatile("cp.async.wait_group %0;" :: "n"(N) : "memory");
}

// m16n8k8 tf32 MMA, C += A*B
__device__ __forceinline__ void mma8(float* c, const uint32_t* a, const uint32_t* b) {
    asm volatile(
        "mma.sync.aligned.m16n8k8.row.col.f32.tf32.tf32.f32 "
        "{%0,%1,%2,%3}, {%4,%5,%6,%7}, {%8,%9}, {%0,%1,%2,%3};"
        : "+f"(c[0]), "+f"(c[1]), "+f"(c[2]), "+f"(c[3])
        : "r"(a[0]), "r"(a[1]), "r"(a[2]), "r"(a[3]), "r"(b[0]), "r"(b[1]));
}

// ---------------- batched weight transpose: WT[n, perm(k)] = tf32(W[k,n]) --------
struct TP8 { const float* src[8]; float* dst[8]; };

__global__ __launch_bounds__(256) void transpose8_kernel(TP8 p, int K, int N)
{
    __shared__ float t[32][33];
    const float* W = p.src[blockIdx.z];
    float* WT = p.dst[blockIdx.z];
    int kb = blockIdx.y * 32, nb = blockIdx.x * 32;
    int tx = threadIdx.x & 31, ty4 = (threadIdx.x >> 5) * 4;
    #pragma unroll
    for (int r = 0; r < 4; r++)
        t[ty4 + r][tx] = W[(size_t)(kb + ty4 + r) * N + nb + tx];
    __syncthreads();
    int txp = (tx & ~7) | ((tx & 3) << 1) | ((tx >> 2) & 1);
    #pragma unroll
    for (int r = 0; r < 4; r++)
        WT[(size_t)(nb + ty4 + r) * K + kb + txp] = to_tf32(t[tx][ty4 + r]);
}

__global__ __launch_bounds__(256) void transpose_kernel(
    const float* __restrict__ W, float* __restrict__ WT, int K, int N)
{
    __shared__ float t[32][33];
    int kb = blockIdx.y * 32, nb = blockIdx.x * 32;
    int tx = threadIdx.x & 31, ty4 = (threadIdx.x >> 5) * 4;
    #pragma unroll
    for (int r = 0; r < 4; r++)
        t[ty4 + r][tx] = W[(size_t)(kb + ty4 + r) * N + nb + tx];
    __syncthreads();
    int txp = (tx & ~7) | ((tx & 3) << 1) | ((tx >> 2) & 1);
    #pragma unroll
    for (int r = 0; r < 4; r++)
        WT[(size_t)(nb + ty4 + r) * K + kb + txp] = to_tf32(t[tx][ty4 + r]);
}

// ---------------- LayerNorm (writes k-permuted tf32; consumed only as GEMM A) ---
__global__ __launch_bounds__(256) void ln_kernel(
    const float* __restrict__ x, const float* __restrict__ g,
    const float* __restrict__ b, float* __restrict__ out)
{
    int row = blockIdx.x;
    int tid = threadIdx.x;
    const float4* xr = reinterpret_cast<const float4*>(x + (size_t)row * D_);
    float4 v4 = xr[tid];
    float s  = v4.x + v4.y + v4.z + v4.w;
    float ss = v4.x*v4.x + v4.y*v4.y + v4.z*v4.z + v4.w*v4.w;

    __shared__ float sh1[8], sh2[8];
    int lane = tid & 31, wid = tid >> 5;
    #pragma unroll
    for (int o = 16; o; o >>= 1) {
        s  += __shfl_down_sync(0xffffffffu, s,  o);
        ss += __shfl_down_sync(0xffffffffu, ss, o);
    }
    if (lane == 0) { sh1[wid] = s; sh2[wid] = ss; }
    __syncthreads();
    if (tid < 32) {
        s  = (tid < 8) ? sh1[tid] : 0.f;
        ss = (tid < 8) ? sh2[tid] : 0.f;
        #pragma unroll
        for (int o = 4; o; o >>= 1) {
            s  += __shfl_down_sync(0xffffffffu, s,  o);
            ss += __shfl_down_sync(0xffffffffu, ss, o);
        }
        if (tid == 0) { sh1[0] = s; sh2[0] = ss; }
    }
    __syncthreads();
    float mean = sh1[0] * (1.0f / D_);
    float var  = sh2[0] * (1.0f / D_) - mean * mean;
    float rstd = rsqrtf(var + 1e-5f);

    const float4 g4 = reinterpret_cast<const float4*>(g)[tid];
    const float4 b4 = reinterpret_cast<const float4*>(b)[tid];
    float vals[4];
    vals[0] = to_tf32((v4.x - mean) * rstd * g4.x + b4.x);
    vals[1] = to_tf32((v4.y - mean) * rstd * g4.y + b4.y);
    vals[2] = to_tf32((v4.z - mean) * rstd * g4.z + b4.z);
    vals[3] = to_tf32((v4.w - mean) * rstd * g4.w + b4.w);
    // cols 4*tid..4*tid+3 are one half of an 8-group; permuted = start+stride2
    int cbase = tid * 4;
    int start = (cbase & ~7) + ((cbase & 4) >> 2);
    float* orow = out + (size_t)row * D_;
    #pragma unroll
    for (int j = 0; j < 4; j++) orow[start + 2 * j] = vals[j];
}

// ---------------- tf32 mma.sync GEMM (k-permuted operands) -----------------------
// 128x128 block tile, 128 threads (4 warps, 2x2), warp tile 64x64, BK=16,
// 3-stage cp.async, ONE sync per iteration, LDS.64 fragment loads (GSTR=24).
#define GSTR 24
#define GEMM_SMEM (3 * 2 * 128 * GSTR * 4)      // 73728 bytes

template<bool GELU, bool CVT, bool PERM_OUT>
__global__ __launch_bounds__(128) void gemm_mma(
    const float* __restrict__ A, const float* __restrict__ WT,
    const float* __restrict__ resid, float* __restrict__ C,
    int M, int N, int K)
{
    extern __shared__ float sm[];
    float* As = sm;                      // [3][128][GSTR]
    float* Bs = sm + 3 * 128 * GSTR;     // [3][128][GSTR]

    int tid = threadIdx.x;
    int wid = tid >> 5, lane = tid & 31;
    int warpM = wid >> 1, warpN = wid & 1;
    int grp = lane >> 2, tig = lane & 3;

    int n0 = blockIdx.x * 128, m0 = blockIdx.y * 128;
    const float* Ab = A  + (size_t)m0 * K;
    const float* Bb = WT + (size_t)n0 * K;

    float acc[4][8][4];
    #pragma unroll
    for (int i = 0; i < 4; i++)
        #pragma unroll
        for (int j = 0; j < 8; j++)
            #pragma unroll
            for (int q = 0; q < 4; q++) acc[i][j][q] = 0.f;

    int nk = K >> 4;

    auto load_stage = [&](int st, int kt) {
        int k0 = kt << 4;
        float* Ast = As + st * 128 * GSTR;
        float* Bst = Bs + st * 128 * GSTR;
        #pragma unroll
        for (int i = 0; i < 4; i++) {
            int idx = tid + i * 128;
            int m = idx >> 2, kc = (idx & 3) * 4;
            cp16(smem_u32(Ast + m * GSTR + kc), Ab + (size_t)m * K + k0 + kc);
            cp16(smem_u32(Bst + m * GSTR + kc), Bb + (size_t)m * K + k0 + kc);
        }
        cp_commit();
    };

    load_stage(0, 0);
    if (nk > 1) load_stage(1, 1);

    for (int kt = 0; kt < nk; kt++) {
        int buf = kt % 3;
        if (kt + 1 < nk) cp_wait<1>(); else cp_wait<0>();
        __syncthreads();
        if (kt + 2 < nk) load_stage((kt + 2) % 3, kt + 2);

        float* Abuf = As + buf * 128 * GSTR;
        float* Bbuf = Bs + buf * 128 * GSTR;

        #pragma unroll
        for (int ks = 0; ks < 2; ks++) {
            int k = ks * 8;
            uint32_t af[4][4], bf[8][2];
            #pragma unroll
            for (int mt = 0; mt < 4; mt++) {
                int rA = warpM * 64 + mt * 16 + grp;
                float2 a02 = *reinterpret_cast<const float2*>(Abuf + rA * GSTR + k + 2 * tig);
                float2 a13 = *reinterpret_cast<const float2*>(Abuf + (rA + 8) * GSTR + k + 2 * tig);
                af[mt][0] = __float_as_uint(a02.x);
                af[mt][1] = __float_as_uint(a13.x);
                af[mt][2] = __float_as_uint(a02.y);
                af[mt][3] = __float_as_uint(a13.y);
            }
            #pragma unroll
            for (int nt = 0; nt < 8; nt++) {
                int rB = warpN * 64 + nt * 8 + grp;
                float2 b01 = *reinterpret_cast<const float2*>(Bbuf + rB * GSTR + k + 2 * tig);
                bf[nt][0] = __float_as_uint(b01.x);
                bf[nt][1] = __float_as_uint(b01.y);
            }
            #pragma unroll
            for (int mt = 0; mt < 4; mt++)
                #pragma unroll
                for (int nt = 0; nt < 8; nt++)
                    mma8(acc[mt][nt], af[mt], bf[nt]);
        }
    }

    #pragma unroll
    for (int mt = 0; mt < 4; mt++) {
        int row = m0 + warpM * 64 + mt * 16 + grp;
        #pragma unroll
        for (int nt = 0; nt < 8; nt++) {
            int col = n0 + warpN * 64 + nt * 8 + 2 * tig;
            #pragma unroll
            for (int half = 0; half < 2; half++) {
                int r = row + half * 8;
                float v0 = acc[mt][nt][half * 2 + 0];
                float v1 = acc[mt][nt][half * 2 + 1];
                if (GELU) {
                    v0 = 0.5f * v0 * (1.0f + erff(v0 * 0.70710678118654752f));
                    v1 = 0.5f * v1 * (1.0f + erff(v1 * 0.70710678118654752f));
                }
                if (resid) {
                    float2 rv = *reinterpret_cast<const float2*>(resid + (size_t)r * N + col);
                    v0 += rv.x; v1 += rv.y;
                }
                if (CVT) { v0 = to_tf32(v0); v1 = to_tf32(v1); }
                if (PERM_OUT) {
                    int cg = col & ~7, cw = col & 7;      // cw even
                    C[(size_t)r * N + cg + pcol(cw)]     = v0;
                    C[(size_t)r * N + cg + pcol(cw + 1)] = v1;
                } else {
                    float2 ov = {v0, v1};
                    *reinterpret_cast<float2*>(C + (size_t)r * N + col) = ov;
                }
            }
        }
    }
}

// ---------------- tensor-core flash attention (tf32 mma, online softmax) --------
// qld/kld: row strides of Q and K/V buffers. Output written k-PERMUTED (GEMM A).
#define KSTR 68
#define VSTR 72
#define ATT_SMEM_FLOATS (2 * (64 * KSTR + 64 * VSTR) + 4 * 16 * KSTR)
#define ATT_SMEM_BYTES  (ATT_SMEM_FLOATS * 4)

template<bool CAUSAL>
__global__ __launch_bounds__(128) void attn_mma(
    const float* __restrict__ Q, const float* __restrict__ Kg,
    const float* __restrict__ Vg, float* __restrict__ O,
    int klen, int q_tokens_per_batch, int kv_tokens_per_batch,
    int qld, int kld)
{
    extern __shared__ float sm[];
    int tid = threadIdx.x, w = tid >> 5, lane = tid & 31;
    int grp = lane >> 2, tig = lane & 3;
    int qt = blockIdx.x, h = blockIdx.y, b = blockIdx.z;
    int qbase  = b * q_tokens_per_batch + qt * 64;
    int kvbase = b * kv_tokens_per_batch;

    const int KV_BUF = 64 * KSTR + 64 * VSTR;
    float* Ksm0 = sm;
    float* Vsm0 = sm + 64 * KSTR;
    float* Ksm1 = sm + KV_BUF;
    float* Vsm1 = sm + KV_BUF + 64 * KSTR;
    float* Ps   = sm + 2 * KV_BUF + w * (16 * KSTR);

    for (int i = tid; i < 64 * 16; i += 128) {
        int r = i >> 4, c4 = (i & 15) << 2;
        *reinterpret_cast<float4*>(&Ksm0[r * KSTR + c4]) =
            *reinterpret_cast<const float4*>(&Q[(size_t)(qbase + r) * qld + h * HD_ + c4]);
    }
    __syncthreads();
    uint32_t aq[8][4];
    {
        int r0 = w * 16 + grp;
        #pragma unroll
        for (int kc = 0; kc < 8; kc++) {
            int c = kc * 8 + tig;
            aq[kc][0] = __float_as_uint(Ksm0[r0 * KSTR + c] * 0.125f);
            aq[kc][1] = __float_as_uint(Ksm0[(r0 + 8) * KSTR + c] * 0.125f);
            aq[kc][2] = __float_as_uint(Ksm0[r0 * KSTR + c + 4] * 0.125f);
            aq[kc][3] = __float_as_uint(Ksm0[(r0 + 8) * KSTR + c + 4] * 0.125f);
        }
    }
    __syncthreads();

    float o[8][4];
    #pragma unroll
    for (int i = 0; i < 8; i++)
        #pragma unroll
        for (int j = 0; j < 4; j++) o[i][j] = 0.f;
    float m0 = -1e30f, m1 = -1e30f, l0 = 0.f, l1 = 0.f;

    int ktiles = klen >> 6;
    if (CAUSAL && qt + 1 < ktiles) ktiles = qt + 1;

    {
        for (int i = tid; i < 64 * 16; i += 128) {
            int r = i >> 4, c4 = (i & 15) << 2;
            size_t gofs = (size_t)(kvbase + r) * kld + h * HD_ + c4;
            cp16(smem_u32(&Ksm0[r * KSTR + c4]), Kg + gofs);
            cp16(smem_u32(&Vsm0[r * VSTR + c4]), Vg + gofs);
        }
        cp_commit();
    }

    for (int kt = 0; kt < ktiles; kt++) {
        int buf = kt & 1;
        float* Ks = buf ? Ksm1 : Ksm0;
        float* Vs = buf ? Vsm1 : Vsm0;
        if (kt + 1 < ktiles) {
            float* Kn = buf ? Ksm0 : Ksm1;
            float* Vn = buf ? Vsm0 : Vsm1;
            int kb = kvbase + (kt + 1) * 64;
            for (int i = tid; i < 64 * 16; i += 128) {
                int r = i >> 4, c4 = (i & 15) << 2;
                size_t gofs = (size_t)(kb + r) * kld + h * HD_ + c4;
                cp16(smem_u32(&Kn[r * KSTR + c4]), Kg + gofs);
                cp16(smem_u32(&Vn[r * VSTR + c4]), Vg + gofs);
            }
            cp_commit();
            cp_wait<1>();
        } else {
            cp_wait<0>();
        }
        __syncthreads();

        float s[8][4];
        #pragma unroll
        for (int nt = 0; nt < 8; nt++)
            #pragma unroll
            for (int j = 0; j < 4; j++) s[nt][j] = 0.f;

        #pragma unroll
        for (int kc = 0; kc < 8; kc++) {
            #pragma unroll
            for (int nt = 0; nt < 8; nt++) {
                uint32_t bk[2];
                int key = nt * 8 + grp;
                bk[0] = __float_as_uint(Ks[key * KSTR + kc * 8 + tig]);
                bk[1] = __float_as_uint(Ks[key * KSTR + kc * 8 + tig + 4]);
                mma8(s[nt], aq[kc], bk);
            }
        }

        if (CAUSAL && kt == qt) {
            int r0 = qt * 64 + w * 16 + grp;
            #pragma unroll
            for (int nt = 0; nt < 8; nt++) {
                int c = kt * 64 + nt * 8 + 2 * tig;
                if (c     > r0)     s[nt][0] = -1e30f;
                if (c + 1 > r0)     s[nt][1] = -1e30f;
                if (c     > r0 + 8) s[nt][2] = -1e30f;
                if (c + 1 > r0 + 8) s[nt][3] = -1e30f;
            }
        }

        float t0 = -1e30f, t1 = -1e30f;
        #pragma unroll
        for (int nt = 0; nt < 8; nt++) {
            t0 = fmaxf(t0, fmaxf(s[nt][0], s[nt][1]));
            t1 = fmaxf(t1, fmaxf(s[nt][2], s[nt][3]));
        }
        t0 = fmaxf(t0, __shfl_xor_sync(0xffffffffu, t0, 1));
        t0 = fmaxf(t0, __shfl_xor_sync(0xffffffffu, t0, 2));
        t1 = fmaxf(t1, __shfl_xor_sync(0xffffffffu, t1, 1));
        t1 = fmaxf(t1, __shfl_xor_sync(0xffffffffu, t1, 2));
        float nm0 = fmaxf(m0, t0), nm1 = fmaxf(m1, t1);
        float c0 = __expf(m0 - nm0), c1 = __expf(m1 - nm1);
        float ts0 = 0.f, ts1 = 0.f;
        #pragma unroll
        for (int nt = 0; nt < 8; nt++) {
            s[nt][0] = __expf(s[nt][0] - nm0);
            s[nt][1] = __expf(s[nt][1] - nm0);
            s[nt][2] = __expf(s[nt][2] - nm1);
            s[nt][3] = __expf(s[nt][3] - nm1);
            ts0 += s[nt][0] + s[nt][1];
            ts1 += s[nt][2] + s[nt][3];
        }
        ts0 += __shfl_xor_sync(0xffffffffu, ts0, 1);
        ts0 += __shfl_xor_sync(0xffffffffu, ts0, 2);
        ts1 += __shfl_xor_sync(0xffffffffu, ts1, 1);
        ts1 += __shfl_xor_sync(0xffffffffu, ts1, 2);
        l0 = l0 * c0 + ts0;
        l1 = l1 * c1 + ts1;
        m0 = nm0; m1 = nm1;
        #pragma unroll
        for (int nt = 0; nt < 8; nt++) {
            o[nt][0] *= c0; o[nt][1] *= c0;
            o[nt][2] *= c1; o[nt][3] *= c1;
        }

        #pragma unroll
        for (int nt = 0; nt < 8; nt++) {
            float2 p0 = {s[nt][0], s[nt][1]};
            float2 p1 = {s[nt][2], s[nt][3]};
            *reinterpret_cast<float2*>(&Ps[grp * KSTR + nt * 8 + 2 * tig]) = p0;
            *reinterpret_cast<float2*>(&Ps[(grp + 8) * KSTR + nt * 8 + 2 * tig]) = p1;
        }
        __syncwarp();

        #pragma unroll
        for (int kc = 0; kc < 8; kc++) {
            uint32_t ap[4];
            ap[0] = __float_as_uint(Ps[grp * KSTR + kc * 8 + tig]);
            ap[1] = __float_as_uint(Ps[(grp + 8) * KSTR + kc * 8 + tig]);
            ap[2] = __float_as_uint(Ps[grp * KSTR + kc * 8 + tig + 4]);
            ap[3] = __float_as_uint(Ps[(grp + 8) * KSTR + kc * 8 + tig + 4]);
            #pragma unroll
            for (int nt2 = 0; nt2 < 8; nt2++) {
                uint32_t bv[2];
                bv[0] = __float_as_uint(Vs[(kc * 8 + tig) * VSTR + nt2 * 8 + grp]);
                bv[1] = __float_as_uint(Vs[(kc * 8 + tig + 4) * VSTR + nt2 * 8 + grp]);
                mma8(o[nt2], ap, bv);
            }
        }
        __syncwarp();
        __syncthreads();
    }

    // epilogue: k-permuted tf32 writes (output consumed only as GEMM A operand)
    float il0 = 1.0f / l0, il1 = 1.0f / l1;
    int r0 = qbase + w * 16 + grp;
    #pragma unroll
    for (int nt2 = 0; nt2 < 8; nt2++) {
        int cg = h * HD_ + nt2 * 8;
        int cw = 2 * tig;
        int p0c = cg + pcol(cw), p1c = cg + pcol(cw + 1);
        O[(size_t)r0 * D_ + p0c]       = to_tf32(o[nt2][0] * il0);
        O[(size_t)r0 * D_ + p1c]       = to_tf32(o[nt2][1] * il0);
        O[(size_t)(r0 + 8) * D_ + p0c] = to_tf32(o[nt2][2] * il1);
        O[(size_t)(r0 + 8) * D_ + p1c] = to_tf32(o[nt2][3] * il1);
    }
}

// ---------------- launch ---------------------------------------------------------
extern "C" void kernel_launch(void* const* d_in, const int* in_sizes, int n_in,
                              void* d_out, int out_size)
{
    const float* x         = (const float*)d_in[0];
    const float* neighbors = (const float*)d_in[1];
    const float* sa_ln_g   = (const float*)d_in[2];
    const float* sa_ln_b   = (const float*)d_in[3];
    const float* sa_wq     = (const float*)d_in[4];
    const float* sa_wk     = (const float*)d_in[5];
    const float* sa_wv     = (const float*)d_in[6];
    const float* sa_wo     = (const float*)d_in[7];
    const float* cca_lnq_g = (const float*)d_in[8];
    const float* cca_lnq_b = (const float*)d_in[9];
    const float* cca_lnkv_g= (const float*)d_in[10];
    const float* cca_lnkv_b= (const float*)d_in[11];
    const float* cca_wq    = (const float*)d_in[12];
    const float* cca_wk    = (const float*)d_in[13];
    const float* cca_wv    = (const float*)d_in[14];
    const float* cca_wo    = (const float*)d_in[15];
    const float* ffn_ln_g  = (const float*)d_in[16];
    const float* ffn_ln_b  = (const float*)d_in[17];
    const float* ffn_w1    = (const float*)d_in[18];
    const float* ffn_w2    = (const float*)d_in[19];
    float* out = (float*)d_out;

    float *h, *qkv, *q, *kv, *kvln, *attn, *x1, *ffn, *wt;
    cudaGetSymbolAddress((void**)&h,    g_h);
    cudaGetSymbolAddress((void**)&qkv,  g_qkv);
    cudaGetSymbolAddress((void**)&q,    g_q);
    cudaGetSymbolAddress((void**)&kv,   g_kv);
    cudaGetSymbolAddress((void**)&kvln, g_kvln);
    cudaGetSymbolAddress((void**)&attn, g_attn);
    cudaGetSymbolAddress((void**)&x1,   g_x1);
    cudaGetSymbolAddress((void**)&ffn,  g_ffn);
    cudaGetSymbolAddress((void**)&wt,   g_wt);

    const size_t MB = 1024 * 1024;
    float* wt_saqkv = wt + 0 * MB;   // [3072, 1024]
    float* wt_sao   = wt + 3 * MB;
    float* wt_ccq   = wt + 4 * MB;
    float* wt_cckv  = wt + 5 * MB;   // [2048, 1024]
    float* wt_cco   = wt + 7 * MB;
    float* wt_f1    = wt + 8 * MB;   // [DFF, D]
    float* wt_f2    = wt + 12 * MB;  // [D, DFF]

    cudaFuncSetAttribute(attn_mma<true >, cudaFuncAttributeMaxDynamicSharedMemorySize, ATT_SMEM_BYTES);
    cudaFuncSetAttribute(attn_mma<false>, cudaFuncAttributeMaxDynamicSharedMemorySize, ATT_SMEM_BYTES);
    cudaFuncSetAttribute((const void*)&gemm_mma<false,false,false>,
                         cudaFuncAttributeMaxDynamicSharedMemorySize, GEMM_SMEM);
    cudaFuncSetAttribute((const void*)&gemm_mma<true ,true ,true >,
                         cudaFuncAttributeMaxDynamicSharedMemorySize, GEMM_SMEM);

    dim3 blk256(256), blk128(128);

    // ---- batched weight transposes (+tf32 rounding, k-permuted) ----
    TP8 tp;
    tp.src[0] = sa_wq;  tp.dst[0] = wt_saqkv + 0 * MB;
    tp.src[1] = sa_wk;  tp.dst[1] = wt_saqkv + 1 * MB;
    tp.src[2] = sa_wv;  tp.dst[2] = wt_saqkv + 2 * MB;
    tp.src[3] = sa_wo;  tp.dst[3] = wt_sao;
    tp.src[4] = cca_wq; tp.dst[4] = wt_ccq;
    tp.src[5] = cca_wk; tp.dst[5] = wt_cckv + 0 * MB;
    tp.src[6] = cca_wv; tp.dst[6] = wt_cckv + 1 * MB;
    tp.src[7] = cca_wo; tp.dst[7] = wt_cco;
    transpose8_kernel<<<dim3(D_ / 32, D_ / 32, 8), blk256>>>(tp, D_, D_);
    transpose_kernel<<<dim3(DFF_ / 32, D_ / 32), blk256>>>(ffn_w1, wt_f1, D_, DFF_);
    transpose_kernel<<<dim3(D_ / 32, DFF_ / 32), blk256>>>(ffn_w2, wt_f2, DFF_, D_);

    dim3 gProj(D_ / 128, TOK_ / 128);            // (8, 32)
    dim3 gQKV(3 * D_ / 128, TOK_ / 128);         // (24, 32)
    dim3 gKV2(2 * D_ / 128, KVTOK_ / 128);       // (16, 128)
    dim3 gFFN1(DFF_ / 128, TOK_ / 128);          // (32, 32)

    // ---- self-attention ----
    ln_kernel<<<TOK_, blk256>>>(x, sa_ln_g, sa_ln_b, h);
    gemm_mma<false,false,false><<<gQKV, blk128, GEMM_SMEM>>>(h, wt_saqkv, nullptr, qkv, TOK_, 3 * D_, D_);
    attn_mma<true><<<dim3(T_ / 64, H_, B_), blk128, ATT_SMEM_BYTES>>>(
        qkv, qkv + D_, qkv + 2 * D_, attn, T_, T_, T_, 3 * D_, 3 * D_);
    gemm_mma<false,false,false><<<gProj, blk128, GEMM_SMEM>>>(attn, wt_sao, x, x1, TOK_, D_, D_);

    // ---- chunked cross-attention (T == NC*chunk; reshapes are views) ----
    ln_kernel<<<TOK_,  blk256>>>(x1, cca_lnq_g, cca_lnq_b, h);
    ln_kernel<<<KVTOK_, blk256>>>(neighbors, cca_lnkv_g, cca_lnkv_b, kvln);
    gemm_mma<false,false,false><<<gProj, blk128, GEMM_SMEM>>>(h,    wt_ccq,  nullptr, q,  TOK_,   D_,     D_);
    gemm_mma<false,false,false><<<gKV2,  blk128, GEMM_SMEM>>>(kvln, wt_cckv, nullptr, kv, KVTOK_, 2 * D_, D_);
    attn_mma<false><<<dim3(1, H_, NCH_), blk128, ATT_SMEM_BYTES>>>(
        q, kv, kv + D_, attn, KV_, CH_, KV_, D_, 2 * D_);
    gemm_mma<false,false,false><<<gProj, blk128, GEMM_SMEM>>>(attn, wt_cco, x1, out, TOK_, D_, D_);

    // ---- FFN ----
    ln_kernel<<<TOK_, blk256>>>(out, ffn_ln_g, ffn_ln_b, h);
    gemm_mma<true, true, true ><<<gFFN1, blk128, GEMM_SMEM>>>(h,   wt_f1, nullptr, ffn, TOK_, DFF_, D_);
    gemm_mma<false,false,false><<<gProj, blk128, GEMM_SMEM>>>(ffn, wt_f2, out,     out, TOK_, D_, DFF_);
}

// round 8
// speedup vs baseline: 6.4702x; 1.5721x over previous
#include <cuda_runtime.h>
#include <cuda_fp16.h>
#include <math.h>
#include <cstdint>

// Problem constants (fixed by setup_inputs)
#define B_     2
#define T_     2048
#define D_     1024
#define H_     16
#define HD_    64
#define TOK_   4096      // B*T
#define NCH_   64        // B*NC chunks
#define CH_    64        // chunk_size
#define KV_    256       // K*NL
#define KVTOK_ 16384     // NCH_*KV_
#define DFF_   4096

// ---------------- scratch (static device globals; no allocation) ----------------
__device__ __half g_h   [TOK_  * D_];      // LN out (GEMM A, half k16-perm)
__device__ __half g_kvln[KVTOK_* D_];
__device__ __half g_attn[TOK_  * D_];      // attention out (GEMM A)
__device__ __half g_ffn [TOK_  * DFF_];    // GELU out (GEMM A)
__device__ __half g_wt  [16u * 1024u * 1024u];  // transposed weights (GEMM B), 32 MB
__device__ float  g_qkv [TOK_  * 3 * D_];  // fused SA q|k|v (attention input, fp32)
__device__ float  g_q   [TOK_  * D_];      // cca q
__device__ float  g_kv  [KVTOK_* 2 * D_];  // fused CCA k|v
__device__ float  g_x1  [TOK_  * D_];

// ---------------- helpers ---------------------------------------------------------
__device__ __forceinline__ uint32_t smem_u32(const void* p) {
    uint32_t a;
    asm("{ .reg .u64 t; cvta.to.shared.u64 t, %1; cvt.u32.u64 %0, t; }" : "=r"(a) : "l"(p));
    return a;
}

// k16 permutation: original col c -> packed pos (pairs (2t,2t+1),(2t+8,2t+9) adjacent)
__device__ __forceinline__ int p16(int c) {
    return (c & ~15) + 4 * ((c & 7) >> 1) + 2 * ((c >> 3) & 1) + (c & 1);
}

__device__ __forceinline__ void cp16(uint32_t s, const void* g) {
    asm volatile("cp.async.cg.shared.global [%0], [%1], 16;" :: "r"(s), "l"(g));
}
__device__ __forceinline__ void cp_commit() {
    asm volatile("cp.async.commit_group;" ::: "memory");
}
template<int N>
__device__ __forceinline__ void cp_wait() {
    asm volatile("cp.async.wait_group %0;" :: "n"(N) : "memory");
}

// m16n8k16 fp16 MMA, C(f32) += A*B
__device__ __forceinline__ void mma16(float* c, const uint32_t* a, const uint32_t* b) {
    asm volatile(
        "mma.sync.aligned.m16n8k16.row.col.f32.f16.f16.f32 "
        "{%0,%1,%2,%3}, {%4,%5,%6,%7}, {%8,%9}, {%0,%1,%2,%3};"
        : "+f"(c[0]), "+f"(c[1]), "+f"(c[2]), "+f"(c[3])
        : "r"(a[0]), "r"(a[1]), "r"(a[2]), "r"(a[3]), "r"(b[0]), "r"(b[1]));
}

// m16n8k8 tf32 MMA (attention)
__device__ __forceinline__ void mma8(float* c, const uint32_t* a, const uint32_t* b) {
    asm volatile(
        "mma.sync.aligned.m16n8k8.row.col.f32.tf32.tf32.f32 "
        "{%0,%1,%2,%3}, {%4,%5,%6,%7}, {%8,%9}, {%0,%1,%2,%3};"
        : "+f"(c[0]), "+f"(c[1]), "+f"(c[2]), "+f"(c[3])
        : "r"(a[0]), "r"(a[1]), "r"(a[2]), "r"(a[3]), "r"(b[0]), "r"(b[1]));
}

// ---------------- batched weight transpose: WT[n, p16(k)] = half(W[k,n]) ---------
struct TP8 { const float* src[8]; __half* dst[8]; };

__global__ __launch_bounds__(256) void transpose8_kernel(TP8 p, int K, int N)
{
    __shared__ float t[32][33];
    const float* W = p.src[blockIdx.z];
    __half* WT = p.dst[blockIdx.z];
    int kb = blockIdx.y * 32, nb = blockIdx.x * 32;
    int tx = threadIdx.x & 31, ty4 = (threadIdx.x >> 5) * 4;
    #pragma unroll
    for (int r = 0; r < 4; r++)
        t[ty4 + r][tx] = W[(size_t)(kb + ty4 + r) * N + nb + tx];
    __syncthreads();
    int txp = p16(tx);
    #pragma unroll
    for (int r = 0; r < 4; r++)
        WT[(size_t)(nb + ty4 + r) * K + kb + txp] = __float2half_rn(t[tx][ty4 + r]);
}

__global__ __launch_bounds__(256) void transpose_kernel(
    const float* __restrict__ W, __half* __restrict__ WT, int K, int N)
{
    __shared__ float t[32][33];
    int kb = blockIdx.y * 32, nb = blockIdx.x * 32;
    int tx = threadIdx.x & 31, ty4 = (threadIdx.x >> 5) * 4;
    #pragma unroll
    for (int r = 0; r < 4; r++)
        t[ty4 + r][tx] = W[(size_t)(kb + ty4 + r) * N + nb + tx];
    __syncthreads();
    int txp = p16(tx);
    #pragma unroll
    for (int r = 0; r < 4; r++)
        WT[(size_t)(nb + ty4 + r) * K + kb + txp] = __float2half_rn(t[tx][ty4 + r]);
}

// ---------------- LayerNorm -> half, k16-permuted (GEMM A operand) ---------------
__global__ __launch_bounds__(256) void ln_kernel(
    const float* __restrict__ x, const float* __restrict__ g,
    const float* __restrict__ b, __half* __restrict__ out)
{
    int row = blockIdx.x;
    int tid = threadIdx.x;
    const float4* xr = reinterpret_cast<const float4*>(x + (size_t)row * D_);
    float4 v4 = xr[tid];
    float s  = v4.x + v4.y + v4.z + v4.w;
    float ss = v4.x*v4.x + v4.y*v4.y + v4.z*v4.z + v4.w*v4.w;

    __shared__ float sh1[8], sh2[8];
    int lane = tid & 31, wid = tid >> 5;
    #pragma unroll
    for (int o = 16; o; o >>= 1) {
        s  += __shfl_down_sync(0xffffffffu, s,  o);
        ss += __shfl_down_sync(0xffffffffu, ss, o);
    }
    if (lane == 0) { sh1[wid] = s; sh2[wid] = ss; }
    __syncthreads();
    if (tid < 32) {
        s  = (tid < 8) ? sh1[tid] : 0.f;
        ss = (tid < 8) ? sh2[tid] : 0.f;
        #pragma unroll
        for (int o = 4; o; o >>= 1) {
            s  += __shfl_down_sync(0xffffffffu, s,  o);
            ss += __shfl_down_sync(0xffffffffu, ss, o);
        }
        if (tid == 0) { sh1[0] = s; sh2[0] = ss; }
    }
    __syncthreads();
    float mean = sh1[0] * (1.0f / D_);
    float var  = sh2[0] * (1.0f / D_) - mean * mean;
    float rstd = rsqrtf(var + 1e-5f);

    const float4 g4 = reinterpret_cast<const float4*>(g)[tid];
    const float4 b4 = reinterpret_cast<const float4*>(b)[tid];
    float o0 = (v4.x - mean) * rstd * g4.x + b4.x;
    float o1 = (v4.y - mean) * rstd * g4.y + b4.y;
    float o2 = (v4.z - mean) * rstd * g4.z + b4.z;
    float o3 = (v4.w - mean) * rstd * g4.w + b4.w;
    int cbase = tid * 4;
    int pos0 = p16(cbase);                   // covers cbase, cbase+1
    __half* orow = out + (size_t)row * D_;
    *reinterpret_cast<__half2*>(orow + pos0)     = __floats2half2_rn(o0, o1);
    *reinterpret_cast<__half2*>(orow + pos0 + 4) = __floats2half2_rn(o2, o3);
}

// ---------------- fp16 mma.sync GEMM: C = A[MxK] @ WT[NxK]^T (+resid)(+gelu) -----
// 128x128 block tile, 128 threads (4 warps, 2x2), warp tile 64x64, BK=32 (halves),
// 3-stage cp.async, LDS.64 fragment loads, row stride 48 halves (conflict-free).
#define SSTR 48
#define HSTAGE (128 * SSTR)
#define GEMM_SMEM (3 * 2 * HSTAGE * 2)      // 73728 bytes

template<bool GELU, bool PERM_OUT>
__global__ __launch_bounds__(128) void gemm_mma(
    const __half* __restrict__ A, const __half* __restrict__ WT,
    const float* __restrict__ resid, void* __restrict__ Cout,
    int M, int N, int K)
{
    extern __shared__ __half smh[];
    __half* As = smh;                 // [3][128][SSTR]
    __half* Bs = smh + 3 * HSTAGE;

    int tid = threadIdx.x;
    int wid = tid >> 5, lane = tid & 31;
    int warpM = wid >> 1, warpN = wid & 1;
    int grp = lane >> 2, tig = lane & 3;

    int n0 = blockIdx.x * 128, m0 = blockIdx.y * 128;
    const __half* Ab = A  + (size_t)m0 * K;
    const __half* Bb = WT + (size_t)n0 * K;

    float acc[4][8][4];
    #pragma unroll
    for (int i = 0; i < 4; i++)
        #pragma unroll
        for (int j = 0; j < 8; j++)
            #pragma unroll
            for (int q = 0; q < 4; q++) acc[i][j][q] = 0.f;

    int nk = K >> 5;

    auto load_stage = [&](int st, int kt) {
        int k0 = kt << 5;
        __half* Ast = As + st * HSTAGE;
        __half* Bst = Bs + st * HSTAGE;
        #pragma unroll
        for (int i = 0; i < 4; i++) {
            int idx = tid + i * 128;
            int m = idx >> 2, kc = (idx & 3) * 8;
            cp16(smem_u32(Ast + m * SSTR + kc), Ab + (size_t)m * K + k0 + kc);
            cp16(smem_u32(Bst + m * SSTR + kc), Bb + (size_t)m * K + k0 + kc);
        }
        cp_commit();
    };

    load_stage(0, 0);
    if (nk > 1) load_stage(1, 1);

    for (int kt = 0; kt < nk; kt++) {
        int buf = kt % 3;
        if (kt + 1 < nk) cp_wait<1>(); else cp_wait<0>();
        __syncthreads();
        if (kt + 2 < nk) load_stage((kt + 2) % 3, kt + 2);

        __half* Abuf = As + buf * HSTAGE;
        __half* Bbuf = Bs + buf * HSTAGE;

        #pragma unroll
        for (int ks = 0; ks < 2; ks++) {
            int kof = ks * 16 + 4 * tig;
            uint32_t af[4][4], bf[8][2];
            #pragma unroll
            for (int mt = 0; mt < 4; mt++) {
                int rA = warpM * 64 + mt * 16 + grp;
                uint2 lo = *reinterpret_cast<const uint2*>(Abuf + rA * SSTR + kof);
                uint2 hi = *reinterpret_cast<const uint2*>(Abuf + (rA + 8) * SSTR + kof);
                af[mt][0] = lo.x; af[mt][1] = hi.x;
                af[mt][2] = lo.y; af[mt][3] = hi.y;
            }
            #pragma unroll
            for (int nt = 0; nt < 8; nt++) {
                int rB = warpN * 64 + nt * 8 + grp;
                uint2 bb = *reinterpret_cast<const uint2*>(Bbuf + rB * SSTR + kof);
                bf[nt][0] = bb.x; bf[nt][1] = bb.y;
            }
            #pragma unroll
            for (int mt = 0; mt < 4; mt++)
                #pragma unroll
                for (int nt = 0; nt < 8; nt++)
                    mma16(acc[mt][nt], af[mt], bf[nt]);
        }
    }

    #pragma unroll
    for (int mt = 0; mt < 4; mt++) {
        int row = m0 + warpM * 64 + mt * 16 + grp;
        #pragma unroll
        for (int nt = 0; nt < 8; nt++) {
            int col = n0 + warpN * 64 + nt * 8 + 2 * tig;
            #pragma unroll
            for (int half_ = 0; half_ < 2; half_++) {
                int r = row + half_ * 8;
                float v0 = acc[mt][nt][half_ * 2 + 0];
                float v1 = acc[mt][nt][half_ * 2 + 1];
                if (GELU) {
                    v0 = 0.5f * v0 * (1.0f + erff(v0 * 0.70710678118654752f));
                    v1 = 0.5f * v1 * (1.0f + erff(v1 * 0.70710678118654752f));
                }
                if (resid) {
                    float2 rv = *reinterpret_cast<const float2*>(resid + (size_t)r * N + col);
                    v0 += rv.x; v1 += rv.y;
                }
                if (PERM_OUT) {
                    __half* C16 = (__half*)Cout;
                    int pos = p16(col);
                    *reinterpret_cast<__half2*>(C16 + (size_t)r * N + pos) =
                        __floats2half2_rn(v0, v1);
                } else {
                    float* Cf = (float*)Cout;
                    float2 ov = {v0, v1};
                    *reinterpret_cast<float2*>(Cf + (size_t)r * N + col) = ov;
                }
            }
        }
    }
}

// ---------------- tensor-core flash attention (tf32 mma, online softmax) --------
// fp32 Q/K/V inputs (qld/kld row strides); output half, k16-permuted (GEMM A).
#define KSTR 68
#define VSTR 72
#define ATT_SMEM_FLOATS (2 * (64 * KSTR + 64 * VSTR) + 4 * 16 * KSTR)
#define ATT_SMEM_BYTES  (ATT_SMEM_FLOATS * 4)

template<bool CAUSAL>
__global__ __launch_bounds__(128) void attn_mma(
    const float* __restrict__ Q, const float* __restrict__ Kg,
    const float* __restrict__ Vg, __half* __restrict__ O,
    int klen, int q_tokens_per_batch, int kv_tokens_per_batch,
    int qld, int kld)
{
    extern __shared__ float sm[];
    int tid = threadIdx.x, w = tid >> 5, lane = tid & 31;
    int grp = lane >> 2, tig = lane & 3;
    int qt = blockIdx.x, h = blockIdx.y, b = blockIdx.z;
    int qbase  = b * q_tokens_per_batch + qt * 64;
    int kvbase = b * kv_tokens_per_batch;

    const int KV_BUF = 64 * KSTR + 64 * VSTR;
    float* Ksm0 = sm;
    float* Vsm0 = sm + 64 * KSTR;
    float* Ksm1 = sm + KV_BUF;
    float* Vsm1 = sm + KV_BUF + 64 * KSTR;
    float* Ps   = sm + 2 * KV_BUF + w * (16 * KSTR);

    for (int i = tid; i < 64 * 16; i += 128) {
        int r = i >> 4, c4 = (i & 15) << 2;
        *reinterpret_cast<float4*>(&Ksm0[r * KSTR + c4]) =
            *reinterpret_cast<const float4*>(&Q[(size_t)(qbase + r) * qld + h * HD_ + c4]);
    }
    __syncthreads();
    uint32_t aq[8][4];
    {
        int r0 = w * 16 + grp;
        #pragma unroll
        for (int kc = 0; kc < 8; kc++) {
            int c = kc * 8 + tig;
            aq[kc][0] = __float_as_uint(Ksm0[r0 * KSTR + c] * 0.125f);
            aq[kc][1] = __float_as_uint(Ksm0[(r0 + 8) * KSTR + c] * 0.125f);
            aq[kc][2] = __float_as_uint(Ksm0[r0 * KSTR + c + 4] * 0.125f);
            aq[kc][3] = __float_as_uint(Ksm0[(r0 + 8) * KSTR + c + 4] * 0.125f);
        }
    }
    __syncthreads();

    float o[8][4];
    #pragma unroll
    for (int i = 0; i < 8; i++)
        #pragma unroll
        for (int j = 0; j < 4; j++) o[i][j] = 0.f;
    float m0 = -1e30f, m1 = -1e30f, l0 = 0.f, l1 = 0.f;

    int ktiles = klen >> 6;
    if (CAUSAL && qt + 1 < ktiles) ktiles = qt + 1;

    {
        for (int i = tid; i < 64 * 16; i += 128) {
            int r = i >> 4, c4 = (i & 15) << 2;
            size_t gofs = (size_t)(kvbase + r) * kld + h * HD_ + c4;
            cp16(smem_u32(&Ksm0[r * KSTR + c4]), Kg + gofs);
            cp16(smem_u32(&Vsm0[r * VSTR + c4]), Vg + gofs);
        }
        cp_commit();
    }

    for (int kt = 0; kt < ktiles; kt++) {
        int buf = kt & 1;
        float* Ks = buf ? Ksm1 : Ksm0;
        float* Vs = buf ? Vsm1 : Vsm0;
        if (kt + 1 < ktiles) {
            float* Kn = buf ? Ksm0 : Ksm1;
            float* Vn = buf ? Vsm0 : Vsm1;
            int kb = kvbase + (kt + 1) * 64;
            for (int i = tid; i < 64 * 16; i += 128) {
                int r = i >> 4, c4 = (i & 15) << 2;
                size_t gofs = (size_t)(kb + r) * kld + h * HD_ + c4;
                cp16(smem_u32(&Kn[r * KSTR + c4]), Kg + gofs);
                cp16(smem_u32(&Vn[r * VSTR + c4]), Vg + gofs);
            }
            cp_commit();
            cp_wait<1>();
        } else {
            cp_wait<0>();
        }
        __syncthreads();

        float s[8][4];
        #pragma unroll
        for (int nt = 0; nt < 8; nt++)
            #pragma unroll
            for (int j = 0; j < 4; j++) s[nt][j] = 0.f;

        #pragma unroll
        for (int kc = 0; kc < 8; kc++) {
            #pragma unroll
            for (int nt = 0; nt < 8; nt++) {
                uint32_t bk[2];
                int key = nt * 8 + grp;
                bk[0] = __float_as_uint(Ks[key * KSTR + kc * 8 + tig]);
                bk[1] = __float_as_uint(Ks[key * KSTR + kc * 8 + tig + 4]);
                mma8(s[nt], aq[kc], bk);
            }
        }

        if (CAUSAL && kt == qt) {
            int r0 = qt * 64 + w * 16 + grp;
            #pragma unroll
            for (int nt = 0; nt < 8; nt++) {
                int c = kt * 64 + nt * 8 + 2 * tig;
                if (c     > r0)     s[nt][0] = -1e30f;
                if (c + 1 > r0)     s[nt][1] = -1e30f;
                if (c     > r0 + 8) s[nt][2] = -1e30f;
                if (c + 1 > r0 + 8) s[nt][3] = -1e30f;
            }
        }

        float t0 = -1e30f, t1 = -1e30f;
        #pragma unroll
        for (int nt = 0; nt < 8; nt++) {
            t0 = fmaxf(t0, fmaxf(s[nt][0], s[nt][1]));
            t1 = fmaxf(t1, fmaxf(s[nt][2], s[nt][3]));
        }
        t0 = fmaxf(t0, __shfl_xor_sync(0xffffffffu, t0, 1));
        t0 = fmaxf(t0, __shfl_xor_sync(0xffffffffu, t0, 2));
        t1 = fmaxf(t1, __shfl_xor_sync(0xffffffffu, t1, 1));
        t1 = fmaxf(t1, __shfl_xor_sync(0xffffffffu, t1, 2));
        float nm0 = fmaxf(m0, t0), nm1 = fmaxf(m1, t1);
        float c0 = __expf(m0 - nm0), c1 = __expf(m1 - nm1);
        float ts0 = 0.f, ts1 = 0.f;
        #pragma unroll
        for (int nt = 0; nt < 8; nt++) {
            s[nt][0] = __expf(s[nt][0] - nm0);
            s[nt][1] = __expf(s[nt][1] - nm0);
            s[nt][2] = __expf(s[nt][2] - nm1);
            s[nt][3] = __expf(s[nt][3] - nm1);
            ts0 += s[nt][0] + s[nt][1];
            ts1 += s[nt][2] + s[nt][3];
        }
        ts0 += __shfl_xor_sync(0xffffffffu, ts0, 1);
        ts0 += __shfl_xor_sync(0xffffffffu, ts0, 2);
        ts1 += __shfl_xor_sync(0xffffffffu, ts1, 1);
        ts1 += __shfl_xor_sync(0xffffffffu, ts1, 2);
        l0 = l0 * c0 + ts0;
        l1 = l1 * c1 + ts1;
        m0 = nm0; m1 = nm1;
        #pragma unroll
        for (int nt = 0; nt < 8; nt++) {
            o[nt][0] *= c0; o[nt][1] *= c0;
            o[nt][2] *= c1; o[nt][3] *= c1;
        }

        #pragma unroll
        for (int nt = 0; nt < 8; nt++) {
            float2 p0 = {s[nt][0], s[nt][1]};
            float2 p1 = {s[nt][2], s[nt][3]};
            *reinterpret_cast<float2*>(&Ps[grp * KSTR + nt * 8 + 2 * tig]) = p0;
            *reinterpret_cast<float2*>(&Ps[(grp + 8) * KSTR + nt * 8 + 2 * tig]) = p1;
        }
        __syncwarp();

        #pragma unroll
        for (int kc = 0; kc < 8; kc++) {
            uint32_t ap[4];
            ap[0] = __float_as_uint(Ps[grp * KSTR + kc * 8 + tig]);
            ap[1] = __float_as_uint(Ps[(grp + 8) * KSTR + kc * 8 + tig]);
            ap[2] = __float_as_uint(Ps[grp * KSTR + kc * 8 + tig + 4]);
            ap[3] = __float_as_uint(Ps[(grp + 8) * KSTR + kc * 8 + tig + 4]);
            #pragma unroll
            for (int nt2 = 0; nt2 < 8; nt2++) {
                uint32_t bv[2];
                bv[0] = __float_as_uint(Vs[(kc * 8 + tig) * VSTR + nt2 * 8 + grp]);
                bv[1] = __float_as_uint(Vs[(kc * 8 + tig + 4) * VSTR + nt2 * 8 + grp]);
                mma8(o[nt2], ap, bv);
            }
        }
        __syncwarp();
        __syncthreads();
    }

    // epilogue: half, k16-permuted (consumed only as GEMM A operand)
    float il0 = 1.0f / l0, il1 = 1.0f / l1;
    int r0 = qbase + w * 16 + grp;
    #pragma unroll
    for (int nt2 = 0; nt2 < 8; nt2++) {
        int col = h * HD_ + nt2 * 8 + 2 * tig;
        int pos = p16(col);
        *reinterpret_cast<__half2*>(O + (size_t)r0 * D_ + pos) =
            __floats2half2_rn(o[nt2][0] * il0, o[nt2][1] * il0);
        *reinterpret_cast<__half2*>(O + (size_t)(r0 + 8) * D_ + pos) =
            __floats2half2_rn(o[nt2][2] * il1, o[nt2][3] * il1);
    }
}

// ---------------- launch ---------------------------------------------------------
extern "C" void kernel_launch(void* const* d_in, const int* in_sizes, int n_in,
                              void* d_out, int out_size)
{
    const float* x         = (const float*)d_in[0];
    const float* neighbors = (const float*)d_in[1];
    const float* sa_ln_g   = (const float*)d_in[2];
    const float* sa_ln_b   = (const float*)d_in[3];
    const float* sa_wq     = (const float*)d_in[4];
    const float* sa_wk     = (const float*)d_in[5];
    const float* sa_wv     = (const float*)d_in[6];
    const float* sa_wo     = (const float*)d_in[7];
    const float* cca_lnq_g = (const float*)d_in[8];
    const float* cca_lnq_b = (const float*)d_in[9];
    const float* cca_lnkv_g= (const float*)d_in[10];
    const float* cca_lnkv_b= (const float*)d_in[11];
    const float* cca_wq    = (const float*)d_in[12];
    const float* cca_wk    = (const float*)d_in[13];
    const float* cca_wv    = (const float*)d_in[14];
    const float* cca_wo    = (const float*)d_in[15];
    const float* ffn_ln_g  = (const float*)d_in[16];
    const float* ffn_ln_b  = (const float*)d_in[17];
    const float* ffn_w1    = (const float*)d_in[18];
    const float* ffn_w2    = (const float*)d_in[19];
    float* out = (float*)d_out;

    __half *h, *kvln, *attn, *ffn, *wt;
    float *qkv, *q, *kv, *x1;
    cudaGetSymbolAddress((void**)&h,    g_h);
    cudaGetSymbolAddress((void**)&kvln, g_kvln);
    cudaGetSymbolAddress((void**)&attn, g_attn);
    cudaGetSymbolAddress((void**)&ffn,  g_ffn);
    cudaGetSymbolAddress((void**)&wt,   g_wt);
    cudaGetSymbolAddress((void**)&qkv,  g_qkv);
    cudaGetSymbolAddress((void**)&q,    g_q);
    cudaGetSymbolAddress((void**)&kv,   g_kv);
    cudaGetSymbolAddress((void**)&x1,   g_x1);

    const size_t MB = 1024 * 1024;
    __half* wt_saqkv = wt + 0 * MB;   // [3072, 1024]
    __half* wt_sao   = wt + 3 * MB;
    __half* wt_ccq   = wt + 4 * MB;
    __half* wt_cckv  = wt + 5 * MB;   // [2048, 1024]
    __half* wt_cco   = wt + 7 * MB;
    __half* wt_f1    = wt + 8 * MB;   // [DFF, D]
    __half* wt_f2    = wt + 12 * MB;  // [D, DFF]

    cudaFuncSetAttribute(attn_mma<true >, cudaFuncAttributeMaxDynamicSharedMemorySize, ATT_SMEM_BYTES);
    cudaFuncSetAttribute(attn_mma<false>, cudaFuncAttributeMaxDynamicSharedMemorySize, ATT_SMEM_BYTES);
    cudaFuncSetAttribute((const void*)&gemm_mma<false,false>,
                         cudaFuncAttributeMaxDynamicSharedMemorySize, GEMM_SMEM);
    cudaFuncSetAttribute((const void*)&gemm_mma<true ,true >,
                         cudaFuncAttributeMaxDynamicSharedMemorySize, GEMM_SMEM);

    dim3 blk256(256), blk128(128);

    // ---- batched weight transposes (fp32 -> half, k16-permuted) ----
    TP8 tp;
    tp.src[0] = sa_wq;  tp.dst[0] = wt_saqkv + 0 * MB;
    tp.src[1] = sa_wk;  tp.dst[1] = wt_saqkv + 1 * MB;
    tp.src[2] = sa_wv;  tp.dst[2] = wt_saqkv + 2 * MB;
    tp.src[3] = sa_wo;  tp.dst[3] = wt_sao;
    tp.src[4] = cca_wq; tp.dst[4] = wt_ccq;
    tp.src[5] = cca_wk; tp.dst[5] = wt_cckv + 0 * MB;
    tp.src[6] = cca_wv; tp.dst[6] = wt_cckv + 1 * MB;
    tp.src[7] = cca_wo; tp.dst[7] = wt_cco;
    transpose8_kernel<<<dim3(D_ / 32, D_ / 32, 8), blk256>>>(tp, D_, D_);
    transpose_kernel<<<dim3(DFF_ / 32, D_ / 32), blk256>>>(ffn_w1, wt_f1, D_, DFF_);
    transpose_kernel<<<dim3(D_ / 32, DFF_ / 32), blk256>>>(ffn_w2, wt_f2, DFF_, D_);

    dim3 gProj(D_ / 128, TOK_ / 128);            // (8, 32)
    dim3 gQKV(3 * D_ / 128, TOK_ / 128);         // (24, 32)
    dim3 gKV2(2 * D_ / 128, KVTOK_ / 128);       // (16, 128)
    dim3 gFFN1(DFF_ / 128, TOK_ / 128);          // (32, 32)

    // ---- self-attention ----
    ln_kernel<<<TOK_, blk256>>>(x, sa_ln_g, sa_ln_b, h);
    gemm_mma<false,false><<<gQKV, blk128, GEMM_SMEM>>>(h, wt_saqkv, nullptr, qkv, TOK_, 3 * D_, D_);
    attn_mma<true><<<dim3(T_ / 64, H_, B_), blk128, ATT_SMEM_BYTES>>>(
        qkv, qkv + D_, qkv + 2 * D_, attn, T_, T_, T_, 3 * D_, 3 * D_);
    gemm_mma<false,false><<<gProj, blk128, GEMM_SMEM>>>(attn, wt_sao, x, x1, TOK_, D_, D_);

    // ---- chunked cross-attention (T == NC*chunk; reshapes are views) ----
    ln_kernel<<<TOK_,  blk256>>>(x1, cca_lnq_g, cca_lnq_b, h);
    ln_kernel<<<KVTOK_, blk256>>>(neighbors, cca_lnkv_g, cca_lnkv_b, kvln);
    gemm_mma<false,false><<<gProj, blk128, GEMM_SMEM>>>(h,    wt_ccq,  nullptr, q,  TOK_,   D_,     D_);
    gemm_mma<false,false><<<gKV2,  blk128, GEMM_SMEM>>>(kvln, wt_cckv, nullptr, kv, KVTOK_, 2 * D_, D_);
    attn_mma<false><<<dim3(1, H_, NCH_), blk128, ATT_SMEM_BYTES>>>(
        q, kv, kv + D_, attn, KV_, CH_, KV_, D_, 2 * D_);
    gemm_mma<false,false><<<gProj, blk128, GEMM_SMEM>>>(attn, wt_cco, x1, out, TOK_, D_, D_);

    // ---- FFN ----
    ln_kernel<<<TOK_, blk256>>>(out, ffn_ln_g, ffn_ln_b, h);
    gemm_mma<true, true ><<<gFFN1, blk128, GEMM_SMEM>>>(h,   wt_f1, nullptr, ffn, TOK_, DFF_, D_);
    gemm_mma<false,false><<<gProj, blk128, GEMM_SMEM>>>(ffn, wt_f2, out,     out, TOK_, D_, DFF_);
}

// round 9
// speedup vs baseline: 7.3318x; 1.1332x over previous
#include <cuda_runtime.h>
#include <cuda_fp16.h>
#include <math.h>
#include <cstdint>

// Problem constants (fixed by setup_inputs)
#define B_     2
#define T_     2048
#define D_     1024
#define H_     16
#define HD_    64
#define TOK_   4096      // B*T
#define NCH_   64        // B*NC chunks
#define CH_    64        // chunk_size
#define KV_    256       // K*NL
#define KVTOK_ 16384     // NCH_*KV_
#define DFF_   4096

// ---------------- scratch (static device globals; no allocation) ----------------
__device__ __half g_h   [TOK_  * D_];      // LN out (GEMM A, half k16-perm)
__device__ __half g_kvln[KVTOK_* D_];
__device__ __half g_attn[TOK_  * D_];      // attention out (GEMM A)
__device__ __half g_ffn [TOK_  * DFF_];    // GELU out (GEMM A)
__device__ __half g_wt  [16u * 1024u * 1024u];  // transposed weights (GEMM B)
__device__ __half g_qk  [TOK_  * 2 * D_];  // SA q|k (half, k16-perm)
__device__ __half g_vt  [TOK_  * D_];      // SA V^T: [b][dim][token]
__device__ __half g_ccq [TOK_  * D_];      // CCA q (half perm)
__device__ __half g_cck [KVTOK_* D_];      // CCA k (half perm)
__device__ __half g_ccvt[KVTOK_* D_];      // CCA V^T: [chunk][dim][key]
__device__ float  g_x1  [TOK_  * D_];

// ---------------- helpers ---------------------------------------------------------
__device__ __forceinline__ uint32_t smem_u32(const void* p) {
    uint32_t a;
    asm("{ .reg .u64 t; cvta.to.shared.u64 t, %1; cvt.u32.u64 %0, t; }" : "=r"(a) : "l"(p));
    return a;
}

// k16 permutation: original col c -> packed pos (pairs (2t,2t+1),(2t+8,2t+9) adjacent)
__device__ __forceinline__ int p16(int c) {
    return (c & ~15) + 4 * ((c & 7) >> 1) + 2 * ((c >> 3) & 1) + (c & 1);
}

__device__ __forceinline__ void cp16(uint32_t s, const void* g) {
    asm volatile("cp.async.cg.shared.global [%0], [%1], 16;" :: "r"(s), "l"(g));
}
__device__ __forceinline__ void cp_commit() {
    asm volatile("cp.async.commit_group;" ::: "memory");
}
template<int N>
__device__ __forceinline__ void cp_wait() {
    asm volatile("cp.async.wait_group %0;" :: "n"(N) : "memory");
}

// m16n8k16 fp16 MMA, C(f32) += A*B
__device__ __forceinline__ void mma16(float* c, const uint32_t* a, const uint32_t* b) {
    asm volatile(
        "mma.sync.aligned.m16n8k16.row.col.f32.f16.f16.f32 "
        "{%0,%1,%2,%3}, {%4,%5,%6,%7}, {%8,%9}, {%0,%1,%2,%3};"
        : "+f"(c[0]), "+f"(c[1]), "+f"(c[2]), "+f"(c[3])
        : "r"(a[0]), "r"(a[1]), "r"(a[2]), "r"(a[3]), "r"(b[0]), "r"(b[1]));
}

__device__ __forceinline__ uint32_t hmul2u(uint32_t x, uint32_t s) {
    __half2 a = *reinterpret_cast<__half2*>(&x);
    __half2 b = *reinterpret_cast<__half2*>(&s);
    __half2 r = __hmul2(a, b);
    return *reinterpret_cast<uint32_t*>(&r);
}

// ---------------- batched weight transpose: WT[n, p16(k)] = half(W[k,n]) ---------
struct TP8 { const float* src[8]; __half* dst[8]; };

__global__ __launch_bounds__(256) void transpose8_kernel(TP8 p, int K, int N)
{
    __shared__ float t[32][33];
    const float* W = p.src[blockIdx.z];
    __half* WT = p.dst[blockIdx.z];
    int kb = blockIdx.y * 32, nb = blockIdx.x * 32;
    int tx = threadIdx.x & 31, ty4 = (threadIdx.x >> 5) * 4;
    #pragma unroll
    for (int r = 0; r < 4; r++)
        t[ty4 + r][tx] = W[(size_t)(kb + ty4 + r) * N + nb + tx];
    __syncthreads();
    int txp = p16(tx);
    #pragma unroll
    for (int r = 0; r < 4; r++)
        WT[(size_t)(nb + ty4 + r) * K + kb + txp] = __float2half_rn(t[tx][ty4 + r]);
}

__global__ __launch_bounds__(256) void transpose_kernel(
    const float* __restrict__ W, __half* __restrict__ WT, int K, int N)
{
    __shared__ float t[32][33];
    int kb = blockIdx.y * 32, nb = blockIdx.x * 32;
    int tx = threadIdx.x & 31, ty4 = (threadIdx.x >> 5) * 4;
    #pragma unroll
    for (int r = 0; r < 4; r++)
        t[ty4 + r][tx] = W[(size_t)(kb + ty4 + r) * N + nb + tx];
    __syncthreads();
    int txp = p16(tx);
    #pragma unroll
    for (int r = 0; r < 4; r++)
        WT[(size_t)(nb + ty4 + r) * K + kb + txp] = __float2half_rn(t[tx][ty4 + r]);
}

// ---------------- LayerNorm -> half, k16-permuted (GEMM A operand) ---------------
__global__ __launch_bounds__(256) void ln_kernel(
    const float* __restrict__ x, const float* __restrict__ g,
    const float* __restrict__ b, __half* __restrict__ out)
{
    int row = blockIdx.x;
    int tid = threadIdx.x;
    const float4* xr = reinterpret_cast<const float4*>(x + (size_t)row * D_);
    float4 v4 = xr[tid];
    float s  = v4.x + v4.y + v4.z + v4.w;
    float ss = v4.x*v4.x + v4.y*v4.y + v4.z*v4.z + v4.w*v4.w;

    __shared__ float sh1[8], sh2[8];
    int lane = tid & 31, wid = tid >> 5;
    #pragma unroll
    for (int o = 16; o; o >>= 1) {
        s  += __shfl_down_sync(0xffffffffu, s,  o);
        ss += __shfl_down_sync(0xffffffffu, ss, o);
    }
    if (lane == 0) { sh1[wid] = s; sh2[wid] = ss; }
    __syncthreads();
    if (tid < 32) {
        s  = (tid < 8) ? sh1[tid] : 0.f;
        ss = (tid < 8) ? sh2[tid] : 0.f;
        #pragma unroll
        for (int o = 4; o; o >>= 1) {
            s  += __shfl_down_sync(0xffffffffu, s,  o);
            ss += __shfl_down_sync(0xffffffffu, ss, o);
        }
        if (tid == 0) { sh1[0] = s; sh2[0] = ss; }
    }
    __syncthreads();
    float mean = sh1[0] * (1.0f / D_);
    float var  = sh2[0] * (1.0f / D_) - mean * mean;
    float rstd = rsqrtf(var + 1e-5f);

    const float4 g4 = reinterpret_cast<const float4*>(g)[tid];
    const float4 b4 = reinterpret_cast<const float4*>(b)[tid];
    float o0 = (v4.x - mean) * rstd * g4.x + b4.x;
    float o1 = (v4.y - mean) * rstd * g4.y + b4.y;
    float o2 = (v4.z - mean) * rstd * g4.z + b4.z;
    float o3 = (v4.w - mean) * rstd * g4.w + b4.w;
    int cbase = tid * 4;
    int pos0 = p16(cbase);
    __half* orow = out + (size_t)row * D_;
    *reinterpret_cast<__half2*>(orow + pos0)     = __floats2half2_rn(o0, o1);
    *reinterpret_cast<__half2*>(orow + pos0 + 4) = __floats2half2_rn(o2, o3);
}

// ---------------- fp16 mma.sync GEMM: C = A[MxK] @ WT[NxK]^T ---------------------
// MODE 0: fp32 out (+resid); MODE 1: half k16-perm out; MODE 2: QKV split
//   (cols < vcol0 -> half perm, stride vcol0; cols >= vcol0 -> V^T half
//    vt[batch][dim][t], batch = r / vbatch).
#define SSTR 48
#define HSTAGE (128 * SSTR)
#define GEMM_SMEM (3 * 2 * HSTAGE * 2)      // 73728 bytes

template<bool GELU, int MODE>
__global__ __launch_bounds__(128) void gemm_mma(
    const __half* __restrict__ A, const __half* __restrict__ WT,
    const float* __restrict__ resid, void* __restrict__ Cout,
    __half* __restrict__ vt_out, int vcol0, int vbatch,
    int M, int N, int K)
{
    extern __shared__ __half smh[];
    __half* As = smh;                 // [3][128][SSTR]
    __half* Bs = smh + 3 * HSTAGE;

    int tid = threadIdx.x;
    int wid = tid >> 5, lane = tid & 31;
    int warpM = wid >> 1, warpN = wid & 1;
    int grp = lane >> 2, tig = lane & 3;

    int n0 = blockIdx.x * 128, m0 = blockIdx.y * 128;
    const __half* Ab = A  + (size_t)m0 * K;
    const __half* Bb = WT + (size_t)n0 * K;

    float acc[4][8][4];
    #pragma unroll
    for (int i = 0; i < 4; i++)
        #pragma unroll
        for (int j = 0; j < 8; j++)
            #pragma unroll
            for (int q = 0; q < 4; q++) acc[i][j][q] = 0.f;

    int nk = K >> 5;

    auto load_stage = [&](int st, int kt) {
        int k0 = kt << 5;
        __half* Ast = As + st * HSTAGE;
        __half* Bst = Bs + st * HSTAGE;
        #pragma unroll
        for (int i = 0; i < 4; i++) {
            int idx = tid + i * 128;
            int m = idx >> 2, kc = (idx & 3) * 8;
            cp16(smem_u32(Ast + m * SSTR + kc), Ab + (size_t)m * K + k0 + kc);
            cp16(smem_u32(Bst + m * SSTR + kc), Bb + (size_t)m * K + k0 + kc);
        }
        cp_commit();
    };

    load_stage(0, 0);
    if (nk > 1) load_stage(1, 1);

    for (int kt = 0; kt < nk; kt++) {
        int buf = kt % 3;
        if (kt + 1 < nk) cp_wait<1>(); else cp_wait<0>();
        __syncthreads();
        if (kt + 2 < nk) load_stage((kt + 2) % 3, kt + 2);

        __half* Abuf = As + buf * HSTAGE;
        __half* Bbuf = Bs + buf * HSTAGE;

        #pragma unroll
        for (int ks = 0; ks < 2; ks++) {
            int kof = ks * 16 + 4 * tig;
            uint32_t af[4][4], bf[8][2];
            #pragma unroll
            for (int mt = 0; mt < 4; mt++) {
                int rA = warpM * 64 + mt * 16 + grp;
                uint2 lo = *reinterpret_cast<const uint2*>(Abuf + rA * SSTR + kof);
                uint2 hi = *reinterpret_cast<const uint2*>(Abuf + (rA + 8) * SSTR + kof);
                af[mt][0] = lo.x; af[mt][1] = hi.x;
                af[mt][2] = lo.y; af[mt][3] = hi.y;
            }
            #pragma unroll
            for (int nt = 0; nt < 8; nt++) {
                int rB = warpN * 64 + nt * 8 + grp;
                uint2 bb = *reinterpret_cast<const uint2*>(Bbuf + rB * SSTR + kof);
                bf[nt][0] = bb.x; bf[nt][1] = bb.y;
            }
            #pragma unroll
            for (int mt = 0; mt < 4; mt++)
                #pragma unroll
                for (int nt = 0; nt < 8; nt++)
                    mma16(acc[mt][nt], af[mt], bf[nt]);
        }
    }

    bool vt_region = (MODE == 2) && (n0 >= vcol0);

    #pragma unroll
    for (int mt = 0; mt < 4; mt++) {
        int row = m0 + warpM * 64 + mt * 16 + grp;
        #pragma unroll
        for (int nt = 0; nt < 8; nt++) {
            int col = n0 + warpN * 64 + nt * 8 + 2 * tig;
            #pragma unroll
            for (int half_ = 0; half_ < 2; half_++) {
                int r = row + half_ * 8;
                float v0 = acc[mt][nt][half_ * 2 + 0];
                float v1 = acc[mt][nt][half_ * 2 + 1];
                if (GELU) {
                    v0 = 0.5f * v0 * (1.0f + erff(v0 * 0.70710678118654752f));
                    v1 = 0.5f * v1 * (1.0f + erff(v1 * 0.70710678118654752f));
                }
                if (MODE == 0) {
                    if (resid) {
                        float2 rv = *reinterpret_cast<const float2*>(resid + (size_t)r * N + col);
                        v0 += rv.x; v1 += rv.y;
                    }
                    float* Cf = (float*)Cout;
                    float2 ov = {v0, v1};
                    *reinterpret_cast<float2*>(Cf + (size_t)r * N + col) = ov;
                } else if (MODE == 1 || !vt_region) {
                    int ldo = (MODE == 2) ? vcol0 : N;
                    __half* C16 = (__half*)Cout;
                    *reinterpret_cast<__half2*>(C16 + (size_t)r * ldo + p16(col)) =
                        __floats2half2_rn(v0, v1);
                } else {
                    int dim = col - vcol0;
                    int batch = r / vbatch;
                    int t = r - batch * vbatch;
                    size_t base = ((size_t)batch * (N - vcol0) + dim) * vbatch + t;
                    vt_out[base]          = __float2half_rn(v0);
                    vt_out[base + vbatch] = __float2half_rn(v1);
                }
            }
        }
    }
}

// ---------------- fp16 tensor-core flash attention (online softmax) --------------
// Qh/Kh: half, k16-permuted dims, row strides qld/kld.
// Vt: half V^T  [batch][dim][key], key stride = kv_tokens_per_batch.
// O: half, k16-permuted (GEMM A operand), stride D_.
#define KSH 80
#define VSH 72
#define PSH 80
#define ATTH_HALVES (2 * (64 * KSH + 64 * VSH) + 4 * 16 * PSH)
#define ATTH_BYTES  (ATTH_HALVES * 2)

template<bool CAUSAL>
__global__ __launch_bounds__(128) void attn_h(
    const __half* __restrict__ Qh, const __half* __restrict__ Kh,
    const __half* __restrict__ Vt, __half* __restrict__ O,
    int klen, int qtpb, int kvtpb, int qld, int kld)
{
    extern __shared__ __half smh[];
    int tid = threadIdx.x, w = tid >> 5, lane = tid & 31;
    int grp = lane >> 2, tig = lane & 3;
    int qt = blockIdx.x, h = blockIdx.y, b = blockIdx.z;
    int qbase = b * qtpb + qt * 64;

    const int KV_BUF = 64 * KSH + 64 * VSH;
    __half* Ks0 = smh;
    __half* Vs0 = smh + 64 * KSH;
    __half* Ks1 = smh + KV_BUF;
    __half* Vs1 = smh + KV_BUF + 64 * KSH;
    __half* Ps  = smh + 2 * KV_BUF + w * (16 * PSH);

    // ---- stage Q (half, permuted) into Ks0, build scaled A-fragments ----
    for (int i = tid; i < 64 * 8; i += 128) {
        int r = i >> 3, c = (i & 7) * 8;
        *reinterpret_cast<uint4*>(&Ks0[r * KSH + c]) =
            *reinterpret_cast<const uint4*>(&Qh[(size_t)(qbase + r) * qld + h * HD_ + c]);
    }
    __syncthreads();
    uint32_t aq[4][4];
    {
        __half2 sch = __half2half2(__float2half(0.125f));   // exact
        uint32_t sc = *reinterpret_cast<uint32_t*>(&sch);
        int r0 = w * 16 + grp;
        #pragma unroll
        for (int ko = 0; ko < 4; ko++) {
            int base = 16 * ko + 4 * tig;
            uint2 lo = *reinterpret_cast<const uint2*>(&Ks0[r0 * KSH + base]);
            uint2 hi = *reinterpret_cast<const uint2*>(&Ks0[(r0 + 8) * KSH + base]);
            aq[ko][0] = hmul2u(lo.x, sc); aq[ko][1] = hmul2u(hi.x, sc);
            aq[ko][2] = hmul2u(lo.y, sc); aq[ko][3] = hmul2u(hi.y, sc);
        }
    }
    __syncthreads();

    float o[8][4];
    #pragma unroll
    for (int i = 0; i < 8; i++)
        #pragma unroll
        for (int j = 0; j < 4; j++) o[i][j] = 0.f;
    float m0 = -1e30f, m1 = -1e30f, l0 = 0.f, l1 = 0.f;

    int ktiles = klen >> 6;
    if (CAUSAL && qt + 1 < ktiles) ktiles = qt + 1;

    auto load_kv = [&](__half* Ks, __half* Vs, int kt) {
        int kb = kt * 64;
        for (int i = tid; i < 512; i += 128) {
            int r = i >> 3, c = (i & 7) * 8;
            cp16(smem_u32(&Ks[r * KSH + c]),
                 Kh + (size_t)(b * kvtpb + kb + r) * kld + h * HD_ + c);
            cp16(smem_u32(&Vs[r * VSH + c]),
                 Vt + ((size_t)(b * D_ + h * HD_ + r)) * kvtpb + kb + c);
        }
        cp_commit();
    };

    load_kv(Ks0, Vs0, 0);

    for (int kt = 0; kt < ktiles; kt++) {
        int buf = kt & 1;
        __half* Ks = buf ? Ks1 : Ks0;
        __half* Vs = buf ? Vs1 : Vs0;
        if (kt + 1 < ktiles) {
            load_kv(buf ? Ks0 : Ks1, buf ? Vs0 : Vs1, kt + 1);
            cp_wait<1>();
        } else {
            cp_wait<0>();
        }
        __syncthreads();

        // ---- S = Q @ K^T (fp16 k16) ----
        float s[8][4];
        #pragma unroll
        for (int nt = 0; nt < 8; nt++)
            #pragma unroll
            for (int j = 0; j < 4; j++) s[nt][j] = 0.f;

        #pragma unroll
        for (int ko = 0; ko < 4; ko++) {
            int kof = 16 * ko + 4 * tig;
            #pragma unroll
            for (int nt = 0; nt < 8; nt++) {
                int key = nt * 8 + grp;
                uint2 bb = *reinterpret_cast<const uint2*>(&Ks[key * KSH + kof]);
                uint32_t bk[2] = {bb.x, bb.y};
                mma16(s[nt], aq[ko], bk);
            }
        }

        if (CAUSAL && kt == qt) {
            int r0 = qt * 64 + w * 16 + grp;
            #pragma unroll
            for (int nt = 0; nt < 8; nt++) {
                int c = kt * 64 + nt * 8 + 2 * tig;
                if (c     > r0)     s[nt][0] = -1e30f;
                if (c + 1 > r0)     s[nt][1] = -1e30f;
                if (c     > r0 + 8) s[nt][2] = -1e30f;
                if (c + 1 > r0 + 8) s[nt][3] = -1e30f;
            }
        }

        // ---- online softmax ----
        float t0 = -1e30f, t1 = -1e30f;
        #pragma unroll
        for (int nt = 0; nt < 8; nt++) {
            t0 = fmaxf(t0, fmaxf(s[nt][0], s[nt][1]));
            t1 = fmaxf(t1, fmaxf(s[nt][2], s[nt][3]));
        }
        t0 = fmaxf(t0, __shfl_xor_sync(0xffffffffu, t0, 1));
        t0 = fmaxf(t0, __shfl_xor_sync(0xffffffffu, t0, 2));
        t1 = fmaxf(t1, __shfl_xor_sync(0xffffffffu, t1, 1));
        t1 = fmaxf(t1, __shfl_xor_sync(0xffffffffu, t1, 2));
        float nm0 = fmaxf(m0, t0), nm1 = fmaxf(m1, t1);
        float c0 = __expf(m0 - nm0), c1 = __expf(m1 - nm1);
        float ts0 = 0.f, ts1 = 0.f;
        #pragma unroll
        for (int nt = 0; nt < 8; nt++) {
            s[nt][0] = __expf(s[nt][0] - nm0);
            s[nt][1] = __expf(s[nt][1] - nm0);
            s[nt][2] = __expf(s[nt][2] - nm1);
            s[nt][3] = __expf(s[nt][3] - nm1);
            ts0 += s[nt][0] + s[nt][1];
            ts1 += s[nt][2] + s[nt][3];
        }
        ts0 += __shfl_xor_sync(0xffffffffu, ts0, 1);
        ts0 += __shfl_xor_sync(0xffffffffu, ts0, 2);
        ts1 += __shfl_xor_sync(0xffffffffu, ts1, 1);
        ts1 += __shfl_xor_sync(0xffffffffu, ts1, 2);
        l0 = l0 * c0 + ts0;
        l1 = l1 * c1 + ts1;
        m0 = nm0; m1 = nm1;
        #pragma unroll
        for (int nt = 0; nt < 8; nt++) {
            o[nt][0] *= c0; o[nt][1] *= c0;
            o[nt][2] *= c1; o[nt][3] *= c1;
        }

        // ---- P -> half, key-permuted, warp-private smem ----
        #pragma unroll
        for (int nt = 0; nt < 8; nt++) {
            int pos = (nt >> 1) * 16 + 4 * tig + 2 * (nt & 1);
            *reinterpret_cast<__half2*>(&Ps[grp * PSH + pos]) =
                __floats2half2_rn(s[nt][0], s[nt][1]);
            *reinterpret_cast<__half2*>(&Ps[(grp + 8) * PSH + pos]) =
                __floats2half2_rn(s[nt][2], s[nt][3]);
        }
        __syncwarp();

        // ---- O += P @ V (fp16 k16, V^T dim-major smem) ----
        #pragma unroll
        for (int ko = 0; ko < 4; ko++) {
            int kof = 16 * ko + 4 * tig;
            uint2 lo = *reinterpret_cast<const uint2*>(&Ps[grp * PSH + kof]);
            uint2 hi = *reinterpret_cast<const uint2*>(&Ps[(grp + 8) * PSH + kof]);
            uint32_t ap[4] = {lo.x, hi.x, lo.y, hi.y};
            #pragma unroll
            for (int nt2 = 0; nt2 < 8; nt2++) {
                int n = nt2 * 8 + grp;
                uint32_t bv[2];
                bv[0] = *reinterpret_cast<const uint32_t*>(&Vs[n * VSH + 16 * ko + 2 * tig]);
                bv[1] = *reinterpret_cast<const uint32_t*>(&Vs[n * VSH + 16 * ko + 2 * tig + 8]);
                mma16(o[nt2], ap, bv);
            }
        }
        __syncwarp();
        __syncthreads();
    }

    // ---- epilogue: half, k16-permuted ----
    float il0 = 1.0f / l0, il1 = 1.0f / l1;
    int r0 = qbase + w * 16 + grp;
    #pragma unroll
    for (int nt2 = 0; nt2 < 8; nt2++) {
        int col = h * HD_ + nt2 * 8 + 2 * tig;
        int pos = p16(col);
        *reinterpret_cast<__half2*>(O + (size_t)r0 * D_ + pos) =
            __floats2half2_rn(o[nt2][0] * il0, o[nt2][1] * il0);
        *reinterpret_cast<__half2*>(O + (size_t)(r0 + 8) * D_ + pos) =
            __floats2half2_rn(o[nt2][2] * il1, o[nt2][3] * il1);
    }
}

// ---------------- launch ---------------------------------------------------------
extern "C" void kernel_launch(void* const* d_in, const int* in_sizes, int n_in,
                              void* d_out, int out_size)
{
    const float* x         = (const float*)d_in[0];
    const float* neighbors = (const float*)d_in[1];
    const float* sa_ln_g   = (const float*)d_in[2];
    const float* sa_ln_b   = (const float*)d_in[3];
    const float* sa_wq     = (const float*)d_in[4];
    const float* sa_wk     = (const float*)d_in[5];
    const float* sa_wv     = (const float*)d_in[6];
    const float* sa_wo     = (const float*)d_in[7];
    const float* cca_lnq_g = (const float*)d_in[8];
    const float* cca_lnq_b = (const float*)d_in[9];
    const float* cca_lnkv_g= (const float*)d_in[10];
    const float* cca_lnkv_b= (const float*)d_in[11];
    const float* cca_wq    = (const float*)d_in[12];
    const float* cca_wk    = (const float*)d_in[13];
    const float* cca_wv    = (const float*)d_in[14];
    const float* cca_wo    = (const float*)d_in[15];
    const float* ffn_ln_g  = (const float*)d_in[16];
    const float* ffn_ln_b  = (const float*)d_in[17];
    const float* ffn_w1    = (const float*)d_in[18];
    const float* ffn_w2    = (const float*)d_in[19];
    float* out = (float*)d_out;

    __half *h, *kvln, *attn, *ffn, *wt, *qk, *vt, *ccq, *cck, *ccvt;
    float *x1;
    cudaGetSymbolAddress((void**)&h,    g_h);
    cudaGetSymbolAddress((void**)&kvln, g_kvln);
    cudaGetSymbolAddress((void**)&attn, g_attn);
    cudaGetSymbolAddress((void**)&ffn,  g_ffn);
    cudaGetSymbolAddress((void**)&wt,   g_wt);
    cudaGetSymbolAddress((void**)&qk,   g_qk);
    cudaGetSymbolAddress((void**)&vt,   g_vt);
    cudaGetSymbolAddress((void**)&ccq,  g_ccq);
    cudaGetSymbolAddress((void**)&cck,  g_cck);
    cudaGetSymbolAddress((void**)&ccvt, g_ccvt);
    cudaGetSymbolAddress((void**)&x1,   g_x1);

    const size_t MB = 1024 * 1024;
    __half* wt_saqkv = wt + 0 * MB;   // [3072, 1024]
    __half* wt_sao   = wt + 3 * MB;
    __half* wt_ccq   = wt + 4 * MB;
    __half* wt_cckv  = wt + 5 * MB;   // [2048, 1024]
    __half* wt_cco   = wt + 7 * MB;
    __half* wt_f1    = wt + 8 * MB;   // [DFF, D]
    __half* wt_f2    = wt + 12 * MB;  // [D, DFF]

    cudaFuncSetAttribute(attn_h<true >, cudaFuncAttributeMaxDynamicSharedMemorySize, ATTH_BYTES);
    cudaFuncSetAttribute(attn_h<false>, cudaFuncAttributeMaxDynamicSharedMemorySize, ATTH_BYTES);
    cudaFuncSetAttribute((const void*)&gemm_mma<false,0>,
                         cudaFuncAttributeMaxDynamicSharedMemorySize, GEMM_SMEM);
    cudaFuncSetAttribute((const void*)&gemm_mma<false,1>,
                         cudaFuncAttributeMaxDynamicSharedMemorySize, GEMM_SMEM);
    cudaFuncSetAttribute((const void*)&gemm_mma<false,2>,
                         cudaFuncAttributeMaxDynamicSharedMemorySize, GEMM_SMEM);
    cudaFuncSetAttribute((const void*)&gemm_mma<true ,1>,
                         cudaFuncAttributeMaxDynamicSharedMemorySize, GEMM_SMEM);

    dim3 blk256(256), blk128(128);

    // ---- batched weight transposes (fp32 -> half, k16-permuted) ----
    TP8 tp;
    tp.src[0] = sa_wq;  tp.dst[0] = wt_saqkv + 0 * MB;
    tp.src[1] = sa_wk;  tp.dst[1] = wt_saqkv + 1 * MB;
    tp.src[2] = sa_wv;  tp.dst[2] = wt_saqkv + 2 * MB;
    tp.src[3] = sa_wo;  tp.dst[3] = wt_sao;
    tp.src[4] = cca_wq; tp.dst[4] = wt_ccq;
    tp.src[5] = cca_wk; tp.dst[5] = wt_cckv + 0 * MB;
    tp.src[6] = cca_wv; tp.dst[6] = wt_cckv + 1 * MB;
    tp.src[7] = cca_wo; tp.dst[7] = wt_cco;
    transpose8_kernel<<<dim3(D_ / 32, D_ / 32, 8), blk256>>>(tp, D_, D_);
    transpose_kernel<<<dim3(DFF_ / 32, D_ / 32), blk256>>>(ffn_w1, wt_f1, D_, DFF_);
    transpose_kernel<<<dim3(D_ / 32, DFF_ / 32), blk256>>>(ffn_w2, wt_f2, DFF_, D_);

    dim3 gProj(D_ / 128, TOK_ / 128);            // (8, 32)
    dim3 gQKV(3 * D_ / 128, TOK_ / 128);         // (24, 32)
    dim3 gKV2(2 * D_ / 128, KVTOK_ / 128);       // (16, 128)
    dim3 gFFN1(DFF_ / 128, TOK_ / 128);          // (32, 32)

    // ---- self-attention ----
    ln_kernel<<<TOK_, blk256>>>(x, sa_ln_g, sa_ln_b, h);
    gemm_mma<false,2><<<gQKV, blk128, GEMM_SMEM>>>(
        h, wt_saqkv, nullptr, qk, vt, 2 * D_, T_, TOK_, 3 * D_, D_);
    attn_h<true><<<dim3(T_ / 64, H_, B_), blk128, ATTH_BYTES>>>(
        qk, qk + D_, vt, attn, T_, T_, T_, 2 * D_, 2 * D_);
    gemm_mma<false,0><<<gProj, blk128, GEMM_SMEM>>>(
        attn, wt_sao, x, x1, nullptr, 0, 0, TOK_, D_, D_);

    // ---- chunked cross-attention (T == NC*chunk; reshapes are views) ----
    ln_kernel<<<TOK_,  blk256>>>(x1, cca_lnq_g, cca_lnq_b, h);
    ln_kernel<<<KVTOK_, blk256>>>(neighbors, cca_lnkv_g, cca_lnkv_b, kvln);
    gemm_mma<false,1><<<gProj, blk128, GEMM_SMEM>>>(
        h, wt_ccq, nullptr, ccq, nullptr, 0, 0, TOK_, D_, D_);
    gemm_mma<false,2><<<gKV2, blk128, GEMM_SMEM>>>(
        kvln, wt_cckv, nullptr, cck, ccvt, D_, KV_, KVTOK_, 2 * D_, D_);
    attn_h<false><<<dim3(1, H_, NCH_), blk128, ATTH_BYTES>>>(
        ccq, cck, ccvt, attn, KV_, CH_, KV_, D_, D_);
    gemm_mma<false,0><<<gProj, blk128, GEMM_SMEM>>>(
        attn, wt_cco, x1, out, nullptr, 0, 0, TOK_, D_, D_);

    // ---- FFN ----
    ln_kernel<<<TOK_, blk256>>>(out, ffn_ln_g, ffn_ln_b, h);
    gemm_mma<true ,1><<<gFFN1, blk128, GEMM_SMEM>>>(
        h, wt_f1, nullptr, ffn, nullptr, 0, 0, TOK_, DFF_, D_);
    gemm_mma<false,0><<<gProj, blk128, GEMM_SMEM>>>(
        ffn, wt_f2, out, out, nullptr, 0, 0, TOK_, D_, DFF_);
}

// round 11
// speedup vs baseline: 7.3986x; 1.0091x over previous
#include <cuda_runtime.h>
#include <cuda_fp16.h>
#include <math.h>
#include <cstdint>

// Problem constants (fixed by setup_inputs)
#define B_     2
#define T_     2048
#define D_     1024
#define H_     16
#define HD_    64
#define TOK_   4096      // B*T
#define NCH_   64        // B*NC chunks
#define CH_    64        // chunk_size
#define KV_    256       // K*NL
#define KVTOK_ 16384     // NCH_*KV_
#define DFF_   4096

// ---------------- scratch (static device globals; no allocation) ----------------
__device__ __half g_h   [TOK_  * D_];      // LN out (GEMM A, half k16-perm)
__device__ __half g_kvln[KVTOK_* D_];
__device__ __half g_attn[TOK_  * D_];      // attention out (GEMM A)
__device__ __half g_ffn [TOK_  * DFF_];    // GELU out (GEMM A)
__device__ __half g_wt  [16u * 1024u * 1024u];  // transposed weights (GEMM B)
__device__ __half g_qk  [TOK_  * 2 * D_];  // SA q|k (half, k16-perm)
__device__ __half g_vt  [TOK_  * D_];      // SA V^T: [b][dim][token]
__device__ __half g_ccq [TOK_  * D_];      // CCA q (half perm)
__device__ __half g_cck [KVTOK_* D_];      // CCA k (half perm)
__device__ __half g_ccvt[KVTOK_* D_];      // CCA V^T: [chunk][dim][key]
__device__ float  g_x1  [TOK_  * D_];

// ---------------- helpers ---------------------------------------------------------
__device__ __forceinline__ uint32_t smem_u32(const void* p) {
    uint32_t a;
    asm("{ .reg .u64 t; cvta.to.shared.u64 t, %1; cvt.u32.u64 %0, t; }" : "=r"(a) : "l"(p));
    return a;
}

// k16 permutation: original col c -> packed pos (pairs (2t,2t+1),(2t+8,2t+9) adjacent)
__device__ __forceinline__ int p16(int c) {
    return (c & ~15) + 4 * ((c & 7) >> 1) + 2 * ((c >> 3) & 1) + (c & 1);
}

__device__ __forceinline__ void cp16(uint32_t s, const void* g) {
    asm volatile("cp.async.cg.shared.global [%0], [%1], 16;" :: "r"(s), "l"(g));
}
__device__ __forceinline__ void cp_commit() {
    asm volatile("cp.async.commit_group;" ::: "memory");
}
template<int N>
__device__ __forceinline__ void cp_wait() {
    asm volatile("cp.async.wait_group %0;" :: "n"(N) : "memory");
}

// m16n8k16 fp16 MMA, C(f32) += A*B
__device__ __forceinline__ void mma16(float* c, const uint32_t* a, const uint32_t* b) {
    asm volatile(
        "mma.sync.aligned.m16n8k16.row.col.f32.f16.f16.f32 "
        "{%0,%1,%2,%3}, {%4,%5,%6,%7}, {%8,%9}, {%0,%1,%2,%3};"
        : "+f"(c[0]), "+f"(c[1]), "+f"(c[2]), "+f"(c[3])
        : "r"(a[0]), "r"(a[1]), "r"(a[2]), "r"(a[3]), "r"(b[0]), "r"(b[1]));
}

__device__ __forceinline__ uint32_t hmul2u(uint32_t x, uint32_t s) {
    __half2 a = *reinterpret_cast<__half2*>(&x);
    __half2 b = *reinterpret_cast<__half2*>(&s);
    __half2 r = __hmul2(a, b);
    return *reinterpret_cast<uint32_t*>(&r);
}

// ---------------- batched weight transpose: WT[n, p16(k)] = half(W[k,n]) ---------
struct TP8 { const float* src[8]; __half* dst[8]; };

__global__ __launch_bounds__(256) void transpose8_kernel(TP8 p, int K, int N)
{
    __shared__ float t[32][33];
    const float* W = p.src[blockIdx.z];
    __half* WT = p.dst[blockIdx.z];
    int kb = blockIdx.y * 32, nb = blockIdx.x * 32;
    int tx = threadIdx.x & 31, ty4 = (threadIdx.x >> 5) * 4;
    #pragma unroll
    for (int r = 0; r < 4; r++)
        t[ty4 + r][tx] = W[(size_t)(kb + ty4 + r) * N + nb + tx];
    __syncthreads();
    int txp = p16(tx);
    #pragma unroll
    for (int r = 0; r < 4; r++)
        WT[(size_t)(nb + ty4 + r) * K + kb + txp] = __float2half_rn(t[tx][ty4 + r]);
}

__global__ __launch_bounds__(256) void transpose_kernel(
    const float* __restrict__ W, __half* __restrict__ WT, int K, int N)
{
    __shared__ float t[32][33];
    int kb = blockIdx.y * 32, nb = blockIdx.x * 32;
    int tx = threadIdx.x & 31, ty4 = (threadIdx.x >> 5) * 4;
    #pragma unroll
    for (int r = 0; r < 4; r++)
        t[ty4 + r][tx] = W[(size_t)(kb + ty4 + r) * N + nb + tx];
    __syncthreads();
    int txp = p16(tx);
    #pragma unroll
    for (int r = 0; r < 4; r++)
        WT[(size_t)(nb + ty4 + r) * K + kb + txp] = __float2half_rn(t[tx][ty4 + r]);
}

// ---------------- LayerNorm: warp-per-row, no barriers -> half k16-perm ----------
__global__ __launch_bounds__(256) void ln_kernel(
    const float* __restrict__ x, const float* __restrict__ g,
    const float* __restrict__ b, __half* __restrict__ out)
{
    int w = threadIdx.x >> 5, lane = threadIdx.x & 31;
    int row = blockIdx.x * 8 + w;
    const float4* xr = reinterpret_cast<const float4*>(x + (size_t)row * D_);

    float4 v[8];
    float s = 0.f, ss = 0.f;
    #pragma unroll
    for (int j = 0; j < 8; j++) {
        v[j] = xr[lane + 32 * j];
        s  += v[j].x + v[j].y + v[j].z + v[j].w;
        ss += v[j].x*v[j].x + v[j].y*v[j].y + v[j].z*v[j].z + v[j].w*v[j].w;
    }
    #pragma unroll
    for (int o = 16; o; o >>= 1) {
        s  += __shfl_xor_sync(0xffffffffu, s,  o);
        ss += __shfl_xor_sync(0xffffffffu, ss, o);
    }
    float mean = s * (1.0f / D_);
    float var  = ss * (1.0f / D_) - mean * mean;
    float rstd = rsqrtf(var + 1e-5f);

    const float4* gv = reinterpret_cast<const float4*>(g);
    const float4* bv = reinterpret_cast<const float4*>(b);
    __half* orow = out + (size_t)row * D_;
    #pragma unroll
    for (int j = 0; j < 8; j++) {
        int idx = lane + 32 * j;
        float4 g4 = gv[idx], b4 = bv[idx];
        float o0 = (v[j].x - mean) * rstd * g4.x + b4.x;
        float o1 = (v[j].y - mean) * rstd * g4.y + b4.y;
        float o2 = (v[j].z - mean) * rstd * g4.z + b4.z;
        float o3 = (v[j].w - mean) * rstd * g4.w + b4.w;
        int cbase = idx * 4;
        int pos0 = p16(cbase);
        *reinterpret_cast<__half2*>(orow + pos0)     = __floats2half2_rn(o0, o1);
        *reinterpret_cast<__half2*>(orow + pos0 + 4) = __floats2half2_rn(o2, o3);
    }
}

// ---------------- fp16 mma.sync GEMM: C = A[MxK] @ WT[NxK]^T ---------------------
// MODE 0: fp32 out (+resid); MODE 1: half k16-perm out; MODE 2: QKV split
//   (cols < vcol0 -> half perm, stride vcol0; cols >= vcol0 -> V^T half
//    vt[batch][dim][t], batch = r / vbatch).
#define SSTR 48
#define HSTAGE (128 * SSTR)
#define GEMM_SMEM (3 * 2 * HSTAGE * 2)      // 73728 bytes

template<bool GELU, int MODE>
__global__ __launch_bounds__(128) void gemm_mma(
    const __half* __restrict__ A, const __half* __restrict__ WT,
    const float* __restrict__ resid, void* __restrict__ Cout,
    __half* __restrict__ vt_out, int vcol0, int vbatch,
    int M, int N, int K)
{
    extern __shared__ __half smh[];
    __half* As = smh;                 // [3][128][SSTR]
    __half* Bs = smh + 3 * HSTAGE;

    int tid = threadIdx.x;
    int wid = tid >> 5, lane = tid & 31;
    int warpM = wid >> 1, warpN = wid & 1;
    int grp = lane >> 2, tig = lane & 3;

    int n0 = blockIdx.x * 128, m0 = blockIdx.y * 128;
    const __half* Ab = A  + (size_t)m0 * K;
    const __half* Bb = WT + (size_t)n0 * K;

    float acc[4][8][4];
    #pragma unroll
    for (int i = 0; i < 4; i++)
        #pragma unroll
        for (int j = 0; j < 8; j++)
            #pragma unroll
            for (int q = 0; q < 4; q++) acc[i][j][q] = 0.f;

    int nk = K >> 5;

    auto load_stage = [&](int st, int kt) {
        int k0 = kt << 5;
        __half* Ast = As + st * HSTAGE;
        __half* Bst = Bs + st * HSTAGE;
        #pragma unroll
        for (int i = 0; i < 4; i++) {
            int idx = tid + i * 128;
            int m = idx >> 2, kc = (idx & 3) * 8;
            cp16(smem_u32(Ast + m * SSTR + kc), Ab + (size_t)m * K + k0 + kc);
            cp16(smem_u32(Bst + m * SSTR + kc), Bb + (size_t)m * K + k0 + kc);
        }
        cp_commit();
    };

    load_stage(0, 0);
    if (nk > 1) load_stage(1, 1);

    for (int kt = 0; kt < nk; kt++) {
        int buf = kt % 3;
        if (kt + 1 < nk) cp_wait<1>(); else cp_wait<0>();
        __syncthreads();
        if (kt + 2 < nk) load_stage((kt + 2) % 3, kt + 2);

        __half* Abuf = As + buf * HSTAGE;
        __half* Bbuf = Bs + buf * HSTAGE;

        #pragma unroll
        for (int ks = 0; ks < 2; ks++) {
            int kof = ks * 16 + 4 * tig;
            uint32_t af[4][4], bf[8][2];
            #pragma unroll
            for (int mt = 0; mt < 4; mt++) {
                int rA = warpM * 64 + mt * 16 + grp;
                uint2 lo = *reinterpret_cast<const uint2*>(Abuf + rA * SSTR + kof);
                uint2 hi = *reinterpret_cast<const uint2*>(Abuf + (rA + 8) * SSTR + kof);
                af[mt][0] = lo.x; af[mt][1] = hi.x;
                af[mt][2] = lo.y; af[mt][3] = hi.y;
            }
            #pragma unroll
            for (int nt = 0; nt < 8; nt++) {
                int rB = warpN * 64 + nt * 8 + grp;
                uint2 bb = *reinterpret_cast<const uint2*>(Bbuf + rB * SSTR + kof);
                bf[nt][0] = bb.x; bf[nt][1] = bb.y;
            }
            #pragma unroll
            for (int mt = 0; mt < 4; mt++)
                #pragma unroll
                for (int nt = 0; nt < 8; nt++)
                    mma16(acc[mt][nt], af[mt], bf[nt]);
        }
    }

    bool vt_region = (MODE == 2) && (n0 >= vcol0);

    #pragma unroll
    for (int mt = 0; mt < 4; mt++) {
        int row = m0 + warpM * 64 + mt * 16 + grp;
        #pragma unroll
        for (int nt = 0; nt < 8; nt++) {
            int col = n0 + warpN * 64 + nt * 8 + 2 * tig;
            #pragma unroll
            for (int half_ = 0; half_ < 2; half_++) {
                int r = row + half_ * 8;
                float v0 = acc[mt][nt][half_ * 2 + 0];
                float v1 = acc[mt][nt][half_ * 2 + 1];
                if (GELU) {
                    v0 = 0.5f * v0 * (1.0f + erff(v0 * 0.70710678118654752f));
                    v1 = 0.5f * v1 * (1.0f + erff(v1 * 0.70710678118654752f));
                }
                if (MODE == 0) {
                    if (resid) {
                        float2 rv = *reinterpret_cast<const float2*>(resid + (size_t)r * N + col);
                        v0 += rv.x; v1 += rv.y;
                    }
                    float* Cf = (float*)Cout;
                    float2 ov = {v0, v1};
                    *reinterpret_cast<float2*>(Cf + (size_t)r * N + col) = ov;
                } else if (MODE == 1 || !vt_region) {
                    int ldo = (MODE == 2) ? vcol0 : N;
                    __half* C16 = (__half*)Cout;
                    *reinterpret_cast<__half2*>(C16 + (size_t)r * ldo + p16(col)) =
                        __floats2half2_rn(v0, v1);
                } else {
                    int dim = col - vcol0;
                    int batch = r / vbatch;
                    int t = r - batch * vbatch;
                    size_t base = ((size_t)batch * (N - vcol0) + dim) * vbatch + t;
                    vt_out[base]          = __float2half_rn(v0);
                    vt_out[base + vbatch] = __float2half_rn(v1);
                }
            }
        }
    }
}

// ---------------- fp16 tensor-core flash attention (online softmax) --------------
// Qh/Kh: half, k16-permuted dims, row strides qld/kld.
// Vt: half V^T  [batch][dim][key], key stride = kv_tokens_per_batch.
// O: half, k16-permuted (GEMM A operand), stride D_.
#define KSH 80
#define VSH 72
#define PSH 80
#define ATTH_HALVES (2 * (64 * KSH + 64 * VSH) + 4 * 16 * PSH)
#define ATTH_BYTES  (ATTH_HALVES * 2)

template<bool CAUSAL>
__global__ __launch_bounds__(128) void attn_h(
    const __half* __restrict__ Qh, const __half* __restrict__ Kh,
    const __half* __restrict__ Vt, __half* __restrict__ O,
    int klen, int qtpb, int kvtpb, int qld, int kld)
{
    extern __shared__ __half smh[];
    int tid = threadIdx.x, w = tid >> 5, lane = tid & 31;
    int grp = lane >> 2, tig = lane & 3;
    int qt = blockIdx.x, h = blockIdx.y, b = blockIdx.z;
    int qbase = b * qtpb + qt * 64;

    const int KV_BUF = 64 * KSH + 64 * VSH;
    __half* Ks0 = smh;
    __half* Vs0 = smh + 64 * KSH;
    __half* Ks1 = smh + KV_BUF;
    __half* Vs1 = smh + KV_BUF + 64 * KSH;
    __half* Ps  = smh + 2 * KV_BUF + w * (16 * PSH);

    // ---- stage Q (half, permuted) into Ks0, build scaled A-fragments ----
    for (int i = tid; i < 64 * 8; i += 128) {
        int r = i >> 3, c = (i & 7) * 8;
        *reinterpret_cast<uint4*>(&Ks0[r * KSH + c]) =
            *reinterpret_cast<const uint4*>(&Qh[(size_t)(qbase + r) * qld + h * HD_ + c]);
    }
    __syncthreads();
    uint32_t aq[4][4];
    {
        __half2 sch = __half2half2(__float2half(0.125f));   // exact
        uint32_t sc = *reinterpret_cast<uint32_t*>(&sch);
        int r0 = w * 16 + grp;
        #pragma unroll
        for (int ko = 0; ko < 4; ko++) {
            int base = 16 * ko + 4 * tig;
            uint2 lo = *reinterpret_cast<const uint2*>(&Ks0[r0 * KSH + base]);
            uint2 hi = *reinterpret_cast<const uint2*>(&Ks0[(r0 + 8) * KSH + base]);
            aq[ko][0] = hmul2u(lo.x, sc); aq[ko][1] = hmul2u(hi.x, sc);
            aq[ko][2] = hmul2u(lo.y, sc); aq[ko][3] = hmul2u(hi.y, sc);
        }
    }
    __syncthreads();

    float o[8][4];
    #pragma unroll
    for (int i = 0; i < 8; i++)
        #pragma unroll
        for (int j = 0; j < 4; j++) o[i][j] = 0.f;
    float m0 = -1e30f, m1 = -1e30f, l0 = 0.f, l1 = 0.f;

    int ktiles = klen >> 6;
    if (CAUSAL && qt + 1 < ktiles) ktiles = qt + 1;

    auto load_kv = [&](__half* Ks, __half* Vs, int kt) {
        int kb = kt * 64;
        for (int i = tid; i < 512; i += 128) {
            int r = i >> 3, c = (i & 7) * 8;
            cp16(smem_u32(&Ks[r * KSH + c]),
                 Kh + (size_t)(b * kvtpb + kb + r) * kld + h * HD_ + c);
            cp16(smem_u32(&Vs[r * VSH + c]),
                 Vt + ((size_t)(b * D_ + h * HD_ + r)) * kvtpb + kb + c);
        }
        cp_commit();
    };

    load_kv(Ks0, Vs0, 0);

    for (int kt = 0; kt < ktiles; kt++) {
        int buf = kt & 1;
        __half* Ks = buf ? Ks1 : Ks0;
        __half* Vs = buf ? Vs1 : Vs0;
        if (kt + 1 < ktiles) {
            load_kv(buf ? Ks0 : Ks1, buf ? Vs0 : Vs1, kt + 1);
            cp_wait<1>();
        } else {
            cp_wait<0>();
        }
        __syncthreads();

        // ---- S = Q @ K^T (fp16 k16) ----
        float s[8][4];
        #pragma unroll
        for (int nt = 0; nt < 8; nt++)
            #pragma unroll
            for (int j = 0; j < 4; j++) s[nt][j] = 0.f;

        #pragma unroll
        for (int ko = 0; ko < 4; ko++) {
            int kof = 16 * ko + 4 * tig;
            #pragma unroll
            for (int nt = 0; nt < 8; nt++) {
                int key = nt * 8 + grp;
                uint2 bb = *reinterpret_cast<const uint2*>(&Ks[key * KSH + kof]);
                uint32_t bk[2] = {bb.x, bb.y};
                mma16(s[nt], aq[ko], bk);
            }
        }

        if (CAUSAL && kt == qt) {
            int r0 = qt * 64 + w * 16 + grp;
            #pragma unroll
            for (int nt = 0; nt < 8; nt++) {
                int c = kt * 64 + nt * 8 + 2 * tig;
                if (c     > r0)     s[nt][0] = -1e30f;
                if (c + 1 > r0)     s[nt][1] = -1e30f;
                if (c     > r0 + 8) s[nt][2] = -1e30f;
                if (c + 1 > r0 + 8) s[nt][3] = -1e30f;
            }
        }

        // ---- online softmax ----
        float t0 = -1e30f, t1 = -1e30f;
        #pragma unroll
        for (int nt = 0; nt < 8; nt++) {
            t0 = fmaxf(t0, fmaxf(s[nt][0], s[nt][1]));
            t1 = fmaxf(t1, fmaxf(s[nt][2], s[nt][3]));
        }
        t0 = fmaxf(t0, __shfl_xor_sync(0xffffffffu, t0, 1));
        t0 = fmaxf(t0, __shfl_xor_sync(0xffffffffu, t0, 2));
        t1 = fmaxf(t1, __shfl_xor_sync(0xffffffffu, t1, 1));
        t1 = fmaxf(t1, __shfl_xor_sync(0xffffffffu, t1, 2));
        float nm0 = fmaxf(m0, t0), nm1 = fmaxf(m1, t1);
        float c0 = __expf(m0 - nm0), c1 = __expf(m1 - nm1);
        float ts0 = 0.f, ts1 = 0.f;
        #pragma unroll
        for (int nt = 0; nt < 8; nt++) {
            s[nt][0] = __expf(s[nt][0] - nm0);
            s[nt][1] = __expf(s[nt][1] - nm0);
            s[nt][2] = __expf(s[nt][2] - nm1);
            s[nt][3] = __expf(s[nt][3] - nm1);
            ts0 += s[nt][0] + s[nt][1];
            ts1 += s[nt][2] + s[nt][3];
        }
        ts0 += __shfl_xor_sync(0xffffffffu, ts0, 1);
        ts0 += __shfl_xor_sync(0xffffffffu, ts0, 2);
        ts1 += __shfl_xor_sync(0xffffffffu, ts1, 1);
        ts1 += __shfl_xor_sync(0xffffffffu, ts1, 2);
        l0 = l0 * c0 + ts0;
        l1 = l1 * c1 + ts1;
        m0 = nm0; m1 = nm1;
        #pragma unroll
        for (int nt = 0; nt < 8; nt++) {
            o[nt][0] *= c0; o[nt][1] *= c0;
            o[nt][2] *= c1; o[nt][3] *= c1;
        }

        // ---- P -> half, key-permuted, warp-private smem ----
        #pragma unroll
        for (int nt = 0; nt < 8; nt++) {
            int pos = (nt >> 1) * 16 + 4 * tig + 2 * (nt & 1);
            *reinterpret_cast<__half2*>(&Ps[grp * PSH + pos]) =
                __floats2half2_rn(s[nt][0], s[nt][1]);
            *reinterpret_cast<__half2*>(&Ps[(grp + 8) * PSH + pos]) =
                __floats2half2_rn(s[nt][2], s[nt][3]);
        }
        __syncwarp();

        // ---- O += P @ V (fp16 k16, V^T dim-major smem) ----
        #pragma unroll
        for (int ko = 0; ko < 4; ko++) {
            int kof = 16 * ko + 4 * tig;
            uint2 lo = *reinterpret_cast<const uint2*>(&Ps[grp * PSH + kof]);
            uint2 hi = *reinterpret_cast<const uint2*>(&Ps[(grp + 8) * PSH + kof]);
            uint32_t ap[4] = {lo.x, hi.x, lo.y, hi.y};
            #pragma unroll
            for (int nt2 = 0; nt2 < 8; nt2++) {
                int n = nt2 * 8 + grp;
                uint32_t bv[2];
                bv[0] = *reinterpret_cast<const uint32_t*>(&Vs[n * VSH + 16 * ko + 2 * tig]);
                bv[1] = *reinterpret_cast<const uint32_t*>(&Vs[n * VSH + 16 * ko + 2 * tig + 8]);
                mma16(o[nt2], ap, bv);
            }
        }
        __syncwarp();
        __syncthreads();
    }

    // ---- epilogue: half, k16-permuted ----
    float il0 = 1.0f / l0, il1 = 1.0f / l1;
    int r0 = qbase + w * 16 + grp;
    #pragma unroll
    for (int nt2 = 0; nt2 < 8; nt2++) {
        int col = h * HD_ + nt2 * 8 + 2 * tig;
        int pos = p16(col);
        *reinterpret_cast<__half2*>(O + (size_t)r0 * D_ + pos) =
            __floats2half2_rn(o[nt2][0] * il0, o[nt2][1] * il0);
        *reinterpret_cast<__half2*>(O + (size_t)(r0 + 8) * D_ + pos) =
            __floats2half2_rn(o[nt2][2] * il1, o[nt2][3] * il1);
    }
}

// ---------------- launch ---------------------------------------------------------
extern "C" void kernel_launch(void* const* d_in, const int* in_sizes, int n_in,
                              void* d_out, int out_size)
{
    const float* x         = (const float*)d_in[0];
    const float* neighbors = (const float*)d_in[1];
    const float* sa_ln_g   = (const float*)d_in[2];
    const float* sa_ln_b   = (const float*)d_in[3];
    const float* sa_wq     = (const float*)d_in[4];
    const float* sa_wk     = (const float*)d_in[5];
    const float* sa_wv     = (const float*)d_in[6];
    const float* sa_wo     = (const float*)d_in[7];
    const float* cca_lnq_g = (const float*)d_in[8];
    const float* cca_lnq_b = (const float*)d_in[9];
    const float* cca_lnkv_g= (const float*)d_in[10];
    const float* cca_lnkv_b= (const float*)d_in[11];
    const float* cca_wq    = (const float*)d_in[12];
    const float* cca_wk    = (const float*)d_in[13];
    const float* cca_wv    = (const float*)d_in[14];
    const float* cca_wo    = (const float*)d_in[15];
    const float* ffn_ln_g  = (const float*)d_in[16];
    const float* ffn_ln_b  = (const float*)d_in[17];
    const float* ffn_w1    = (const float*)d_in[18];
    const float* ffn_w2    = (const float*)d_in[19];
    float* out = (float*)d_out;

    __half *h, *kvln, *attn, *ffn, *wt, *qk, *vt, *ccq, *cck, *ccvt;
    float *x1;
    cudaGetSymbolAddress((void**)&h,    g_h);
    cudaGetSymbolAddress((void**)&kvln, g_kvln);
    cudaGetSymbolAddress((void**)&attn, g_attn);
    cudaGetSymbolAddress((void**)&ffn,  g_ffn);
    cudaGetSymbolAddress((void**)&wt,   g_wt);
    cudaGetSymbolAddress((void**)&qk,   g_qk);
    cudaGetSymbolAddress((void**)&vt,   g_vt);
    cudaGetSymbolAddress((void**)&ccq,  g_ccq);
    cudaGetSymbolAddress((void**)&cck,  g_cck);
    cudaGetSymbolAddress((void**)&ccvt, g_ccvt);
    cudaGetSymbolAddress((void**)&x1,   g_x1);

    const size_t MB = 1024 * 1024;
    __half* wt_saqkv = wt + 0 * MB;   // [3072, 1024]
    __half* wt_sao   = wt + 3 * MB;
    __half* wt_ccq   = wt + 4 * MB;
    __half* wt_cckv  = wt + 5 * MB;   // [2048, 1024]
    __half* wt_cco   = wt + 7 * MB;
    __half* wt_f1    = wt + 8 * MB;   // [DFF, D]
    __half* wt_f2    = wt + 12 * MB;  // [D, DFF]

    cudaFuncSetAttribute(attn_h<true >, cudaFuncAttributeMaxDynamicSharedMemorySize, ATTH_BYTES);
    cudaFuncSetAttribute(attn_h<false>, cudaFuncAttributeMaxDynamicSharedMemorySize, ATTH_BYTES);
    cudaFuncSetAttribute((const void*)&gemm_mma<false,0>,
                         cudaFuncAttributeMaxDynamicSharedMemorySize, GEMM_SMEM);
    cudaFuncSetAttribute((const void*)&gemm_mma<false,1>,
                         cudaFuncAttributeMaxDynamicSharedMemorySize, GEMM_SMEM);
    cudaFuncSetAttribute((const void*)&gemm_mma<false,2>,
                         cudaFuncAttributeMaxDynamicSharedMemorySize, GEMM_SMEM);
    cudaFuncSetAttribute((const void*)&gemm_mma<true ,1>,
                         cudaFuncAttributeMaxDynamicSharedMemorySize, GEMM_SMEM);

    dim3 blk256(256), blk128(128);

    // ---- batched weight transposes (fp32 -> half, k16-permuted) ----
    TP8 tp;
    tp.src[0] = sa_wq;  tp.dst[0] = wt_saqkv + 0 * MB;
    tp.src[1] = sa_wk;  tp.dst[1] = wt_saqkv + 1 * MB;
    tp.src[2] = sa_wv;  tp.dst[2] = wt_saqkv + 2 * MB;
    tp.src[3] = sa_wo;  tp.dst[3] = wt_sao;
    tp.src[4] = cca_wq; tp.dst[4] = wt_ccq;
    tp.src[5] = cca_wk; tp.dst[5] = wt_cckv + 0 * MB;
    tp.src[6] = cca_wv; tp.dst[6] = wt_cckv + 1 * MB;
    tp.src[7] = cca_wo; tp.dst[7] = wt_cco;
    transpose8_kernel<<<dim3(D_ / 32, D_ / 32, 8), blk256>>>(tp, D_, D_);
    transpose_kernel<<<dim3(DFF_ / 32, D_ / 32), blk256>>>(ffn_w1, wt_f1, D_, DFF_);
    transpose_kernel<<<dim3(D_ / 32, DFF_ / 32), blk256>>>(ffn_w2, wt_f2, DFF_, D_);

    dim3 gProj(D_ / 128, TOK_ / 128);            // (8, 32)
    dim3 gQKV(3 * D_ / 128, TOK_ / 128);         // (24, 32)
    dim3 gKV2(2 * D_ / 128, KVTOK_ / 128);       // (16, 128)
    dim3 gFFN1(DFF_ / 128, TOK_ / 128);          // (32, 32)

    // ---- self-attention ----
    ln_kernel<<<TOK_ / 8, blk256>>>(x, sa_ln_g, sa_ln_b, h);
    gemm_mma<false,2><<<gQKV, blk128, GEMM_SMEM>>>(
        h, wt_saqkv, nullptr, qk, vt, 2 * D_, T_, TOK_, 3 * D_, D_);
    attn_h<true><<<dim3(T_ / 64, H_, B_), blk128, ATTH_BYTES>>>(
        qk, qk + D_, vt, attn, T_, T_, T_, 2 * D_, 2 * D_);
    gemm_mma<false,0><<<gProj, blk128, GEMM_SMEM>>>(
        attn, wt_sao, x, x1, nullptr, 0, 0, TOK_, D_, D_);

    // ---- chunked cross-attention (T == NC*chunk; reshapes are views) ----
    ln_kernel<<<TOK_ / 8,  blk256>>>(x1, cca_lnq_g, cca_lnq_b, h);
    ln_kernel<<<KVTOK_ / 8, blk256>>>(neighbors, cca_lnkv_g, cca_lnkv_b, kvln);
    gemm_mma<false,1><<<gProj, blk128, GEMM_SMEM>>>(
        h, wt_ccq, nullptr, ccq, nullptr, 0, 0, TOK_, D_, D_);
    gemm_mma<false,2><<<gKV2, blk128, GEMM_SMEM>>>(
        kvln, wt_cckv, nullptr, cck, ccvt, D_, KV_, KVTOK_, 2 * D_, D_);
    attn_h<false><<<dim3(1, H_, NCH_), blk128, ATTH_BYTES>>>(
        ccq, cck, ccvt, attn, KV_, CH_, KV_, D_, D_);
    gemm_mma<false,0><<<gProj, blk128, GEMM_SMEM>>>(
        attn, wt_cco, x1, out, nullptr, 0, 0, TOK_, D_, D_);

    // ---- FFN ----
    ln_kernel<<<TOK_ / 8, blk256>>>(out, ffn_ln_g, ffn_ln_b, h);
    gemm_mma<true ,1><<<gFFN1, blk128, GEMM_SMEM>>>(
        h, wt_f1, nullptr, ffn, nullptr, 0, 0, TOK_, DFF_, D_);
    gemm_mma<false,0><<<gProj, blk128, GEMM_SMEM>>>(
        ffn, wt_f2, out, out, nullptr, 0, 0, TOK_, D_, DFF_);
}